// round 1
// baseline (speedup 1.0000x reference)
#include <cuda_runtime.h>
#include <math.h>

// ---------------------------------------------------------------------------
// Problem dimensions
// ---------------------------------------------------------------------------
#define BT_   1536                 // B*T = 32*48
#define WL_   33
#define WA_   50
#define WE_   30
#define EL_   300
#define EA_   988
#define EE_   20
#define HH_   128
#define CL_   128
#define CA_   256
#define CE_   64
#define KL_   5
#define KA_   10
#define KE_   3
#define WOL_  (WL_ - KL_ + 1)      // 29
#define WOA_  (WA_ - KA_ + 1)      // 41
#define WOE_  (WE_ - KE_ + 1)      // 28
#define ML_   (BT_ * WOL_)         // 44544
#define MA_   (BT_ * WOA_)         // 62976
#define ME_   (BT_ * WOE_)         // 43008
#define KKL_  (KL_ * EL_)          // 1500
#define KKA_  (KA_ * EA_)          // 9880
#define KKE_  (KE_ * HH_)          // 384
#define OUTW_ 448

// ---------------------------------------------------------------------------
// Device scratch (static, allocation-free)
// ---------------------------------------------------------------------------
#define OFF_CA     ((size_t)0)                       // 62976*256 = 16121856
#define OFF_CL     ((size_t)16121856)                // 44544*128 = 5701632
#define OFF_CE     ((size_t)21823488)                // 43008*64  = 2752512
#define OFF_HBUF   ((size_t)24576000)                // 1536*30*128 = 5898240
#define OFF_WAT    ((size_t)30474240)                // 256*9880 = 2529280
#define OFF_WLT    ((size_t)33003520)                // 128*1500 = 192000
#define OFF_WET    ((size_t)33195520)                // 64*384   = 24576
#define OFF_WIHT   ((size_t)33220096)                // 20*512   = 10240
#define OFF_WHHT   ((size_t)33230336)                // 128*512  = 65536
#define OFF_HWLPT  ((size_t)33295872)                // 128*128
#define OFF_HWLGT  ((size_t)33312256)
#define OFF_HWAPT  ((size_t)33328640)                // 256*256
#define OFF_HWAGT  ((size_t)33394176)
#define OFF_HWEPT  ((size_t)33459712)                // 64*64
#define OFF_HWEGT  ((size_t)33463808)
#define SCRATCH_TOTAL ((size_t)33467904)

__device__ __align__(16) float g_scratch[SCRATCH_TOTAL];

// ---------------------------------------------------------------------------
// Weight permute: (Cout, Cin, K) -> (Cout, K, Cin)
// ---------------------------------------------------------------------------
__global__ void permute_w_kernel(const float* __restrict__ src, size_t dstOff,
                                 int Cout, int Cin, int K)
{
    int idx = blockIdx.x * 256 + threadIdx.x;
    int tot = Cout * Cin * K;
    if (idx >= tot) return;
    float* dst = g_scratch + dstOff;
    int ci = idx % Cin;
    int r  = idx / Cin;
    int k  = r % K;
    int co = r / K;
    dst[idx] = src[(size_t)co * Cin * K + (size_t)ci * K + k];
}

// 2D transpose: src (R x C) -> dst (C x R)
__global__ void transpose2d_kernel(const float* __restrict__ src, size_t dstOff,
                                   int R, int C)
{
    int idx = blockIdx.x * 256 + threadIdx.x;
    int tot = R * C;
    if (idx >= tot) return;
    float* dst = g_scratch + dstOff;
    int r = idx % R;
    int c = idx / R;
    dst[idx] = src[(size_t)r * C + c];
}

// ---------------------------------------------------------------------------
// Conv-as-GEMM: C[m][n] = dot(window(m), Wt[n][:])  (fp32, smem-tiled)
//   m -> (bt = m/Wout, t = m%Wout), window ptr = X + bt*btStride + t*rowStride
//   window is KK contiguous floats; Wt is (N x KK) row-major (permuted weights)
// ---------------------------------------------------------------------------
template<int BM, int BN, int BK, int TM, int TN>
__global__ __launch_bounds__(256)
void conv_gemm_kernel(const float* __restrict__ Xext, size_t xOff,
                      size_t wOff, size_t cOff,
                      int M, int N, int KK,
                      int Wout, int rowStride, int btStride)
{
    static_assert((BM / TM) * (BN / TN) == 256, "256 threads");
    constexpr int A_VECS = BM * BK / (256 * 4);
    constexpr int B_VECS = BN * BK / (256 * 4);

    const float* X    = Xext ? Xext : (g_scratch + xOff);
    const float* Wt   = g_scratch + wOff;
    float*       Cmat = g_scratch + cOff;

    __shared__ __align__(16) float As[BK][BM + 4];
    __shared__ __align__(16) float Bs[BK][BN + 4];

    const int tid = threadIdx.x;
    const int bm  = blockIdx.x * BM;
    const int bn  = blockIdx.y * BN;

    const int lr = tid >> 2;          // 0..63
    const int lk = (tid & 3) * 4;     // 0,4,8,12

    const float* aRow[A_VECS];
#pragma unroll
    for (int v = 0; v < A_VECS; v++) {
        int m  = bm + lr + v * 64;
        int bt = m / Wout;
        int t  = m - bt * Wout;
        aRow[v] = X + (size_t)bt * btStride + (size_t)t * rowStride;
    }
    const float* bRow[B_VECS];
#pragma unroll
    for (int v = 0; v < B_VECS; v++) {
        int n = bn + lr + v * 64;
        bRow[v] = Wt + (size_t)n * KK;
    }

    float acc[TM][TN];
#pragma unroll
    for (int i = 0; i < TM; i++)
#pragma unroll
        for (int j = 0; j < TN; j++) acc[i][j] = 0.f;

    const int ty = tid / (BN / TN);
    const int tx = tid % (BN / TN);

    for (int k0 = 0; k0 < KK; k0 += BK) {
        int kg = k0 + lk;
        bool ok = (kg < KK);   // KK % 4 == 0 for all uses -> whole-float4 guard
#pragma unroll
        for (int v = 0; v < A_VECS; v++) {
            float4 a = ok ? *(const float4*)(aRow[v] + kg)
                          : make_float4(0.f, 0.f, 0.f, 0.f);
            int mr = lr + v * 64;
            As[lk + 0][mr] = a.x; As[lk + 1][mr] = a.y;
            As[lk + 2][mr] = a.z; As[lk + 3][mr] = a.w;
        }
#pragma unroll
        for (int v = 0; v < B_VECS; v++) {
            float4 b = ok ? *(const float4*)(bRow[v] + kg)
                          : make_float4(0.f, 0.f, 0.f, 0.f);
            int nr = lr + v * 64;
            Bs[lk + 0][nr] = b.x; Bs[lk + 1][nr] = b.y;
            Bs[lk + 2][nr] = b.z; Bs[lk + 3][nr] = b.w;
        }
        __syncthreads();

#pragma unroll
        for (int kk = 0; kk < BK; kk++) {
            float a[TM], b[TN];
#pragma unroll
            for (int i = 0; i < TM; i += 4) {
                float4 v = *(const float4*)&As[kk][ty * TM + i];
                a[i] = v.x; a[i + 1] = v.y; a[i + 2] = v.z; a[i + 3] = v.w;
            }
#pragma unroll
            for (int j = 0; j < TN; j += 4) {
                float4 v = *(const float4*)&Bs[kk][tx * TN + j];
                b[j] = v.x; b[j + 1] = v.y; b[j + 2] = v.z; b[j + 3] = v.w;
            }
#pragma unroll
            for (int i = 0; i < TM; i++)
#pragma unroll
                for (int j = 0; j < TN; j++)
                    acc[i][j] = fmaf(a[i], b[j], acc[i][j]);
        }
        __syncthreads();
    }

#pragma unroll
    for (int i = 0; i < TM; i++) {
        size_t m = (size_t)bm + ty * TM + i;
        float* cp = Cmat + m * (size_t)N + bn + tx * TN;
#pragma unroll
        for (int j = 0; j < TN; j += 4) {
            float4 v = make_float4(acc[i][j], acc[i][j + 1],
                                   acc[i][j + 2], acc[i][j + 3]);
            *(float4*)(cp + j) = v;
        }
    }
}

// ---------------------------------------------------------------------------
// Masked LSTM: 8 sequences per block, 512 threads (one gate-row each)
//   z = x_t @ Wih^T + h @ Whh^T + (bih+bhh); gates order i,f,g,o
//   h_t output is zeroed for t >= len (packed-sequence semantics)
// ---------------------------------------------------------------------------
#define SEQS 8
__device__ __forceinline__ float sigf(float x) { return 1.f / (1.f + expf(-x)); }

__global__ __launch_bounds__(512)
void lstm_kernel(const float* __restrict__ xe,   // (BT, 30, 20)
                 const int*   __restrict__ wlen, // (BT,)
                 const float* __restrict__ bih,
                 const float* __restrict__ bhh)
{
    const float* WihT = g_scratch + OFF_WIHT;  // (20 x 512)
    const float* WhhT = g_scratch + OFF_WHHT;  // (128 x 512)
    float*       hbuf = g_scratch + OFF_HBUF;  // (BT, 30, 128)

    __shared__ float sh[SEQS][HH_];
    __shared__ float sc[SEQS][HH_];
    __shared__ float sx[SEQS][EE_];
    __shared__ float sz[4 * HH_][SEQS + 1];
    __shared__ int   slen[SEQS];

    const int tid = threadIdx.x;       // 0..511
    const int bt0 = blockIdx.x * SEQS;

    for (int i = tid; i < SEQS * HH_; i += 512) {
        (&sh[0][0])[i] = 0.f;
        (&sc[0][0])[i] = 0.f;
    }
    if (tid < SEQS) slen[tid] = wlen[bt0 + tid];
    __syncthreads();

    const int r = tid;
    const float bias = bih[r] + bhh[r];

    for (int t = 0; t < WE_; t++) {
        // load x_t for the 8 sequences
        for (int i = tid; i < SEQS * EE_; i += 512) {
            int s = i / EE_, e = i - s * EE_;
            sx[s][e] = xe[(size_t)(bt0 + s) * (WE_ * EE_) + t * EE_ + e];
        }
        __syncthreads();

        float acc[SEQS];
#pragma unroll
        for (int s = 0; s < SEQS; s++) acc[s] = bias;

#pragma unroll
        for (int e = 0; e < EE_; e++) {
            float w = WihT[e * 512 + r];
#pragma unroll
            for (int s = 0; s < SEQS; s++) acc[s] = fmaf(w, sx[s][e], acc[s]);
        }
#pragma unroll 4
        for (int j = 0; j < HH_; j++) {
            float w = WhhT[j * 512 + r];
#pragma unroll
            for (int s = 0; s < SEQS; s++) acc[s] = fmaf(w, sh[s][j], acc[s]);
        }
#pragma unroll
        for (int s = 0; s < SEQS; s++) sz[r][s] = acc[s];
        __syncthreads();

        // gate combine: 1024 (s,j) pairs / 512 threads
#pragma unroll
        for (int p = tid; p < SEQS * HH_; p += 512) {
            int s = p & (SEQS - 1);
            int j = p >> 3;
            float zi = sz[j][s];
            float zf = sz[HH_ + j][s];
            float zg = sz[2 * HH_ + j][s];
            float zo = sz[3 * HH_ + j][s];
            float c  = sc[s][j];
            float cn = sigf(zf) * c + sigf(zi) * tanhf(zg);
            float hn = sigf(zo) * tanhf(cn);
            bool valid = (t < slen[s]);
            sc[s][j] = valid ? cn : c;
            sh[s][j] = valid ? hn : sh[s][j];
            hbuf[(size_t)(bt0 + s) * (WE_ * HH_) + t * HH_ + j] = valid ? hn : 0.f;
        }
        __syncthreads();
    }
}

// ---------------------------------------------------------------------------
// Fused maxpool(+conv bias) + highway, writes final output slice
//   y[co]  = max_t C[bt, t, co] + convB[co]
//   p = relu(y @ WpT + bp), g = sigmoid(y @ WgT + bg)
//   out = g*p + (1-g)*y
// ---------------------------------------------------------------------------
__global__ void pool_highway_kernel(size_t cOff, int N, int Wout,
                                    const float* __restrict__ convB,
                                    size_t wpOff, const float* __restrict__ bp,
                                    size_t wgOff, const float* __restrict__ bg,
                                    float* __restrict__ out, int outOff)
{
    extern __shared__ float sy[];
    const float* Cmat = g_scratch + cOff;
    const float* WpT  = g_scratch + wpOff;   // (N x N), [j][co]
    const float* WgT  = g_scratch + wgOff;

    int bt = blockIdx.x;
    int co = threadIdx.x;

    const float* cp = Cmat + (size_t)bt * Wout * N + co;
    float y = cp[0];
    for (int t = 1; t < Wout; t++) y = fmaxf(y, cp[(size_t)t * N]);
    y += convB[co];
    sy[co] = y;
    __syncthreads();

    float ap = bp[co], ag = bg[co];
    for (int j = 0; j < N; j++) {
        float yj = sy[j];
        ap = fmaf(WpT[j * N + co], yj, ap);
        ag = fmaf(WgT[j * N + co], yj, ag);
    }
    float p = fmaxf(ap, 0.f);
    float g = 1.f / (1.f + expf(-ag));
    out[(size_t)bt * OUTW_ + outOff + co] = g * p + (1.f - g) * y;
}

// ---------------------------------------------------------------------------
// Launch
// ---------------------------------------------------------------------------
extern "C" void kernel_launch(void* const* d_in, const int* in_sizes, int n_in,
                              void* d_out, int out_size)
{
    (void)in_sizes; (void)n_in; (void)out_size;
    const float* x_lin   = (const float*)d_in[0];
    const float* x_aco   = (const float*)d_in[1];
    const float* x_emo   = (const float*)d_in[2];
    const int*   wlen    = (const int*)  d_in[3];
    // d_in[4] = length (unused by reference)
    const float* convL_w = (const float*)d_in[5];
    const float* convL_b = (const float*)d_in[6];
    const float* convA_w = (const float*)d_in[7];
    const float* convA_b = (const float*)d_in[8];
    const float* convE_w = (const float*)d_in[9];
    const float* convE_b = (const float*)d_in[10];
    const float* hwL_Wp  = (const float*)d_in[11];
    const float* hwL_bp  = (const float*)d_in[12];
    const float* hwL_Wg  = (const float*)d_in[13];
    const float* hwL_bg  = (const float*)d_in[14];
    const float* hwA_Wp  = (const float*)d_in[15];
    const float* hwA_bp  = (const float*)d_in[16];
    const float* hwA_Wg  = (const float*)d_in[17];
    const float* hwA_bg  = (const float*)d_in[18];
    const float* hwE_Wp  = (const float*)d_in[19];
    const float* hwE_bp  = (const float*)d_in[20];
    const float* hwE_Wg  = (const float*)d_in[21];
    const float* hwE_bg  = (const float*)d_in[22];
    const float* Wih     = (const float*)d_in[23];
    const float* Whh     = (const float*)d_in[24];
    const float* bih     = (const float*)d_in[25];
    const float* bhh     = (const float*)d_in[26];
    float* out = (float*)d_out;

    // ---- weight prep (small) ----
    {
        int tot;
        tot = CA_ * EA_ * KA_;
        permute_w_kernel<<<(tot + 255) / 256, 256>>>(convA_w, OFF_WAT, CA_, EA_, KA_);
        tot = CL_ * EL_ * KL_;
        permute_w_kernel<<<(tot + 255) / 256, 256>>>(convL_w, OFF_WLT, CL_, EL_, KL_);
        tot = CE_ * HH_ * KE_;
        permute_w_kernel<<<(tot + 255) / 256, 256>>>(convE_w, OFF_WET, CE_, HH_, KE_);

        tot = 512 * EE_;
        transpose2d_kernel<<<(tot + 255) / 256, 256>>>(Wih, OFF_WIHT, 512, EE_);
        tot = 512 * HH_;
        transpose2d_kernel<<<(tot + 255) / 256, 256>>>(Whh, OFF_WHHT, 512, HH_);

        tot = CL_ * CL_;
        transpose2d_kernel<<<(tot + 255) / 256, 256>>>(hwL_Wp, OFF_HWLPT, CL_, CL_);
        transpose2d_kernel<<<(tot + 255) / 256, 256>>>(hwL_Wg, OFF_HWLGT, CL_, CL_);
        tot = CA_ * CA_;
        transpose2d_kernel<<<(tot + 255) / 256, 256>>>(hwA_Wp, OFF_HWAPT, CA_, CA_);
        transpose2d_kernel<<<(tot + 255) / 256, 256>>>(hwA_Wg, OFF_HWAGT, CA_, CA_);
        tot = CE_ * CE_;
        transpose2d_kernel<<<(tot + 255) / 256, 256>>>(hwE_Wp, OFF_HWEPT, CE_, CE_);
        transpose2d_kernel<<<(tot + 255) / 256, 256>>>(hwE_Wg, OFF_HWEGT, CE_, CE_);
    }

    // ---- LSTM (-> hbuf) ----
    lstm_kernel<<<BT_ / SEQS, 512>>>(x_emo, wlen, bih, bhh);

    // ---- Conv GEMMs ----
    conv_gemm_kernel<128, 128, 16, 8, 8><<<dim3(ML_ / 128, CL_ / 128), 256>>>(
        x_lin, 0, OFF_WLT, OFF_CL, ML_, CL_, KKL_, WOL_, EL_, WL_ * EL_);

    conv_gemm_kernel<128, 128, 16, 8, 8><<<dim3(MA_ / 128, CA_ / 128), 256>>>(
        x_aco, 0, OFF_WAT, OFF_CA, MA_, CA_, KKA_, WOA_, EA_, WA_ * EA_);

    conv_gemm_kernel<128, 64, 16, 8, 4><<<dim3(ME_ / 128, CE_ / 64), 256>>>(
        nullptr, OFF_HBUF, OFF_WET, OFF_CE, ME_, CE_, KKE_, WOE_, HH_, WE_ * HH_);

    // ---- Fused maxpool + highway -> output ----
    pool_highway_kernel<<<BT_, CL_, CL_ * sizeof(float)>>>(
        OFF_CL, CL_, WOL_, convL_b, OFF_HWLPT, hwL_bp, OFF_HWLGT, hwL_bg, out, 0);
    pool_highway_kernel<<<BT_, CA_, CA_ * sizeof(float)>>>(
        OFF_CA, CA_, WOA_, convA_b, OFF_HWAPT, hwA_bp, OFF_HWAGT, hwA_bg, out, CL_);
    pool_highway_kernel<<<BT_, CE_, CE_ * sizeof(float)>>>(
        OFF_CE, CE_, WOE_, convE_b, OFF_HWEPT, hwE_bp, OFF_HWEGT, hwE_bg, out, CL_ + CA_);
}

// round 2
// speedup vs baseline: 2.0569x; 2.0569x over previous
#include <cuda_runtime.h>
#include <math.h>
#include <stdint.h>

// ---------------------------------------------------------------------------
// Problem dimensions
// ---------------------------------------------------------------------------
#define BT_   1536                 // B*T = 32*48
#define WL_   33
#define WA_   50
#define WE_   30
#define EL_   300
#define EA_   988
#define EE_   20
#define HH_   128
#define CL_   128
#define CA_   256
#define CE_   64
#define KL_   5
#define KA_   10
#define KE_   3
#define WOL_  (WL_ - KL_ + 1)      // 29
#define WOA_  (WA_ - KA_ + 1)      // 41
#define WOE_  (WE_ - KE_ + 1)      // 28
#define ML_   (BT_ * WOL_)         // 44544
#define MA_   (BT_ * WOA_)         // 62976
#define ME_   (BT_ * WOE_)         // 43008
#define KKL_  (KL_ * EL_)          // 1500
#define KKA_  (KA_ * EA_)          // 9880
#define KKE_  (KE_ * HH_)          // 384
#define OUTW_ 448

// ---------------------------------------------------------------------------
// Device scratch (static, allocation-free)
// ---------------------------------------------------------------------------
#define OFF_CA     ((size_t)0)                       // 62976*256 = 16121856
#define OFF_CL     ((size_t)16121856)                // 44544*128 = 5701632
#define OFF_CE     ((size_t)21823488)                // 43008*64  = 2752512
#define OFF_HBUF   ((size_t)24576000)                // 1536*30*128 = 5898240
#define OFF_WAT    ((size_t)30474240)                // 256*9880 = 2529280
#define OFF_WLT    ((size_t)33003520)                // 128*1500 = 192000
#define OFF_WET    ((size_t)33195520)                // 64*384   = 24576
#define OFF_WIHT   ((size_t)33220096)                // 20*512   = 10240
#define OFF_WHHT   ((size_t)33230336)                // 128*512  = 65536
#define OFF_HWLPT  ((size_t)33295872)                // 128*128
#define OFF_HWLGT  ((size_t)33312256)
#define OFF_HWAPT  ((size_t)33328640)                // 256*256
#define OFF_HWAGT  ((size_t)33394176)
#define OFF_HWEPT  ((size_t)33459712)                // 64*64
#define OFF_HWEGT  ((size_t)33463808)
#define SCRATCH_TOTAL ((size_t)33467904)

__device__ __align__(16) float g_scratch[SCRATCH_TOTAL];

// ---------------------------------------------------------------------------
// Weight permute: (Cout, Cin, K) -> (Cout, K, Cin)
// ---------------------------------------------------------------------------
__global__ void permute_w_kernel(const float* __restrict__ src, size_t dstOff,
                                 int Cout, int Cin, int K)
{
    int idx = blockIdx.x * 256 + threadIdx.x;
    int tot = Cout * Cin * K;
    if (idx >= tot) return;
    float* dst = g_scratch + dstOff;
    int ci = idx % Cin;
    int r  = idx / Cin;
    int k  = r % K;
    int co = r / K;
    dst[idx] = src[(size_t)co * Cin * K + (size_t)ci * K + k];
}

// 2D transpose: src (R x C) -> dst (C x R)
__global__ void transpose2d_kernel(const float* __restrict__ src, size_t dstOff,
                                   int R, int C)
{
    int idx = blockIdx.x * 256 + threadIdx.x;
    int tot = R * C;
    if (idx >= tot) return;
    float* dst = g_scratch + dstOff;
    int r = idx % R;
    int c = idx / R;
    dst[idx] = src[(size_t)r * C + c];
}

// ---------------------------------------------------------------------------
// TF32 tensor-core conv-as-GEMM
//   C[m][n] = dot(window(m), Wt[n][:])
//   m -> (bt = m/Wout, t = m%Wout), window ptr = X + bt*btStride + t*rowStride
//   128x128x16 CTA tile, 8 warps (2x4), warp tile 64x32, mma.m16n8k8 tf32
// ---------------------------------------------------------------------------
__device__ __forceinline__ uint32_t f2tf32(float f) {
    uint32_t u;
    asm("cvt.rna.tf32.f32 %0, %1;" : "=r"(u) : "f"(f));
    return u;
}

__device__ __forceinline__ void mma_tf32(float c[4], const uint32_t a[4],
                                         const uint32_t b[2]) {
    asm volatile(
        "mma.sync.aligned.m16n8k8.row.col.f32.tf32.tf32.f32 "
        "{%0,%1,%2,%3}, {%4,%5,%6,%7}, {%8,%9}, {%0,%1,%2,%3};"
        : "+f"(c[0]), "+f"(c[1]), "+f"(c[2]), "+f"(c[3])
        : "r"(a[0]), "r"(a[1]), "r"(a[2]), "r"(a[3]), "r"(b[0]), "r"(b[1]));
}

#define TBM 128
#define TBN 128
#define TBK 16

__global__ __launch_bounds__(256, 2)
void conv_gemm_tf32_kernel(const float* __restrict__ X,
                           size_t wOff, size_t cOff,
                           int M, int N, int KK,
                           int Wout, int rowStride, int btStride)
{
    __shared__ __align__(16) uint32_t As[TBK][TBM + 4];
    __shared__ __align__(16) uint32_t Bs[TBK][TBN + 4];

    const float* Wt   = g_scratch + wOff;
    float*       Cmat = g_scratch + cOff;

    const int tid  = threadIdx.x;
    const int bm   = blockIdx.x * TBM;
    const int bn   = blockIdx.y * TBN;
    const int wid  = tid >> 5;
    const int lane = tid & 31;
    const int wm   = wid & 1;            // 0..1 (64 rows each)
    const int wn   = wid >> 1;           // 0..3 (32 cols each)
    const int g    = lane >> 2;          // 0..7
    const int c    = lane & 3;           // 0..3

    // loader mapping (256 threads, float4 granularity)
    const int lr = tid >> 2;             // 0..63
    const int lk = (tid & 3) * 4;        // 0,4,8,12

    const float* aRow[2];
#pragma unroll
    for (int v = 0; v < 2; v++) {
        int m  = bm + lr + v * 64;
        int bt = m / Wout;
        int t  = m - bt * Wout;
        aRow[v] = X + (size_t)bt * btStride + (size_t)t * rowStride;
    }
    const float* bRow[2];
#pragma unroll
    for (int v = 0; v < 2; v++) {
        int n = bn + lr + v * 64;
        bRow[v] = Wt + (size_t)n * KK;
    }

    float acc[4][4][4];
#pragma unroll
    for (int mi = 0; mi < 4; mi++)
#pragma unroll
        for (int ni = 0; ni < 4; ni++)
#pragma unroll
            for (int q = 0; q < 4; q++) acc[mi][ni][q] = 0.f;

    float4 ra[2], rb[2];

    // prefetch tile 0
    {
        int kg = lk;
        bool ok = (kg < KK);
#pragma unroll
        for (int v = 0; v < 2; v++)
            ra[v] = ok ? *(const float4*)(aRow[v] + kg)
                       : make_float4(0.f, 0.f, 0.f, 0.f);
#pragma unroll
        for (int v = 0; v < 2; v++)
            rb[v] = ok ? *(const float4*)(bRow[v] + kg)
                       : make_float4(0.f, 0.f, 0.f, 0.f);
    }
    // store tile 0
#pragma unroll
    for (int v = 0; v < 2; v++) {
        int mr = lr + v * 64;
        As[lk + 0][mr] = f2tf32(ra[v].x); As[lk + 1][mr] = f2tf32(ra[v].y);
        As[lk + 2][mr] = f2tf32(ra[v].z); As[lk + 3][mr] = f2tf32(ra[v].w);
    }
#pragma unroll
    for (int v = 0; v < 2; v++) {
        int nr = lr + v * 64;
        Bs[lk + 0][nr] = f2tf32(rb[v].x); Bs[lk + 1][nr] = f2tf32(rb[v].y);
        Bs[lk + 2][nr] = f2tf32(rb[v].z); Bs[lk + 3][nr] = f2tf32(rb[v].w);
    }
    __syncthreads();

    for (int k0 = 0; k0 < KK; k0 += TBK) {
        const bool has_next = (k0 + TBK < KK);
        if (has_next) {
            int kg = k0 + TBK + lk;
            bool ok = (kg < KK);
#pragma unroll
            for (int v = 0; v < 2; v++)
                ra[v] = ok ? *(const float4*)(aRow[v] + kg)
                           : make_float4(0.f, 0.f, 0.f, 0.f);
#pragma unroll
            for (int v = 0; v < 2; v++)
                rb[v] = ok ? *(const float4*)(bRow[v] + kg)
                           : make_float4(0.f, 0.f, 0.f, 0.f);
        }

        // compute 2 k8 steps
#pragma unroll
        for (int ks = 0; ks < 2; ks++) {
            const int kb = ks * 8;
            uint32_t afr[4][4];
#pragma unroll
            for (int mi = 0; mi < 4; mi++) {
                int mr = wm * 64 + mi * 16 + g;
                afr[mi][0] = As[kb + c][mr];
                afr[mi][1] = As[kb + c][mr + 8];
                afr[mi][2] = As[kb + c + 4][mr];
                afr[mi][3] = As[kb + c + 4][mr + 8];
            }
            uint32_t bfr[4][2];
#pragma unroll
            for (int ni = 0; ni < 4; ni++) {
                int nr = wn * 32 + ni * 8 + g;
                bfr[ni][0] = Bs[kb + c][nr];
                bfr[ni][1] = Bs[kb + c + 4][nr];
            }
#pragma unroll
            for (int mi = 0; mi < 4; mi++)
#pragma unroll
                for (int ni = 0; ni < 4; ni++)
                    mma_tf32(acc[mi][ni], afr[mi], bfr[ni]);
        }
        __syncthreads();

        if (has_next) {
#pragma unroll
            for (int v = 0; v < 2; v++) {
                int mr = lr + v * 64;
                As[lk + 0][mr] = f2tf32(ra[v].x); As[lk + 1][mr] = f2tf32(ra[v].y);
                As[lk + 2][mr] = f2tf32(ra[v].z); As[lk + 3][mr] = f2tf32(ra[v].w);
            }
#pragma unroll
            for (int v = 0; v < 2; v++) {
                int nr = lr + v * 64;
                Bs[lk + 0][nr] = f2tf32(rb[v].x); Bs[lk + 1][nr] = f2tf32(rb[v].y);
                Bs[lk + 2][nr] = f2tf32(rb[v].z); Bs[lk + 3][nr] = f2tf32(rb[v].w);
            }
            __syncthreads();
        }
    }

    // epilogue: c0:(row,col), c1:(row,col+1), c2:(row+8,col), c3:(row+8,col+1)
#pragma unroll
    for (int mi = 0; mi < 4; mi++) {
#pragma unroll
        for (int ni = 0; ni < 4; ni++) {
            int row = bm + wm * 64 + mi * 16 + g;
            int col = bn + wn * 32 + ni * 8 + c * 2;
            float2 v0 = make_float2(acc[mi][ni][0], acc[mi][ni][1]);
            float2 v1 = make_float2(acc[mi][ni][2], acc[mi][ni][3]);
            *(float2*)(Cmat + (size_t)row * N + col)       = v0;
            *(float2*)(Cmat + (size_t)(row + 8) * N + col) = v1;
        }
    }
}

// ---------------------------------------------------------------------------
// FP32 conv-as-GEMM (kept for the small Emotient GEMM; input from g_scratch)
// ---------------------------------------------------------------------------
template<int BM, int BN, int BK, int TM, int TN>
__global__ __launch_bounds__(256)
void conv_gemm_kernel(size_t xOff, size_t wOff, size_t cOff,
                      int M, int N, int KK,
                      int Wout, int rowStride, int btStride)
{
    static_assert((BM / TM) * (BN / TN) == 256, "256 threads");
    constexpr int A_VECS = BM * BK / (256 * 4);
    constexpr int B_VECS = BN * BK / (256 * 4);

    const float* X    = g_scratch + xOff;
    const float* Wt   = g_scratch + wOff;
    float*       Cmat = g_scratch + cOff;

    __shared__ __align__(16) float As[BK][BM + 4];
    __shared__ __align__(16) float Bs[BK][BN + 4];

    const int tid = threadIdx.x;
    const int bm  = blockIdx.x * BM;
    const int bn  = blockIdx.y * BN;

    const int lr = tid >> 2;
    const int lk = (tid & 3) * 4;

    const float* aRow[A_VECS];
#pragma unroll
    for (int v = 0; v < A_VECS; v++) {
        int m  = bm + lr + v * 64;
        int bt = m / Wout;
        int t  = m - bt * Wout;
        aRow[v] = X + (size_t)bt * btStride + (size_t)t * rowStride;
    }
    const float* bRow[B_VECS];
#pragma unroll
    for (int v = 0; v < B_VECS; v++) {
        int n = bn + lr + v * 64;
        bRow[v] = Wt + (size_t)n * KK;
    }

    float acc[TM][TN];
#pragma unroll
    for (int i = 0; i < TM; i++)
#pragma unroll
        for (int j = 0; j < TN; j++) acc[i][j] = 0.f;

    const int ty = tid / (BN / TN);
    const int tx = tid % (BN / TN);

    for (int k0 = 0; k0 < KK; k0 += BK) {
        int kg = k0 + lk;
        bool ok = (kg < KK);
#pragma unroll
        for (int v = 0; v < A_VECS; v++) {
            float4 a = ok ? *(const float4*)(aRow[v] + kg)
                          : make_float4(0.f, 0.f, 0.f, 0.f);
            int mr = lr + v * 64;
            As[lk + 0][mr] = a.x; As[lk + 1][mr] = a.y;
            As[lk + 2][mr] = a.z; As[lk + 3][mr] = a.w;
        }
#pragma unroll
        for (int v = 0; v < B_VECS; v++) {
            float4 b = ok ? *(const float4*)(bRow[v] + kg)
                          : make_float4(0.f, 0.f, 0.f, 0.f);
            int nr = lr + v * 64;
            Bs[lk + 0][nr] = b.x; Bs[lk + 1][nr] = b.y;
            Bs[lk + 2][nr] = b.z; Bs[lk + 3][nr] = b.w;
        }
        __syncthreads();

#pragma unroll
        for (int kk = 0; kk < BK; kk++) {
            float a[TM], b[TN];
#pragma unroll
            for (int i = 0; i < TM; i += 4) {
                float4 v = *(const float4*)&As[kk][ty * TM + i];
                a[i] = v.x; a[i + 1] = v.y; a[i + 2] = v.z; a[i + 3] = v.w;
            }
#pragma unroll
            for (int j = 0; j < TN; j += 4) {
                float4 v = *(const float4*)&Bs[kk][tx * TN + j];
                b[j] = v.x; b[j + 1] = v.y; b[j + 2] = v.z; b[j + 3] = v.w;
            }
#pragma unroll
            for (int i = 0; i < TM; i++)
#pragma unroll
                for (int j = 0; j < TN; j++)
                    acc[i][j] = fmaf(a[i], b[j], acc[i][j]);
        }
        __syncthreads();
    }

#pragma unroll
    for (int i = 0; i < TM; i++) {
        size_t m = (size_t)bm + ty * TM + i;
        float* cp = Cmat + m * (size_t)N + bn + tx * TN;
#pragma unroll
        for (int j = 0; j < TN; j += 4) {
            float4 v = make_float4(acc[i][j], acc[i][j + 1],
                                   acc[i][j + 2], acc[i][j + 3]);
            *(float4*)(cp + j) = v;
        }
    }
}

// ---------------------------------------------------------------------------
// Masked LSTM: 8 sequences per block, 512 threads (one gate-row each)
// ---------------------------------------------------------------------------
#define SEQS 8
__device__ __forceinline__ float sigf(float x) { return 1.f / (1.f + expf(-x)); }

__global__ __launch_bounds__(512)
void lstm_kernel(const float* __restrict__ xe,   // (BT, 30, 20)
                 const int*   __restrict__ wlen, // (BT,)
                 const float* __restrict__ bih,
                 const float* __restrict__ bhh)
{
    const float* WihT = g_scratch + OFF_WIHT;  // (20 x 512)
    const float* WhhT = g_scratch + OFF_WHHT;  // (128 x 512)
    float*       hbuf = g_scratch + OFF_HBUF;  // (BT, 30, 128)

    __shared__ float sh[SEQS][HH_];
    __shared__ float sc[SEQS][HH_];
    __shared__ float sx[SEQS][EE_];
    __shared__ float sz[4 * HH_][SEQS + 1];
    __shared__ int   slen[SEQS];

    const int tid = threadIdx.x;
    const int bt0 = blockIdx.x * SEQS;

    for (int i = tid; i < SEQS * HH_; i += 512) {
        (&sh[0][0])[i] = 0.f;
        (&sc[0][0])[i] = 0.f;
    }
    if (tid < SEQS) slen[tid] = wlen[bt0 + tid];
    __syncthreads();

    const int r = tid;
    const float bias = bih[r] + bhh[r];

    for (int t = 0; t < WE_; t++) {
        for (int i = tid; i < SEQS * EE_; i += 512) {
            int s = i / EE_, e = i - s * EE_;
            sx[s][e] = xe[(size_t)(bt0 + s) * (WE_ * EE_) + t * EE_ + e];
        }
        __syncthreads();

        float acc[SEQS];
#pragma unroll
        for (int s = 0; s < SEQS; s++) acc[s] = bias;

#pragma unroll
        for (int e = 0; e < EE_; e++) {
            float w = WihT[e * 512 + r];
#pragma unroll
            for (int s = 0; s < SEQS; s++) acc[s] = fmaf(w, sx[s][e], acc[s]);
        }
#pragma unroll 4
        for (int j = 0; j < HH_; j++) {
            float w = WhhT[j * 512 + r];
#pragma unroll
            for (int s = 0; s < SEQS; s++) acc[s] = fmaf(w, sh[s][j], acc[s]);
        }
#pragma unroll
        for (int s = 0; s < SEQS; s++) sz[r][s] = acc[s];
        __syncthreads();

#pragma unroll
        for (int p = tid; p < SEQS * HH_; p += 512) {
            int s = p & (SEQS - 1);
            int j = p >> 3;
            float zi = sz[j][s];
            float zf = sz[HH_ + j][s];
            float zg = sz[2 * HH_ + j][s];
            float zo = sz[3 * HH_ + j][s];
            float cc = sc[s][j];
            float cn = sigf(zf) * cc + sigf(zi) * tanhf(zg);
            float hn = sigf(zo) * tanhf(cn);
            bool valid = (t < slen[s]);
            sc[s][j] = valid ? cn : cc;
            sh[s][j] = valid ? hn : sh[s][j];
            hbuf[(size_t)(bt0 + s) * (WE_ * HH_) + t * HH_ + j] = valid ? hn : 0.f;
        }
        __syncthreads();
    }
}

// ---------------------------------------------------------------------------
// Fused maxpool(+conv bias) + highway, writes final output slice
// ---------------------------------------------------------------------------
__global__ void pool_highway_kernel(size_t cOff, int N, int Wout,
                                    const float* __restrict__ convB,
                                    size_t wpOff, const float* __restrict__ bp,
                                    size_t wgOff, const float* __restrict__ bg,
                                    float* __restrict__ out, int outOff)
{
    extern __shared__ float sy[];
    const float* Cmat = g_scratch + cOff;
    const float* WpT  = g_scratch + wpOff;
    const float* WgT  = g_scratch + wgOff;

    int bt = blockIdx.x;
    int co = threadIdx.x;

    const float* cp = Cmat + (size_t)bt * Wout * N + co;
    float y = cp[0];
    for (int t = 1; t < Wout; t++) y = fmaxf(y, cp[(size_t)t * N]);
    y += convB[co];
    sy[co] = y;
    __syncthreads();

    float ap = bp[co], ag = bg[co];
    for (int j = 0; j < N; j++) {
        float yj = sy[j];
        ap = fmaf(WpT[j * N + co], yj, ap);
        ag = fmaf(WgT[j * N + co], yj, ag);
    }
    float p = fmaxf(ap, 0.f);
    float gg = 1.f / (1.f + expf(-ag));
    out[(size_t)bt * OUTW_ + outOff + co] = gg * p + (1.f - gg) * y;
}

// ---------------------------------------------------------------------------
// Launch
// ---------------------------------------------------------------------------
extern "C" void kernel_launch(void* const* d_in, const int* in_sizes, int n_in,
                              void* d_out, int out_size)
{
    (void)in_sizes; (void)n_in; (void)out_size;
    const float* x_lin   = (const float*)d_in[0];
    const float* x_aco   = (const float*)d_in[1];
    const float* x_emo   = (const float*)d_in[2];
    const int*   wlen    = (const int*)  d_in[3];
    const float* convL_w = (const float*)d_in[5];
    const float* convL_b = (const float*)d_in[6];
    const float* convA_w = (const float*)d_in[7];
    const float* convA_b = (const float*)d_in[8];
    const float* convE_w = (const float*)d_in[9];
    const float* convE_b = (const float*)d_in[10];
    const float* hwL_Wp  = (const float*)d_in[11];
    const float* hwL_bp  = (const float*)d_in[12];
    const float* hwL_Wg  = (const float*)d_in[13];
    const float* hwL_bg  = (const float*)d_in[14];
    const float* hwA_Wp  = (const float*)d_in[15];
    const float* hwA_bp  = (const float*)d_in[16];
    const float* hwA_Wg  = (const float*)d_in[17];
    const float* hwA_bg  = (const float*)d_in[18];
    const float* hwE_Wp  = (const float*)d_in[19];
    const float* hwE_bp  = (const float*)d_in[20];
    const float* hwE_Wg  = (const float*)d_in[21];
    const float* hwE_bg  = (const float*)d_in[22];
    const float* Wih     = (const float*)d_in[23];
    const float* Whh     = (const float*)d_in[24];
    const float* bih     = (const float*)d_in[25];
    const float* bhh     = (const float*)d_in[26];
    float* out = (float*)d_out;

    // ---- weight prep, ordered so launch #6 is the acoustic GEMM (ncu -s 5) ----
    {
        int tot;
        tot = CA_ * EA_ * KA_;   // 1
        permute_w_kernel<<<(tot + 255) / 256, 256>>>(convA_w, OFF_WAT, CA_, EA_, KA_);
        tot = CL_ * EL_ * KL_;   // 2
        permute_w_kernel<<<(tot + 255) / 256, 256>>>(convL_w, OFF_WLT, CL_, EL_, KL_);
        tot = CE_ * HH_ * KE_;   // 3
        permute_w_kernel<<<(tot + 255) / 256, 256>>>(convE_w, OFF_WET, CE_, HH_, KE_);
        tot = 512 * EE_;         // 4
        transpose2d_kernel<<<(tot + 255) / 256, 256>>>(Wih, OFF_WIHT, 512, EE_);
        tot = 512 * HH_;         // 5
        transpose2d_kernel<<<(tot + 255) / 256, 256>>>(Whh, OFF_WHHT, 512, HH_);
    }

    // 6: acoustic GEMM (tf32 tensor cores) — the ncu-profiled launch
    conv_gemm_tf32_kernel<<<dim3(MA_ / TBM, CA_ / TBN), 256>>>(
        x_aco, OFF_WAT, OFF_CA, MA_, CA_, KKA_, WOA_, EA_, WA_ * EA_);

    // 7: linguistic GEMM (tf32)
    conv_gemm_tf32_kernel<<<dim3(ML_ / TBM, CL_ / TBN), 256>>>(
        x_lin, OFF_WLT, OFF_CL, ML_, CL_, KKL_, WOL_, EL_, WL_ * EL_);

    // 8: LSTM (-> hbuf)
    lstm_kernel<<<BT_ / SEQS, 512>>>(x_emo, wlen, bih, bhh);

    // 9: emotient GEMM (fp32, input = hbuf)
    conv_gemm_kernel<128, 64, 16, 8, 4><<<dim3(ME_ / 128, CE_ / 64), 256>>>(
        OFF_HBUF, OFF_WET, OFF_CE, ME_, CE_, KKE_, WOE_, HH_, WE_ * HH_);

    // 10-15: highway weight transposes (needed only by pool_highway)
    {
        int tot;
        tot = CL_ * CL_;
        transpose2d_kernel<<<(tot + 255) / 256, 256>>>(hwL_Wp, OFF_HWLPT, CL_, CL_);
        transpose2d_kernel<<<(tot + 255) / 256, 256>>>(hwL_Wg, OFF_HWLGT, CL_, CL_);
        tot = CA_ * CA_;
        transpose2d_kernel<<<(tot + 255) / 256, 256>>>(hwA_Wp, OFF_HWAPT, CA_, CA_);
        transpose2d_kernel<<<(tot + 255) / 256, 256>>>(hwA_Wg, OFF_HWAGT, CA_, CA_);
        tot = CE_ * CE_;
        transpose2d_kernel<<<(tot + 255) / 256, 256>>>(hwE_Wp, OFF_HWEPT, CE_, CE_);
        transpose2d_kernel<<<(tot + 255) / 256, 256>>>(hwE_Wg, OFF_HWEGT, CE_, CE_);
    }

    // 16-18: fused maxpool + highway -> output
    pool_highway_kernel<<<BT_, CL_, CL_ * sizeof(float)>>>(
        OFF_CL, CL_, WOL_, convL_b, OFF_HWLPT, hwL_bp, OFF_HWLGT, hwL_bg, out, 0);
    pool_highway_kernel<<<BT_, CA_, CA_ * sizeof(float)>>>(
        OFF_CA, CA_, WOA_, convA_b, OFF_HWAPT, hwA_bp, OFF_HWAGT, hwA_bg, out, CL_);
    pool_highway_kernel<<<BT_, CE_, CE_ * sizeof(float)>>>(
        OFF_CE, CE_, WOE_, convE_b, OFF_HWEPT, hwE_bp, OFF_HWEGT, hwE_bg, out, CL_ + CA_);
}

// round 8
// speedup vs baseline: 2.6773x; 1.3016x over previous
#include <cuda_runtime.h>
#include <cuda_fp16.h>
#include <math.h>
#include <stdint.h>

// ---------------------------------------------------------------------------
// Problem dimensions
// ---------------------------------------------------------------------------
#define BT_   1536
#define WL_   33
#define WA_   50
#define WE_   30
#define EL_   300
#define EA_   988
#define EE_   20
#define HH_   128
#define CL_   128
#define CA_   256
#define CE_   64
#define KL_   5
#define KA_   10
#define KE_   3
#define WOL_  (WL_ - KL_ + 1)      // 29
#define WOA_  (WA_ - KA_ + 1)      // 41
#define WOE_  (WE_ - KE_ + 1)      // 28
#define ML_   (BT_ * WOL_)         // 44544
#define MA_   (BT_ * WOA_)         // 62976
#define ME_   (BT_ * WOE_)         // 43008
#define KKL_  (KL_ * EL_)          // 1500
#define KKA_  (KA_ * EA_)          // 9880
#define KKE_  (KE_ * HH_)          // 384
#define OUTW_ 448

// ---------------------------------------------------------------------------
// Device scratch (identical layout to the passing round-2 kernel, 134 MB)
// ---------------------------------------------------------------------------
#define OFF_CA     ((size_t)0)
#define OFF_CL     ((size_t)16121856)
#define OFF_CE     ((size_t)21823488)
#define OFF_HBUF   ((size_t)24576000)
#define OFF_WAT    ((size_t)30474240)
#define OFF_WLT    ((size_t)33003520)
#define OFF_WET    ((size_t)33195520)
#define OFF_WIHT   ((size_t)33220096)
#define OFF_WHHT   ((size_t)33230336)
#define OFF_HWLPT  ((size_t)33295872)
#define OFF_HWLGT  ((size_t)33312256)
#define OFF_HWAPT  ((size_t)33328640)
#define OFF_HWAGT  ((size_t)33394176)
#define OFF_HWEPT  ((size_t)33459712)
#define OFF_HWEGT  ((size_t)33463808)
#define SCRATCH_TOTAL ((size_t)33467904)

__device__ __align__(16) float g_scratch[SCRATCH_TOTAL];

// ---------------------------------------------------------------------------
// Weight permute: (Cout, Cin, K) -> (Cout, K, Cin)   [verbatim from round 2]
// ---------------------------------------------------------------------------
__global__ void permute_w_kernel(const float* __restrict__ src, size_t dstOff,
                                 int Cout, int Cin, int K)
{
    int idx = blockIdx.x * 256 + threadIdx.x;
    int tot = Cout * Cin * K;
    if (idx >= tot) return;
    float* dst = g_scratch + dstOff;
    int ci = idx % Cin;
    int r  = idx / Cin;
    int k  = r % K;
    int co = r / K;
    dst[idx] = src[(size_t)co * Cin * K + (size_t)ci * K + k];
}

// 2D transpose: src (R x C) -> dst (C x R)   [verbatim from round 2]
__global__ void transpose2d_kernel(const float* __restrict__ src, size_t dstOff,
                                   int R, int C)
{
    int idx = blockIdx.x * 256 + threadIdx.x;
    int tot = R * C;
    if (idx >= tot) return;
    float* dst = g_scratch + dstOff;
    int r = idx % R;
    int c = idx / R;
    dst[idx] = src[(size_t)r * C + c];
}

// ---------------------------------------------------------------------------
// FP16 tensor-core conv-as-GEMM  (round-2 skeleton, mma shape m16n8k16.f16)
//   C[m][n] = dot(window(m), Wt[n][:]) ; fp32 inputs converted to half2 at STS
//   128x128x16 CTA tile, 8 warps (2x4), warp tile 64x32
// ---------------------------------------------------------------------------
__device__ __forceinline__ uint32_t f2h2(float lo, float hi) {
    __half2 h = __floats2half2_rn(lo, hi);
    return *(uint32_t*)&h;
}

__device__ __forceinline__ void mma_f16(float c[4], const uint32_t a[4],
                                        uint32_t b0, uint32_t b1) {
    asm volatile(
        "mma.sync.aligned.m16n8k16.row.col.f32.f16.f16.f32 "
        "{%0,%1,%2,%3}, {%4,%5,%6,%7}, {%8,%9}, {%0,%1,%2,%3};"
        : "+f"(c[0]), "+f"(c[1]), "+f"(c[2]), "+f"(c[3])
        : "r"(a[0]), "r"(a[1]), "r"(a[2]), "r"(a[3]), "r"(b0), "r"(b1));
}

#define TBM 128
#define TBN 128
#define TBK 16          // k-values (halves) per tile; 8 half2 smem rows

__global__ __launch_bounds__(256, 2)
void conv_gemm_f16_kernel(const float* __restrict__ X,
                          size_t wOff, size_t cOff,
                          int N, int KK,
                          int Wout, int rowStride, int btStride)
{
    __shared__ __align__(16) uint32_t As2[8][TBM + 4];   // half2: k=2*k2, 2*k2+1
    __shared__ __align__(16) uint32_t Bs2[8][TBN + 4];

    const float* Wt   = g_scratch + wOff;
    float*       Cmat = g_scratch + cOff;

    const int tid  = threadIdx.x;
    const int bm   = blockIdx.x * TBM;
    const int bn   = blockIdx.y * TBN;
    const int wid  = tid >> 5;
    const int lane = tid & 31;
    const int wm   = wid & 1;            // 0..1 (64 rows each)
    const int wn   = wid >> 1;           // 0..3 (32 cols each)
    const int g    = lane >> 2;          // 0..7
    const int c    = lane & 3;           // 0..3

    // loader mapping (256 threads, float4 granularity) — round-2 identical
    const int lr  = tid >> 2;            // 0..63
    const int lk  = (tid & 3) * 4;       // float offset 0,4,8,12
    const int k2s = (tid & 3) * 2;       // half2 slot 0,2,4,6

    const float* aRow[2];
#pragma unroll
    for (int v = 0; v < 2; v++) {
        int m  = bm + lr + v * 64;
        int bt = m / Wout;
        int t  = m - bt * Wout;
        aRow[v] = X + (size_t)bt * btStride + (size_t)t * rowStride;
    }
    const float* bRow[2];
#pragma unroll
    for (int v = 0; v < 2; v++) {
        int n = bn + lr + v * 64;
        bRow[v] = Wt + (size_t)n * KK;
    }

    float acc[4][4][4];
#pragma unroll
    for (int mi = 0; mi < 4; mi++)
#pragma unroll
        for (int ni = 0; ni < 4; ni++)
#pragma unroll
            for (int q = 0; q < 4; q++) acc[mi][ni][q] = 0.f;

    float4 ra[2], rb[2];

    // prefetch tile 0
    {
        int kg = lk;
        bool ok = (kg < KK);
#pragma unroll
        for (int v = 0; v < 2; v++)
            ra[v] = ok ? *(const float4*)(aRow[v] + kg)
                       : make_float4(0.f, 0.f, 0.f, 0.f);
#pragma unroll
        for (int v = 0; v < 2; v++)
            rb[v] = ok ? *(const float4*)(bRow[v] + kg)
                       : make_float4(0.f, 0.f, 0.f, 0.f);
    }
    // store tile 0 (convert fp32 -> half2)
#pragma unroll
    for (int v = 0; v < 2; v++) {
        int mr = lr + v * 64;
        As2[k2s + 0][mr] = f2h2(ra[v].x, ra[v].y);
        As2[k2s + 1][mr] = f2h2(ra[v].z, ra[v].w);
    }
#pragma unroll
    for (int v = 0; v < 2; v++) {
        int nr = lr + v * 64;
        Bs2[k2s + 0][nr] = f2h2(rb[v].x, rb[v].y);
        Bs2[k2s + 1][nr] = f2h2(rb[v].z, rb[v].w);
    }
    __syncthreads();

    for (int k0 = 0; k0 < KK; k0 += TBK) {
        const bool has_next = (k0 + TBK < KK);
        if (has_next) {
            int kg = k0 + TBK + lk;
            bool ok = (kg < KK);
#pragma unroll
            for (int v = 0; v < 2; v++)
                ra[v] = ok ? *(const float4*)(aRow[v] + kg)
                           : make_float4(0.f, 0.f, 0.f, 0.f);
#pragma unroll
            for (int v = 0; v < 2; v++)
                rb[v] = ok ? *(const float4*)(bRow[v] + kg)
                           : make_float4(0.f, 0.f, 0.f, 0.f);
        }

        // compute one k16 step: 16 HMMA per warp
        {
            uint32_t afr[4][4];
#pragma unroll
            for (int mi = 0; mi < 4; mi++) {
                int mr = wm * 64 + mi * 16 + g;
                afr[mi][0] = As2[c][mr];          // (g,   k 2c..2c+1)
                afr[mi][1] = As2[c][mr + 8];      // (g+8, k 2c..2c+1)
                afr[mi][2] = As2[c + 4][mr];      // (g,   k 2c+8..2c+9)
                afr[mi][3] = As2[c + 4][mr + 8];  // (g+8, k 2c+8..2c+9)
            }
            uint32_t bfr[4][2];
#pragma unroll
            for (int ni = 0; ni < 4; ni++) {
                int nr = wn * 32 + ni * 8 + g;
                bfr[ni][0] = Bs2[c][nr];          // (k 2c..2c+1,   n g)
                bfr[ni][1] = Bs2[c + 4][nr];      // (k 2c+8..2c+9, n g)
            }
#pragma unroll
            for (int mi = 0; mi < 4; mi++)
#pragma unroll
                for (int ni = 0; ni < 4; ni++)
                    mma_f16(acc[mi][ni], afr[mi], bfr[ni][0], bfr[ni][1]);
        }
        __syncthreads();

        if (has_next) {
#pragma unroll
            for (int v = 0; v < 2; v++) {
                int mr = lr + v * 64;
                As2[k2s + 0][mr] = f2h2(ra[v].x, ra[v].y);
                As2[k2s + 1][mr] = f2h2(ra[v].z, ra[v].w);
            }
#pragma unroll
            for (int v = 0; v < 2; v++) {
                int nr = lr + v * 64;
                Bs2[k2s + 0][nr] = f2h2(rb[v].x, rb[v].y);
                Bs2[k2s + 1][nr] = f2h2(rb[v].z, rb[v].w);
            }
            __syncthreads();
        }
    }

    // epilogue: c0:(row,col), c1:(row,col+1), c2:(row+8,col), c3:(row+8,col+1)
#pragma unroll
    for (int mi = 0; mi < 4; mi++) {
#pragma unroll
        for (int ni = 0; ni < 4; ni++) {
            int row = bm + wm * 64 + mi * 16 + g;
            int col = bn + wn * 32 + ni * 8 + c * 2;
            *(float2*)(Cmat + (size_t)row * N + col) =
                make_float2(acc[mi][ni][0], acc[mi][ni][1]);
            *(float2*)(Cmat + (size_t)(row + 8) * N + col) =
                make_float2(acc[mi][ni][2], acc[mi][ni][3]);
        }
    }
}

// ---------------------------------------------------------------------------
// FP32 conv-as-GEMM (small Emotient GEMM)   [verbatim from round 2]
// ---------------------------------------------------------------------------
template<int BM, int BN, int BK, int TM, int TN>
__global__ __launch_bounds__(256)
void conv_gemm_kernel(size_t xOff, size_t wOff, size_t cOff,
                      int M, int N, int KK,
                      int Wout, int rowStride, int btStride)
{
    static_assert((BM / TM) * (BN / TN) == 256, "256 threads");
    constexpr int A_VECS = BM * BK / (256 * 4);
    constexpr int B_VECS = BN * BK / (256 * 4);

    const float* X    = g_scratch + xOff;
    const float* Wt   = g_scratch + wOff;
    float*       Cmat = g_scratch + cOff;

    __shared__ __align__(16) float As[BK][BM + 4];
    __shared__ __align__(16) float Bs[BK][BN + 4];

    const int tid = threadIdx.x;
    const int bm  = blockIdx.x * BM;
    const int bn  = blockIdx.y * BN;
    const int lr = tid >> 2;
    const int lk = (tid & 3) * 4;

    const float* aRow[A_VECS];
#pragma unroll
    for (int v = 0; v < A_VECS; v++) {
        int m  = bm + lr + v * 64;
        int bt = m / Wout;
        int t  = m - bt * Wout;
        aRow[v] = X + (size_t)bt * btStride + (size_t)t * rowStride;
    }
    const float* bRow[B_VECS];
#pragma unroll
    for (int v = 0; v < B_VECS; v++) {
        int n = bn + lr + v * 64;
        bRow[v] = Wt + (size_t)n * KK;
    }

    float acc[TM][TN];
#pragma unroll
    for (int i = 0; i < TM; i++)
#pragma unroll
        for (int j = 0; j < TN; j++) acc[i][j] = 0.f;

    const int ty = tid / (BN / TN);
    const int tx = tid % (BN / TN);

    for (int k0 = 0; k0 < KK; k0 += BK) {
        int kg = k0 + lk;
        bool ok = (kg < KK);
#pragma unroll
        for (int v = 0; v < A_VECS; v++) {
            float4 a = ok ? *(const float4*)(aRow[v] + kg)
                          : make_float4(0.f, 0.f, 0.f, 0.f);
            int mr = lr + v * 64;
            As[lk + 0][mr] = a.x; As[lk + 1][mr] = a.y;
            As[lk + 2][mr] = a.z; As[lk + 3][mr] = a.w;
        }
#pragma unroll
        for (int v = 0; v < B_VECS; v++) {
            float4 b = ok ? *(const float4*)(bRow[v] + kg)
                          : make_float4(0.f, 0.f, 0.f, 0.f);
            int nr = lr + v * 64;
            Bs[lk + 0][nr] = b.x; Bs[lk + 1][nr] = b.y;
            Bs[lk + 2][nr] = b.z; Bs[lk + 3][nr] = b.w;
        }
        __syncthreads();

#pragma unroll
        for (int kk = 0; kk < BK; kk++) {
            float a[TM], b[TN];
#pragma unroll
            for (int i = 0; i < TM; i += 4) {
                float4 v = *(const float4*)&As[kk][ty * TM + i];
                a[i] = v.x; a[i + 1] = v.y; a[i + 2] = v.z; a[i + 3] = v.w;
            }
#pragma unroll
            for (int j = 0; j < TN; j += 4) {
                float4 v = *(const float4*)&Bs[kk][tx * TN + j];
                b[j] = v.x; b[j + 1] = v.y; b[j + 2] = v.z; b[j + 3] = v.w;
            }
#pragma unroll
            for (int i = 0; i < TM; i++)
#pragma unroll
                for (int j = 0; j < TN; j++)
                    acc[i][j] = fmaf(a[i], b[j], acc[i][j]);
        }
        __syncthreads();
    }

#pragma unroll
    for (int i = 0; i < TM; i++) {
        size_t m = (size_t)bm + ty * TM + i;
        float* cp = Cmat + m * (size_t)N + bn + tx * TN;
#pragma unroll
        for (int j = 0; j < TN; j += 4) {
            float4 v = make_float4(acc[i][j], acc[i][j + 1],
                                   acc[i][j + 2], acc[i][j + 3]);
            *(float4*)(cp + j) = v;
        }
    }
}

// ---------------------------------------------------------------------------
// Masked LSTM   [verbatim from round 2]
// ---------------------------------------------------------------------------
#define SEQS 8
__device__ __forceinline__ float sigf(float x) { return 1.f / (1.f + expf(-x)); }

__global__ __launch_bounds__(512)
void lstm_kernel(const float* __restrict__ xe,
                 const int*   __restrict__ wlen,
                 const float* __restrict__ bih,
                 const float* __restrict__ bhh)
{
    const float* WihT = g_scratch + OFF_WIHT;
    const float* WhhT = g_scratch + OFF_WHHT;
    float*       hbuf = g_scratch + OFF_HBUF;

    __shared__ float sh[SEQS][HH_];
    __shared__ float sc[SEQS][HH_];
    __shared__ float sx[SEQS][EE_];
    __shared__ float sz[4 * HH_][SEQS + 1];
    __shared__ int   slen[SEQS];

    const int tid = threadIdx.x;
    const int bt0 = blockIdx.x * SEQS;

    for (int i = tid; i < SEQS * HH_; i += 512) {
        (&sh[0][0])[i] = 0.f;
        (&sc[0][0])[i] = 0.f;
    }
    if (tid < SEQS) slen[tid] = wlen[bt0 + tid];
    __syncthreads();

    const int r = tid;
    const float bias = bih[r] + bhh[r];

    for (int t = 0; t < WE_; t++) {
        for (int i = tid; i < SEQS * EE_; i += 512) {
            int s = i / EE_, e = i - s * EE_;
            sx[s][e] = xe[(size_t)(bt0 + s) * (WE_ * EE_) + t * EE_ + e];
        }
        __syncthreads();

        float acc[SEQS];
#pragma unroll
        for (int s = 0; s < SEQS; s++) acc[s] = bias;
#pragma unroll
        for (int e = 0; e < EE_; e++) {
            float w = WihT[e * 512 + r];
#pragma unroll
            for (int s = 0; s < SEQS; s++) acc[s] = fmaf(w, sx[s][e], acc[s]);
        }
#pragma unroll 4
        for (int j = 0; j < HH_; j++) {
            float w = WhhT[j * 512 + r];
#pragma unroll
            for (int s = 0; s < SEQS; s++) acc[s] = fmaf(w, sh[s][j], acc[s]);
        }
#pragma unroll
        for (int s = 0; s < SEQS; s++) sz[r][s] = acc[s];
        __syncthreads();

#pragma unroll
        for (int p = tid; p < SEQS * HH_; p += 512) {
            int s = p & (SEQS - 1);
            int j = p >> 3;
            float zi = sz[j][s];
            float zf = sz[HH_ + j][s];
            float zg = sz[2 * HH_ + j][s];
            float zo = sz[3 * HH_ + j][s];
            float cc = sc[s][j];
            float cn = sigf(zf) * cc + sigf(zi) * tanhf(zg);
            float hn = sigf(zo) * tanhf(cn);
            bool valid = (t < slen[s]);
            sc[s][j] = valid ? cn : cc;
            sh[s][j] = valid ? hn : sh[s][j];
            hbuf[(size_t)(bt0 + s) * (WE_ * HH_) + t * HH_ + j] = valid ? hn : 0.f;
        }
        __syncthreads();
    }
}

// ---------------------------------------------------------------------------
// Fused maxpool(+conv bias) + highway   [verbatim from round 2]
// ---------------------------------------------------------------------------
__global__ void pool_highway_kernel(size_t cOff, int N, int Wout,
                                    const float* __restrict__ convB,
                                    size_t wpOff, const float* __restrict__ bp,
                                    size_t wgOff, const float* __restrict__ bg,
                                    float* __restrict__ out, int outOff)
{
    extern __shared__ float sy[];
    const float* Cmat = g_scratch + cOff;
    const float* WpT  = g_scratch + wpOff;
    const float* WgT  = g_scratch + wgOff;

    int bt = blockIdx.x;
    int co = threadIdx.x;

    const float* cp = Cmat + (size_t)bt * Wout * N + co;
    float y = cp[0];
    for (int t = 1; t < Wout; t++) y = fmaxf(y, cp[(size_t)t * N]);
    y += convB[co];
    sy[co] = y;
    __syncthreads();

    float ap = bp[co], ag = bg[co];
    for (int j = 0; j < N; j++) {
        float yj = sy[j];
        ap = fmaf(WpT[j * N + co], yj, ap);
        ag = fmaf(WgT[j * N + co], yj, ag);
    }
    float p = fmaxf(ap, 0.f);
    float gg = 1.f / (1.f + expf(-ag));
    out[(size_t)bt * OUTW_ + outOff + co] = gg * p + (1.f - gg) * y;
}

// ---------------------------------------------------------------------------
// Launch
// ---------------------------------------------------------------------------
extern "C" void kernel_launch(void* const* d_in, const int* in_sizes, int n_in,
                              void* d_out, int out_size)
{
    (void)in_sizes; (void)n_in; (void)out_size;
    const float* x_lin   = (const float*)d_in[0];
    const float* x_aco   = (const float*)d_in[1];
    const float* x_emo   = (const float*)d_in[2];
    const int*   wlen    = (const int*)  d_in[3];
    const float* convL_w = (const float*)d_in[5];
    const float* convL_b = (const float*)d_in[6];
    const float* convA_w = (const float*)d_in[7];
    const float* convA_b = (const float*)d_in[8];
    const float* convE_w = (const float*)d_in[9];
    const float* convE_b = (const float*)d_in[10];
    const float* hwL_Wp  = (const float*)d_in[11];
    const float* hwL_bp  = (const float*)d_in[12];
    const float* hwL_Wg  = (const float*)d_in[13];
    const float* hwL_bg  = (const float*)d_in[14];
    const float* hwA_Wp  = (const float*)d_in[15];
    const float* hwA_bp  = (const float*)d_in[16];
    const float* hwA_Wg  = (const float*)d_in[17];
    const float* hwA_bg  = (const float*)d_in[18];
    const float* hwE_Wp  = (const float*)d_in[19];
    const float* hwE_bp  = (const float*)d_in[20];
    const float* hwE_Wg  = (const float*)d_in[21];
    const float* hwE_bg  = (const float*)d_in[22];
    const float* Wih     = (const float*)d_in[23];
    const float* Whh     = (const float*)d_in[24];
    const float* bih     = (const float*)d_in[25];
    const float* bhh     = (const float*)d_in[26];
    float* out = (float*)d_out;

    // 1-3: conv weight permutes
    permute_w_kernel<<<(CA_ * EA_ * KA_ + 255) / 256, 256>>>(convA_w, OFF_WAT, CA_, EA_, KA_);
    permute_w_kernel<<<(CL_ * EL_ * KL_ + 255) / 256, 256>>>(convL_w, OFF_WLT, CL_, EL_, KL_);
    permute_w_kernel<<<(CE_ * HH_ * KE_ + 255) / 256, 256>>>(convE_w, OFF_WET, CE_, HH_, KE_);

    // 4: acoustic GEMM (fp16 HMMA) — the ncu-profiled launch
    conv_gemm_f16_kernel<<<dim3(MA_ / TBM, CA_ / TBN), 256>>>(
        x_aco, OFF_WAT, OFF_CA, CA_, KKA_, WOA_, EA_, WA_ * EA_);

    // 5: linguistic GEMM (fp16 HMMA)
    conv_gemm_f16_kernel<<<dim3(ML_ / TBM, CL_ / TBN), 256>>>(
        x_lin, OFF_WLT, OFF_CL, CL_, KKL_, WOL_, EL_, WL_ * EL_);

    // 6-7: LSTM weight transposes
    transpose2d_kernel<<<(512 * EE_ + 255) / 256, 256>>>(Wih, OFF_WIHT, 512, EE_);
    transpose2d_kernel<<<(512 * HH_ + 255) / 256, 256>>>(Whh, OFF_WHHT, 512, HH_);

    // 8: LSTM (-> hbuf)
    lstm_kernel<<<BT_ / SEQS, 512>>>(x_emo, wlen, bih, bhh);

    // 9: emotient GEMM (fp32, input = hbuf)
    conv_gemm_kernel<128, 64, 16, 8, 4><<<dim3(ME_ / 128, CE_ / 64), 256>>>(
        OFF_HBUF, OFF_WET, OFF_CE, ME_, CE_, KKE_, WOE_, HH_, WE_ * HH_);

    // 10-15: highway weight transposes
    transpose2d_kernel<<<(CL_ * CL_ + 255) / 256, 256>>>(hwL_Wp, OFF_HWLPT, CL_, CL_);
    transpose2d_kernel<<<(CL_ * CL_ + 255) / 256, 256>>>(hwL_Wg, OFF_HWLGT, CL_, CL_);
    transpose2d_kernel<<<(CA_ * CA_ + 255) / 256, 256>>>(hwA_Wp, OFF_HWAPT, CA_, CA_);
    transpose2d_kernel<<<(CA_ * CA_ + 255) / 256, 256>>>(hwA_Wg, OFF_HWAGT, CA_, CA_);
    transpose2d_kernel<<<(CE_ * CE_ + 255) / 256, 256>>>(hwE_Wp, OFF_HWEPT, CE_, CE_);
    transpose2d_kernel<<<(CE_ * CE_ + 255) / 256, 256>>>(hwE_Wg, OFF_HWEGT, CE_, CE_);

    // 16-18: fused maxpool + highway -> output
    pool_highway_kernel<<<BT_, CL_, CL_ * sizeof(float)>>>(
        OFF_CL, CL_, WOL_, convL_b, OFF_HWLPT, hwL_bp, OFF_HWLGT, hwL_bg, out, 0);
    pool_highway_kernel<<<BT_, CA_, CA_ * sizeof(float)>>>(
        OFF_CA, CA_, WOA_, convA_b, OFF_HWAPT, hwA_bp, OFF_HWAGT, hwA_bg, out, CL_);
    pool_highway_kernel<<<BT_, CE_, CE_ * sizeof(float)>>>(
        OFF_CE, CE_, WOE_, convE_b, OFF_HWEPT, hwE_bp, OFF_HWEGT, hwE_bg, out, CL_ + CA_);
}

// round 9
// speedup vs baseline: 2.8264x; 1.0557x over previous
#include <cuda_runtime.h>
#include <cuda_fp16.h>
#include <math.h>
#include <stdint.h>

// ---------------------------------------------------------------------------
// Problem dimensions
// ---------------------------------------------------------------------------
#define BT_   1536
#define WL_   33
#define WA_   50
#define WE_   30
#define EL_   300
#define EA_   988
#define EE_   20
#define HH_   128
#define CL_   128
#define CA_   256
#define CE_   64
#define KL_   5
#define KA_   10
#define KE_   3
#define WOL_  (WL_ - KL_ + 1)      // 29
#define WOA_  (WA_ - KA_ + 1)      // 41
#define WOE_  (WE_ - KE_ + 1)      // 28
#define ML_   (BT_ * WOL_)         // 44544
#define MA_   (BT_ * WOA_)         // 62976
#define ME_   (BT_ * WOE_)         // 43008
#define KKL_  (KL_ * EL_)          // 1500
#define KKA_  (KA_ * EA_)          // 9880
#define KKE_  (KE_ * HH_)          // 384
#define OUTW_ 448

// ---------------------------------------------------------------------------
// Device scratch (identical layout to passing rounds 2/8)
// ---------------------------------------------------------------------------
#define OFF_CA     ((size_t)0)
#define OFF_CL     ((size_t)16121856)
#define OFF_CE     ((size_t)21823488)
#define OFF_HBUF   ((size_t)24576000)
#define OFF_WAT    ((size_t)30474240)
#define OFF_WLT    ((size_t)33003520)
#define OFF_WET    ((size_t)33195520)
#define OFF_WIHT   ((size_t)33220096)
#define OFF_WHHT   ((size_t)33230336)
#define OFF_HWLPT  ((size_t)33295872)
#define OFF_HWLGT  ((size_t)33312256)
#define OFF_HWAPT  ((size_t)33328640)
#define OFF_HWAGT  ((size_t)33394176)
#define OFF_HWEPT  ((size_t)33459712)
#define OFF_HWEGT  ((size_t)33463808)
#define SCRATCH_TOTAL ((size_t)33467904)

__device__ __align__(16) float g_scratch[SCRATCH_TOTAL];

// ---------------------------------------------------------------------------
// Weight permute: (Cout, Cin, K) -> (Cout, K, Cin)
// ---------------------------------------------------------------------------
__global__ void permute_w_kernel(const float* __restrict__ src, size_t dstOff,
                                 int Cout, int Cin, int K)
{
    int idx = blockIdx.x * 256 + threadIdx.x;
    int tot = Cout * Cin * K;
    if (idx >= tot) return;
    float* dst = g_scratch + dstOff;
    int ci = idx % Cin;
    int r  = idx / Cin;
    int k  = r % K;
    int co = r / K;
    dst[idx] = src[(size_t)co * Cin * K + (size_t)ci * K + k];
}

// 2D transpose: src (R x C) -> dst (C x R)
__global__ void transpose2d_kernel(const float* __restrict__ src, size_t dstOff,
                                   int R, int C)
{
    int idx = blockIdx.x * 256 + threadIdx.x;
    int tot = R * C;
    if (idx >= tot) return;
    float* dst = g_scratch + dstOff;
    int r = idx % R;
    int c = idx / R;
    dst[idx] = src[(size_t)r * C + c];
}

// ---------------------------------------------------------------------------
// FP16 HMMA conv-as-GEMM, vectorized-fragment smem layout + double buffer
//   C[m][n] = dot(window(m), Wt[n][:]) ; fp32 -> half2 at STS
//   128x128x16 CTA tile, 8 warps (2x4), warp tile 64x32, m16n8k16
//   A frag = 1 x LDS.128 / mi ; B frag = 1 x LDS.64 / ni  (conflict-free)
// ---------------------------------------------------------------------------
__device__ __forceinline__ uint32_t f2h2(float lo, float hi) {
    __half2 h = __floats2half2_rn(lo, hi);
    return *(uint32_t*)&h;
}

__device__ __forceinline__ void mma_f16(float c[4], uint32_t a0, uint32_t a1,
                                        uint32_t a2, uint32_t a3,
                                        uint32_t b0, uint32_t b1) {
    asm volatile(
        "mma.sync.aligned.m16n8k16.row.col.f32.f16.f16.f32 "
        "{%0,%1,%2,%3}, {%4,%5,%6,%7}, {%8,%9}, {%0,%1,%2,%3};"
        : "+f"(c[0]), "+f"(c[1]), "+f"(c[2]), "+f"(c[3])
        : "r"(a0), "r"(a1), "r"(a2), "r"(a3), "r"(b0), "r"(b1));
}

#define TBM 128
#define TBN 128
#define TBK 16
#define ASTR 264          // row stride (uint32) ; 264 mod 32 = 8 -> conflict-free frag reads

__global__ __launch_bounds__(256, 2)
void conv_gemm_f16_kernel(const float* __restrict__ X,
                          size_t wOff, size_t cOff,
                          int N, int KK,
                          int Wout, int rowStride, int btStride)
{
    // layout: value (m, k2-slot s) at  [s&3][ (m>>4)*32 + (m&7)*4 + (s>>2)*2 + ((m&15)>>3) ]
    //         value (n, k2-slot s) at  [s&3][ n*2 + (s>>2) ]
    __shared__ __align__(16) uint32_t As[2][4][ASTR];
    __shared__ __align__(16) uint32_t Bs[2][4][ASTR];

    const float* Wt   = g_scratch + wOff;
    float*       Cmat = g_scratch + cOff;

    const int tid  = threadIdx.x;
    const int bm   = blockIdx.x * TBM;
    const int bn   = blockIdx.y * TBN;
    const int wid  = tid >> 5;
    const int lane = tid & 31;
    const int wm   = wid & 1;            // 0..1 (64 rows each)
    const int wn   = wid >> 1;           // 0..3 (32 cols each)
    const int g    = lane >> 2;          // 0..7
    const int c    = lane & 3;           // 0..3

    // loader mapping (256 threads, float4 granularity)
    const int lr   = tid >> 2;           // 0..63
    const int lk   = (tid & 3) * 4;      // float offset 0,4,8,12
    const int hb   = (tid & 3) >> 1;     // h group of slots k2s,k2s+1
    const int row0 = ((tid & 3) * 2) & 3; // 0 or 2

    const float* aRow[2];
    const float* bRow[2];
    int cA[2], cB[2];
#pragma unroll
    for (int v = 0; v < 2; v++) {
        int mr = lr + v * 64;
        int m  = bm + mr;
        int bt = m / Wout;
        int t  = m - bt * Wout;
        aRow[v] = X + (size_t)bt * btStride + (size_t)t * rowStride;
        int q = mr >> 4, r = mr & 15;
        cA[v] = q * 32 + (r & 7) * 4 + hb * 2 + (r >> 3);
        cB[v] = mr * 2 + hb;
        bRow[v] = Wt + (size_t)(bn + mr) * KK;
    }

    float acc[4][4][4];
#pragma unroll
    for (int mi = 0; mi < 4; mi++)
#pragma unroll
        for (int ni = 0; ni < 4; ni++)
#pragma unroll
            for (int q = 0; q < 4; q++) acc[mi][ni][q] = 0.f;

    float4 ra[2], rb[2];

    // ---- load + store tile 0 (stage 0)
    {
        bool ok = (lk < KK);
#pragma unroll
        for (int v = 0; v < 2; v++) {
            ra[v] = ok ? *(const float4*)(aRow[v] + lk)
                       : make_float4(0.f, 0.f, 0.f, 0.f);
            rb[v] = ok ? *(const float4*)(bRow[v] + lk)
                       : make_float4(0.f, 0.f, 0.f, 0.f);
        }
#pragma unroll
        for (int v = 0; v < 2; v++) {
            As[0][row0    ][cA[v]] = f2h2(ra[v].x, ra[v].y);
            As[0][row0 + 1][cA[v]] = f2h2(ra[v].z, ra[v].w);
            Bs[0][row0    ][cB[v]] = f2h2(rb[v].x, rb[v].y);
            Bs[0][row0 + 1][cB[v]] = f2h2(rb[v].z, rb[v].w);
        }
    }
    __syncthreads();

    const int ktiles = (KK + TBK - 1) / TBK;
    for (int kt = 0; kt < ktiles; kt++) {
        const bool more = (kt + 1 < ktiles);
        if (more) {
            int kg = (kt + 1) * TBK + lk;
            bool ok = (kg < KK);
#pragma unroll
            for (int v = 0; v < 2; v++) {
                ra[v] = ok ? *(const float4*)(aRow[v] + kg)
                           : make_float4(0.f, 0.f, 0.f, 0.f);
                rb[v] = ok ? *(const float4*)(bRow[v] + kg)
                           : make_float4(0.f, 0.f, 0.f, 0.f);
            }
        }

        // ---- compute from stage kt&1
        {
            const int st = kt & 1;
            uint2 bfr[4];
#pragma unroll
            for (int ni = 0; ni < 4; ni++)
                bfr[ni] = *(const uint2*)&Bs[st][c][(wn * 32 + ni * 8 + g) * 2];
#pragma unroll
            for (int mi = 0; mi < 4; mi++) {
                uint4 av = *(const uint4*)&As[st][c][(wm * 4 + mi) * 32 + g * 4];
#pragma unroll
                for (int ni = 0; ni < 4; ni++)
                    mma_f16(acc[mi][ni], av.x, av.y, av.z, av.w,
                            bfr[ni].x, bfr[ni].y);
            }
        }

        if (more) {
            const int st = (kt + 1) & 1;
#pragma unroll
            for (int v = 0; v < 2; v++) {
                As[st][row0    ][cA[v]] = f2h2(ra[v].x, ra[v].y);
                As[st][row0 + 1][cA[v]] = f2h2(ra[v].z, ra[v].w);
                Bs[st][row0    ][cB[v]] = f2h2(rb[v].x, rb[v].y);
                Bs[st][row0 + 1][cB[v]] = f2h2(rb[v].z, rb[v].w);
            }
            __syncthreads();
        }
    }

    // epilogue: c0:(row,col), c1:(row,col+1), c2:(row+8,col), c3:(row+8,col+1)
#pragma unroll
    for (int mi = 0; mi < 4; mi++) {
#pragma unroll
        for (int ni = 0; ni < 4; ni++) {
            int row = bm + wm * 64 + mi * 16 + g;
            int col = bn + wn * 32 + ni * 8 + c * 2;
            *(float2*)(Cmat + (size_t)row * N + col) =
                make_float2(acc[mi][ni][0], acc[mi][ni][1]);
            *(float2*)(Cmat + (size_t)(row + 8) * N + col) =
                make_float2(acc[mi][ni][2], acc[mi][ni][3]);
        }
    }
}

// ---------------------------------------------------------------------------
// FP32 conv-as-GEMM (small Emotient GEMM)   [verbatim from round 2]
// ---------------------------------------------------------------------------
template<int BM, int BN, int BK, int TM, int TN>
__global__ __launch_bounds__(256)
void conv_gemm_kernel(size_t xOff, size_t wOff, size_t cOff,
                      int M, int N, int KK,
                      int Wout, int rowStride, int btStride)
{
    static_assert((BM / TM) * (BN / TN) == 256, "256 threads");
    constexpr int A_VECS = BM * BK / (256 * 4);
    constexpr int B_VECS = BN * BK / (256 * 4);

    const float* X    = g_scratch + xOff;
    const float* Wt   = g_scratch + wOff;
    float*       Cmat = g_scratch + cOff;

    __shared__ __align__(16) float As[BK][BM + 4];
    __shared__ __align__(16) float Bs[BK][BN + 4];

    const int tid = threadIdx.x;
    const int bm  = blockIdx.x * BM;
    const int bn  = blockIdx.y * BN;
    const int lr = tid >> 2;
    const int lk = (tid & 3) * 4;

    const float* aRow[A_VECS];
#pragma unroll
    for (int v = 0; v < A_VECS; v++) {
        int m  = bm + lr + v * 64;
        int bt = m / Wout;
        int t  = m - bt * Wout;
        aRow[v] = X + (size_t)bt * btStride + (size_t)t * rowStride;
    }
    const float* bRow[B_VECS];
#pragma unroll
    for (int v = 0; v < B_VECS; v++) {
        int n = bn + lr + v * 64;
        bRow[v] = Wt + (size_t)n * KK;
    }

    float acc[TM][TN];
#pragma unroll
    for (int i = 0; i < TM; i++)
#pragma unroll
        for (int j = 0; j < TN; j++) acc[i][j] = 0.f;

    const int ty = tid / (BN / TN);
    const int tx = tid % (BN / TN);

    for (int k0 = 0; k0 < KK; k0 += BK) {
        int kg = k0 + lk;
        bool ok = (kg < KK);
#pragma unroll
        for (int v = 0; v < A_VECS; v++) {
            float4 a = ok ? *(const float4*)(aRow[v] + kg)
                          : make_float4(0.f, 0.f, 0.f, 0.f);
            int mr = lr + v * 64;
            As[lk + 0][mr] = a.x; As[lk + 1][mr] = a.y;
            As[lk + 2][mr] = a.z; As[lk + 3][mr] = a.w;
        }
#pragma unroll
        for (int v = 0; v < B_VECS; v++) {
            float4 b = ok ? *(const float4*)(bRow[v] + kg)
                          : make_float4(0.f, 0.f, 0.f, 0.f);
            int nr = lr + v * 64;
            Bs[lk + 0][nr] = b.x; Bs[lk + 1][nr] = b.y;
            Bs[lk + 2][nr] = b.z; Bs[lk + 3][nr] = b.w;
        }
        __syncthreads();

#pragma unroll
        for (int kk = 0; kk < BK; kk++) {
            float a[TM], b[TN];
#pragma unroll
            for (int i = 0; i < TM; i += 4) {
                float4 v = *(const float4*)&As[kk][ty * TM + i];
                a[i] = v.x; a[i + 1] = v.y; a[i + 2] = v.z; a[i + 3] = v.w;
            }
#pragma unroll
            for (int j = 0; j < TN; j += 4) {
                float4 v = *(const float4*)&Bs[kk][tx * TN + j];
                b[j] = v.x; b[j + 1] = v.y; b[j + 2] = v.z; b[j + 3] = v.w;
            }
#pragma unroll
            for (int i = 0; i < TM; i++)
#pragma unroll
                for (int j = 0; j < TN; j++)
                    acc[i][j] = fmaf(a[i], b[j], acc[i][j]);
        }
        __syncthreads();
    }

#pragma unroll
    for (int i = 0; i < TM; i++) {
        size_t m = (size_t)bm + ty * TM + i;
        float* cp = Cmat + m * (size_t)N + bn + tx * TN;
#pragma unroll
        for (int j = 0; j < TN; j += 4) {
            float4 v = make_float4(acc[i][j], acc[i][j + 1],
                                   acc[i][j + 2], acc[i][j + 3]);
            *(float4*)(cp + j) = v;
        }
    }
}

// ---------------------------------------------------------------------------
// Masked LSTM: 8 sequences per block, 512 threads (one gate-row each)
// ---------------------------------------------------------------------------
#define SEQS 8
__device__ __forceinline__ float sigf(float x) { return 1.f / (1.f + expf(-x)); }

__global__ __launch_bounds__(512)
void lstm_kernel(const float* __restrict__ xe,
                 const int*   __restrict__ wlen,
                 const float* __restrict__ bih,
                 const float* __restrict__ bhh)
{
    const float* WihT = g_scratch + OFF_WIHT;
    const float* WhhT = g_scratch + OFF_WHHT;
    float*       hbuf = g_scratch + OFF_HBUF;

    __shared__ float sh[SEQS][HH_];
    __shared__ float sc[SEQS][HH_];
    __shared__ float sx[SEQS][EE_];
    __shared__ float sz[4 * HH_][SEQS + 1];
    __shared__ int   slen[SEQS];

    const int tid = threadIdx.x;
    const int bt0 = blockIdx.x * SEQS;

    for (int i = tid; i < SEQS * HH_; i += 512) {
        (&sh[0][0])[i] = 0.f;
        (&sc[0][0])[i] = 0.f;
    }
    if (tid < SEQS) slen[tid] = wlen[bt0 + tid];
    __syncthreads();

    const int r = tid;
    const float bias = bih[r] + bhh[r];

    for (int t = 0; t < WE_; t++) {
        for (int i = tid; i < SEQS * EE_; i += 512) {
            int s = i / EE_, e = i - s * EE_;
            sx[s][e] = xe[(size_t)(bt0 + s) * (WE_ * EE_) + t * EE_ + e];
        }
        __syncthreads();

        float acc[SEQS];
#pragma unroll
        for (int s = 0; s < SEQS; s++) acc[s] = bias;
#pragma unroll
        for (int e = 0; e < EE_; e++) {
            float w = WihT[e * 512 + r];
#pragma unroll
            for (int s = 0; s < SEQS; s++) acc[s] = fmaf(w, sx[s][e], acc[s]);
        }
#pragma unroll 4
        for (int j = 0; j < HH_; j++) {
            float w = WhhT[j * 512 + r];
#pragma unroll
            for (int s = 0; s < SEQS; s++) acc[s] = fmaf(w, sh[s][j], acc[s]);
        }
#pragma unroll
        for (int s = 0; s < SEQS; s++) sz[r][s] = acc[s];
        __syncthreads();

#pragma unroll
        for (int p = tid; p < SEQS * HH_; p += 512) {
            int s = p & (SEQS - 1);
            int j = p >> 3;
            float zi = sz[j][s];
            float zf = sz[HH_ + j][s];
            float zg = sz[2 * HH_ + j][s];
            float zo = sz[3 * HH_ + j][s];
            float cc = sc[s][j];
            float cn = sigf(zf) * cc + sigf(zi) * tanhf(zg);
            float hn = sigf(zo) * tanhf(cn);
            bool valid = (t < slen[s]);
            sc[s][j] = valid ? cn : cc;
            sh[s][j] = valid ? hn : sh[s][j];
            hbuf[(size_t)(bt0 + s) * (WE_ * HH_) + t * HH_ + j] = valid ? hn : 0.f;
        }
        __syncthreads();
    }
}

// ---------------------------------------------------------------------------
// Fused maxpool(+conv bias) + highway, writes final output slice
// ---------------------------------------------------------------------------
__global__ void pool_highway_kernel(size_t cOff, int N, int Wout,
                                    const float* __restrict__ convB,
                                    size_t wpOff, const float* __restrict__ bp,
                                    size_t wgOff, const float* __restrict__ bg,
                                    float* __restrict__ out, int outOff)
{
    extern __shared__ float sy[];
    const float* Cmat = g_scratch + cOff;
    const float* WpT  = g_scratch + wpOff;
    const float* WgT  = g_scratch + wgOff;

    int bt = blockIdx.x;
    int co = threadIdx.x;

    const float* cp = Cmat + (size_t)bt * Wout * N + co;
    float y = cp[0];
    for (int t = 1; t < Wout; t++) y = fmaxf(y, cp[(size_t)t * N]);
    y += convB[co];
    sy[co] = y;
    __syncthreads();

    float ap = bp[co], ag = bg[co];
    for (int j = 0; j < N; j++) {
        float yj = sy[j];
        ap = fmaf(WpT[j * N + co], yj, ap);
        ag = fmaf(WgT[j * N + co], yj, ag);
    }
    float p = fmaxf(ap, 0.f);
    float gg = 1.f / (1.f + expf(-ag));
    out[(size_t)bt * OUTW_ + outOff + co] = gg * p + (1.f - gg) * y;
}

// ---------------------------------------------------------------------------
// Launch
// ---------------------------------------------------------------------------
extern "C" void kernel_launch(void* const* d_in, const int* in_sizes, int n_in,
                              void* d_out, int out_size)
{
    (void)in_sizes; (void)n_in; (void)out_size;
    const float* x_lin   = (const float*)d_in[0];
    const float* x_aco   = (const float*)d_in[1];
    const float* x_emo   = (const float*)d_in[2];
    const int*   wlen    = (const int*)  d_in[3];
    const float* convL_w = (const float*)d_in[5];
    const float* convL_b = (const float*)d_in[6];
    const float* convA_w = (const float*)d_in[7];
    const float* convA_b = (const float*)d_in[8];
    const float* convE_w = (const float*)d_in[9];
    const float* convE_b = (const float*)d_in[10];
    const float* hwL_Wp  = (const float*)d_in[11];
    const float* hwL_bp  = (const float*)d_in[12];
    const float* hwL_Wg  = (const float*)d_in[13];
    const float* hwL_bg  = (const float*)d_in[14];
    const float* hwA_Wp  = (const float*)d_in[15];
    const float* hwA_bp  = (const float*)d_in[16];
    const float* hwA_Wg  = (const float*)d_in[17];
    const float* hwA_bg  = (const float*)d_in[18];
    const float* hwE_Wp  = (const float*)d_in[19];
    const float* hwE_bp  = (const float*)d_in[20];
    const float* hwE_Wg  = (const float*)d_in[21];
    const float* hwE_bg  = (const float*)d_in[22];
    const float* Wih     = (const float*)d_in[23];
    const float* Whh     = (const float*)d_in[24];
    const float* bih     = (const float*)d_in[25];
    const float* bhh     = (const float*)d_in[26];
    float* out = (float*)d_out;

    // 1-3: conv weight permutes
    permute_w_kernel<<<(CA_ * EA_ * KA_ + 255) / 256, 256>>>(convA_w, OFF_WAT, CA_, EA_, KA_);
    permute_w_kernel<<<(CL_ * EL_ * KL_ + 255) / 256, 256>>>(convL_w, OFF_WLT, CL_, EL_, KL_);
    permute_w_kernel<<<(CE_ * HH_ * KE_ + 255) / 256, 256>>>(convE_w, OFF_WET, CE_, HH_, KE_);

    // 4: acoustic GEMM (fp16 HMMA) — the ncu-profiled launch
    conv_gemm_f16_kernel<<<dim3(MA_ / TBM, CA_ / TBN), 256>>>(
        x_aco, OFF_WAT, OFF_CA, CA_, KKA_, WOA_, EA_, WA_ * EA_);

    // 5: linguistic GEMM (fp16 HMMA)
    conv_gemm_f16_kernel<<<dim3(ML_ / TBM, CL_ / TBN), 256>>>(
        x_lin, OFF_WLT, OFF_CL, CL_, KKL_, WOL_, EL_, WL_ * EL_);

    // 6-7: LSTM weight transposes
    transpose2d_kernel<<<(512 * EE_ + 255) / 256, 256>>>(Wih, OFF_WIHT, 512, EE_);
    transpose2d_kernel<<<(512 * HH_ + 255) / 256, 256>>>(Whh, OFF_WHHT, 512, HH_);

    // 8: LSTM (-> hbuf)
    lstm_kernel<<<BT_ / SEQS, 512>>>(x_emo, wlen, bih, bhh);

    // 9: emotient GEMM (fp32, input = hbuf)
    conv_gemm_kernel<128, 64, 16, 8, 4><<<dim3(ME_ / 128, CE_ / 64), 256>>>(
        OFF_HBUF, OFF_WET, OFF_CE, ME_, CE_, KKE_, WOE_, HH_, WE_ * HH_);

    // 10-15: highway weight transposes
    transpose2d_kernel<<<(CL_ * CL_ + 255) / 256, 256>>>(hwL_Wp, OFF_HWLPT, CL_, CL_);
    transpose2d_kernel<<<(CL_ * CL_ + 255) / 256, 256>>>(hwL_Wg, OFF_HWLGT, CL_, CL_);
    transpose2d_kernel<<<(CA_ * CA_ + 255) / 256, 256>>>(hwA_Wp, OFF_HWAPT, CA_, CA_);
    transpose2d_kernel<<<(CA_ * CA_ + 255) / 256, 256>>>(hwA_Wg, OFF_HWAGT, CA_, CA_);
    transpose2d_kernel<<<(CE_ * CE_ + 255) / 256, 256>>>(hwE_Wp, OFF_HWEPT, CE_, CE_);
    transpose2d_kernel<<<(CE_ * CE_ + 255) / 256, 256>>>(hwE_Wg, OFF_HWEGT, CE_, CE_);

    // 16-18: fused maxpool + highway -> output
    pool_highway_kernel<<<BT_, CL_, CL_ * sizeof(float)>>>(
        OFF_CL, CL_, WOL_, convL_b, OFF_HWLPT, hwL_bp, OFF_HWLGT, hwL_bg, out, 0);
    pool_highway_kernel<<<BT_, CA_, CA_ * sizeof(float)>>>(
        OFF_CA, CA_, WOA_, convA_b, OFF_HWAPT, hwA_bp, OFF_HWAGT, hwA_bg, out, CL_);
    pool_highway_kernel<<<BT_, CE_, CE_ * sizeof(float)>>>(
        OFF_CE, CE_, WOE_, convE_b, OFF_HWEPT, hwE_bp, OFF_HWEGT, hwE_bg, out, CL_ + CA_);
}

// round 10
// speedup vs baseline: 3.4102x; 1.2066x over previous
#include <cuda_runtime.h>
#include <cuda_fp16.h>
#include <math.h>
#include <stdint.h>

// ---------------------------------------------------------------------------
// Problem dimensions
// ---------------------------------------------------------------------------
#define BT_   1536
#define WL_   33
#define WA_   50
#define WE_   30
#define EL_   300
#define EA_   988
#define EE_   20
#define HH_   128
#define CL_   128
#define CA_   256
#define CE_   64
#define KL_   5
#define KA_   10
#define KE_   3
#define WOL_  (WL_ - KL_ + 1)      // 29
#define WOA_  (WA_ - KA_ + 1)      // 41
#define WOE_  (WE_ - KE_ + 1)      // 28
#define ML_   (BT_ * WOL_)         // 44544
#define MA_   (BT_ * WOA_)         // 62976
#define ME_   (BT_ * WOE_)         // 43008
#define KKL_  (KL_ * EL_)          // 1500
#define KKA_  (KA_ * EA_)          // 9880
#define KKE_  (KE_ * HH_)          // 384
#define OUTW_ 448

// ---------------------------------------------------------------------------
// Device scratch (identical layout to passing rounds 2/8/9)
// ---------------------------------------------------------------------------
#define OFF_CA     ((size_t)0)
#define OFF_CL     ((size_t)16121856)
#define OFF_CE     ((size_t)21823488)
#define OFF_HBUF   ((size_t)24576000)
#define OFF_WAT    ((size_t)30474240)
#define OFF_WLT    ((size_t)33003520)
#define OFF_WET    ((size_t)33195520)
#define OFF_WIHT   ((size_t)33220096)
#define OFF_WHHT   ((size_t)33230336)
#define OFF_HWLPT  ((size_t)33295872)
#define OFF_HWLGT  ((size_t)33312256)
#define OFF_HWAPT  ((size_t)33328640)
#define OFF_HWAGT  ((size_t)33394176)
#define OFF_HWEPT  ((size_t)33459712)
#define OFF_HWEGT  ((size_t)33463808)
#define SCRATCH_TOTAL ((size_t)33467904)

__device__ __align__(16) float g_scratch[SCRATCH_TOTAL];

// ---------------------------------------------------------------------------
// Weight permute: (Cout, Cin, K) -> (Cout, K, Cin)
// ---------------------------------------------------------------------------
__global__ void permute_w_kernel(const float* __restrict__ src, size_t dstOff,
                                 int Cout, int Cin, int K)
{
    int idx = blockIdx.x * 256 + threadIdx.x;
    int tot = Cout * Cin * K;
    if (idx >= tot) return;
    float* dst = g_scratch + dstOff;
    int ci = idx % Cin;
    int r  = idx / Cin;
    int k  = r % K;
    int co = r / K;
    dst[idx] = src[(size_t)co * Cin * K + (size_t)ci * K + k];
}

// 2D transpose: src (R x C) -> dst (C x R)
__global__ void transpose2d_kernel(const float* __restrict__ src, size_t dstOff,
                                   int R, int C)
{
    int idx = blockIdx.x * 256 + threadIdx.x;
    int tot = R * C;
    if (idx >= tot) return;
    float* dst = g_scratch + dstOff;
    int r = idx % R;
    int c = idx / R;
    dst[idx] = src[(size_t)r * C + c];
}

// ---------------------------------------------------------------------------
// FP16 HMMA conv-as-GEMM, vectorized-fragment smem layout, double buffer,
// STS-first pipeline (STS of tile k+1 uses registers loaded a FULL iteration
// ago -> DRAM latency hidden), grid = (n-blocks, m-blocks) so the CTA pair
// sharing an A row is schedule-adjacent (second read hits L2).
// ---------------------------------------------------------------------------
__device__ __forceinline__ uint32_t f2h2(float lo, float hi) {
    __half2 h = __floats2half2_rn(lo, hi);
    return *(uint32_t*)&h;
}

__device__ __forceinline__ void mma_f16(float c[4], uint32_t a0, uint32_t a1,
                                        uint32_t a2, uint32_t a3,
                                        uint32_t b0, uint32_t b1) {
    asm volatile(
        "mma.sync.aligned.m16n8k16.row.col.f32.f16.f16.f32 "
        "{%0,%1,%2,%3}, {%4,%5,%6,%7}, {%8,%9}, {%0,%1,%2,%3};"
        : "+f"(c[0]), "+f"(c[1]), "+f"(c[2]), "+f"(c[3])
        : "r"(a0), "r"(a1), "r"(a2), "r"(a3), "r"(b0), "r"(b1));
}

#define TBM 128
#define TBN 128
#define TBK 16
#define ASTR 264

__global__ __launch_bounds__(256, 2)
void conv_gemm_f16_kernel(const float* __restrict__ X,
                          size_t wOff, size_t cOff,
                          int N, int KK,
                          int Wout, int rowStride, int btStride)
{
    __shared__ __align__(16) uint32_t As[2][4][ASTR];
    __shared__ __align__(16) uint32_t Bs[2][4][ASTR];

    const float* Wt   = g_scratch + wOff;
    float*       Cmat = g_scratch + cOff;

    const int tid  = threadIdx.x;
    const int bm   = blockIdx.y * TBM;     // m-blocks on Y (slow axis)
    const int bn   = blockIdx.x * TBN;     // n-blocks on X (fast axis)
    const int wid  = tid >> 5;
    const int lane = tid & 31;
    const int wm   = wid & 1;
    const int wn   = wid >> 1;
    const int g    = lane >> 2;
    const int c    = lane & 3;

    const int lr   = tid >> 2;
    const int lk   = (tid & 3) * 4;
    const int hb   = (tid & 3) >> 1;
    const int row0 = ((tid & 3) * 2) & 3;

    const float* aRow[2];
    const float* bRow[2];
    int cA[2], cB[2];
#pragma unroll
    for (int v = 0; v < 2; v++) {
        int mr = lr + v * 64;
        int m  = bm + mr;
        int bt = m / Wout;
        int t  = m - bt * Wout;
        aRow[v] = X + (size_t)bt * btStride + (size_t)t * rowStride;
        int q = mr >> 4, r = mr & 15;
        cA[v] = q * 32 + (r & 7) * 4 + hb * 2 + (r >> 3);
        cB[v] = mr * 2 + hb;
        bRow[v] = Wt + (size_t)(bn + mr) * KK;
    }

    float acc[4][4][4];
#pragma unroll
    for (int mi = 0; mi < 4; mi++)
#pragma unroll
        for (int ni = 0; ni < 4; ni++)
#pragma unroll
            for (int q = 0; q < 4; q++) acc[mi][ni][q] = 0.f;

    float4 ra[2], rb[2];
    const int ktiles = (KK + TBK - 1) / TBK;

    // ---- prologue: tile 0 -> stage 0; tile 1 -> registers
    {
        bool ok = (lk < KK);
#pragma unroll
        for (int v = 0; v < 2; v++) {
            ra[v] = ok ? *(const float4*)(aRow[v] + lk)
                       : make_float4(0.f, 0.f, 0.f, 0.f);
            rb[v] = ok ? *(const float4*)(bRow[v] + lk)
                       : make_float4(0.f, 0.f, 0.f, 0.f);
        }
#pragma unroll
        for (int v = 0; v < 2; v++) {
            As[0][row0    ][cA[v]] = f2h2(ra[v].x, ra[v].y);
            As[0][row0 + 1][cA[v]] = f2h2(ra[v].z, ra[v].w);
            Bs[0][row0    ][cB[v]] = f2h2(rb[v].x, rb[v].y);
            Bs[0][row0 + 1][cB[v]] = f2h2(rb[v].z, rb[v].w);
        }
        if (ktiles > 1) {
            int kg = TBK + lk;
            bool ok1 = (kg < KK);
#pragma unroll
            for (int v = 0; v < 2; v++) {
                ra[v] = ok1 ? *(const float4*)(aRow[v] + kg)
                            : make_float4(0.f, 0.f, 0.f, 0.f);
                rb[v] = ok1 ? *(const float4*)(bRow[v] + kg)
                            : make_float4(0.f, 0.f, 0.f, 0.f);
            }
        }
    }
    __syncthreads();

    for (int kt = 0; kt < ktiles; kt++) {
        // 1) STS tile kt+1 (registers loaded a full iteration ago -> no stall)
        if (kt + 1 < ktiles) {
            const int st = (kt + 1) & 1;
#pragma unroll
            for (int v = 0; v < 2; v++) {
                As[st][row0    ][cA[v]] = f2h2(ra[v].x, ra[v].y);
                As[st][row0 + 1][cA[v]] = f2h2(ra[v].z, ra[v].w);
                Bs[st][row0    ][cB[v]] = f2h2(rb[v].x, rb[v].y);
                Bs[st][row0 + 1][cB[v]] = f2h2(rb[v].z, rb[v].w);
            }
        }
        // 2) issue LDG for tile kt+2 (lands during compute kt + iter kt+1)
        if (kt + 2 < ktiles) {
            int kg = (kt + 2) * TBK + lk;
            bool ok = (kg < KK);
#pragma unroll
            for (int v = 0; v < 2; v++) {
                ra[v] = ok ? *(const float4*)(aRow[v] + kg)
                           : make_float4(0.f, 0.f, 0.f, 0.f);
                rb[v] = ok ? *(const float4*)(bRow[v] + kg)
                           : make_float4(0.f, 0.f, 0.f, 0.f);
            }
        }
        // 3) compute from stage kt&1
        {
            const int st = kt & 1;
            uint2 bfr[4];
#pragma unroll
            for (int ni = 0; ni < 4; ni++)
                bfr[ni] = *(const uint2*)&Bs[st][c][(wn * 32 + ni * 8 + g) * 2];
#pragma unroll
            for (int mi = 0; mi < 4; mi++) {
                uint4 av = *(const uint4*)&As[st][c][(wm * 4 + mi) * 32 + g * 4];
#pragma unroll
                for (int ni = 0; ni < 4; ni++)
                    mma_f16(acc[mi][ni], av.x, av.y, av.z, av.w,
                            bfr[ni].x, bfr[ni].y);
            }
        }
        // 4) barrier (publishes STS kt+1, retires reads of stage kt&1)
        if (kt + 1 < ktiles) __syncthreads();
    }

    // epilogue
#pragma unroll
    for (int mi = 0; mi < 4; mi++) {
#pragma unroll
        for (int ni = 0; ni < 4; ni++) {
            int row = bm + wm * 64 + mi * 16 + g;
            int col = bn + wn * 32 + ni * 8 + c * 2;
            *(float2*)(Cmat + (size_t)row * N + col) =
                make_float2(acc[mi][ni][0], acc[mi][ni][1]);
            *(float2*)(Cmat + (size_t)(row + 8) * N + col) =
                make_float2(acc[mi][ni][2], acc[mi][ni][3]);
        }
    }
}

// ---------------------------------------------------------------------------
// FP32 conv-as-GEMM (small Emotient GEMM)   [verbatim]
// ---------------------------------------------------------------------------
template<int BM, int BN, int BK, int TM, int TN>
__global__ __launch_bounds__(256)
void conv_gemm_kernel(size_t xOff, size_t wOff, size_t cOff,
                      int M, int N, int KK,
                      int Wout, int rowStride, int btStride)
{
    static_assert((BM / TM) * (BN / TN) == 256, "256 threads");
    constexpr int A_VECS = BM * BK / (256 * 4);
    constexpr int B_VECS = BN * BK / (256 * 4);

    const float* X    = g_scratch + xOff;
    const float* Wt   = g_scratch + wOff;
    float*       Cmat = g_scratch + cOff;

    __shared__ __align__(16) float As[BK][BM + 4];
    __shared__ __align__(16) float Bs[BK][BN + 4];

    const int tid = threadIdx.x;
    const int bm  = blockIdx.x * BM;
    const int bn  = blockIdx.y * BN;
    const int lr = tid >> 2;
    const int lk = (tid & 3) * 4;

    const float* aRow[A_VECS];
#pragma unroll
    for (int v = 0; v < A_VECS; v++) {
        int m  = bm + lr + v * 64;
        int bt = m / Wout;
        int t  = m - bt * Wout;
        aRow[v] = X + (size_t)bt * btStride + (size_t)t * rowStride;
    }
    const float* bRow[B_VECS];
#pragma unroll
    for (int v = 0; v < B_VECS; v++) {
        int n = bn + lr + v * 64;
        bRow[v] = Wt + (size_t)n * KK;
    }

    float acc[TM][TN];
#pragma unroll
    for (int i = 0; i < TM; i++)
#pragma unroll
        for (int j = 0; j < TN; j++) acc[i][j] = 0.f;

    const int ty = tid / (BN / TN);
    const int tx = tid % (BN / TN);

    for (int k0 = 0; k0 < KK; k0 += BK) {
        int kg = k0 + lk;
        bool ok = (kg < KK);
#pragma unroll
        for (int v = 0; v < A_VECS; v++) {
            float4 a = ok ? *(const float4*)(aRow[v] + kg)
                          : make_float4(0.f, 0.f, 0.f, 0.f);
            int mr = lr + v * 64;
            As[lk + 0][mr] = a.x; As[lk + 1][mr] = a.y;
            As[lk + 2][mr] = a.z; As[lk + 3][mr] = a.w;
        }
#pragma unroll
        for (int v = 0; v < B_VECS; v++) {
            float4 b = ok ? *(const float4*)(bRow[v] + kg)
                          : make_float4(0.f, 0.f, 0.f, 0.f);
            int nr = lr + v * 64;
            Bs[lk + 0][nr] = b.x; Bs[lk + 1][nr] = b.y;
            Bs[lk + 2][nr] = b.z; Bs[lk + 3][nr] = b.w;
        }
        __syncthreads();

#pragma unroll
        for (int kk = 0; kk < BK; kk++) {
            float a[TM], b[TN];
#pragma unroll
            for (int i = 0; i < TM; i += 4) {
                float4 v = *(const float4*)&As[kk][ty * TM + i];
                a[i] = v.x; a[i + 1] = v.y; a[i + 2] = v.z; a[i + 3] = v.w;
            }
#pragma unroll
            for (int j = 0; j < TN; j += 4) {
                float4 v = *(const float4*)&Bs[kk][tx * TN + j];
                b[j] = v.x; b[j + 1] = v.y; b[j + 2] = v.z; b[j + 3] = v.w;
            }
#pragma unroll
            for (int i = 0; i < TM; i++)
#pragma unroll
                for (int j = 0; j < TN; j++)
                    acc[i][j] = fmaf(a[i], b[j], acc[i][j]);
        }
        __syncthreads();
    }

#pragma unroll
    for (int i = 0; i < TM; i++) {
        size_t m = (size_t)bm + ty * TM + i;
        float* cp = Cmat + m * (size_t)N + bn + tx * TN;
#pragma unroll
        for (int j = 0; j < TN; j += 4) {
            float4 v = make_float4(acc[i][j], acc[i][j + 1],
                                   acc[i][j + 2], acc[i][j + 3]);
            *(float4*)(cp + j) = v;
        }
    }
}

// ---------------------------------------------------------------------------
// Masked LSTM: 8 sequences per block, 512 threads (one gate-row each)
// ---------------------------------------------------------------------------
#define SEQS 8
__device__ __forceinline__ float sigf(float x) { return 1.f / (1.f + expf(-x)); }

__global__ __launch_bounds__(512)
void lstm_kernel(const float* __restrict__ xe,
                 const int*   __restrict__ wlen,
                 const float* __restrict__ bih,
                 const float* __restrict__ bhh)
{
    const float* WihT = g_scratch + OFF_WIHT;
    const float* WhhT = g_scratch + OFF_WHHT;
    float*       hbuf = g_scratch + OFF_HBUF;

    __shared__ float sh[SEQS][HH_];
    __shared__ float sc[SEQS][HH_];
    __shared__ float sx[SEQS][EE_];
    __shared__ float sz[4 * HH_][SEQS + 1];
    __shared__ int   slen[SEQS];

    const int tid = threadIdx.x;
    const int bt0 = blockIdx.x * SEQS;

    for (int i = tid; i < SEQS * HH_; i += 512) {
        (&sh[0][0])[i] = 0.f;
        (&sc[0][0])[i] = 0.f;
    }
    if (tid < SEQS) slen[tid] = wlen[bt0 + tid];
    __syncthreads();

    const int r = tid;
    const float bias = bih[r] + bhh[r];

    for (int t = 0; t < WE_; t++) {
        for (int i = tid; i < SEQS * EE_; i += 512) {
            int s = i / EE_, e = i - s * EE_;
            sx[s][e] = xe[(size_t)(bt0 + s) * (WE_ * EE_) + t * EE_ + e];
        }
        __syncthreads();

        float acc[SEQS];
#pragma unroll
        for (int s = 0; s < SEQS; s++) acc[s] = bias;
#pragma unroll
        for (int e = 0; e < EE_; e++) {
            float w = WihT[e * 512 + r];
#pragma unroll
            for (int s = 0; s < SEQS; s++) acc[s] = fmaf(w, sx[s][e], acc[s]);
        }
#pragma unroll 4
        for (int j = 0; j < HH_; j++) {
            float w = WhhT[j * 512 + r];
#pragma unroll
            for (int s = 0; s < SEQS; s++) acc[s] = fmaf(w, sh[s][j], acc[s]);
        }
#pragma unroll
        for (int s = 0; s < SEQS; s++) sz[r][s] = acc[s];
        __syncthreads();

#pragma unroll
        for (int p = tid; p < SEQS * HH_; p += 512) {
            int s = p & (SEQS - 1);
            int j = p >> 3;
            float zi = sz[j][s];
            float zf = sz[HH_ + j][s];
            float zg = sz[2 * HH_ + j][s];
            float zo = sz[3 * HH_ + j][s];
            float cc = sc[s][j];
            float cn = sigf(zf) * cc + sigf(zi) * tanhf(zg);
            float hn = sigf(zo) * tanhf(cn);
            bool valid = (t < slen[s]);
            sc[s][j] = valid ? cn : cc;
            sh[s][j] = valid ? hn : sh[s][j];
            hbuf[(size_t)(bt0 + s) * (WE_ * HH_) + t * HH_ + j] = valid ? hn : 0.f;
        }
        __syncthreads();
    }
}

// ---------------------------------------------------------------------------
// Fused maxpool(+conv bias) + highway, writes final output slice
// ---------------------------------------------------------------------------
__global__ void pool_highway_kernel(size_t cOff, int N, int Wout,
                                    const float* __restrict__ convB,
                                    size_t wpOff, const float* __restrict__ bp,
                                    size_t wgOff, const float* __restrict__ bg,
                                    float* __restrict__ out, int outOff)
{
    extern __shared__ float sy[];
    const float* Cmat = g_scratch + cOff;
    const float* WpT  = g_scratch + wpOff;
    const float* WgT  = g_scratch + wgOff;

    int bt = blockIdx.x;
    int co = threadIdx.x;

    const float* cp = Cmat + (size_t)bt * Wout * N + co;
    float y = cp[0];
    for (int t = 1; t < Wout; t++) y = fmaxf(y, cp[(size_t)t * N]);
    y += convB[co];
    sy[co] = y;
    __syncthreads();

    float ap = bp[co], ag = bg[co];
    for (int j = 0; j < N; j++) {
        float yj = sy[j];
        ap = fmaf(WpT[j * N + co], yj, ap);
        ag = fmaf(WgT[j * N + co], yj, ag);
    }
    float p = fmaxf(ap, 0.f);
    float gg = 1.f / (1.f + expf(-ag));
    out[(size_t)bt * OUTW_ + outOff + co] = gg * p + (1.f - gg) * y;
}

// ---------------------------------------------------------------------------
// Launch
// ---------------------------------------------------------------------------
extern "C" void kernel_launch(void* const* d_in, const int* in_sizes, int n_in,
                              void* d_out, int out_size)
{
    (void)in_sizes; (void)n_in; (void)out_size;
    const float* x_lin   = (const float*)d_in[0];
    const float* x_aco   = (const float*)d_in[1];
    const float* x_emo   = (const float*)d_in[2];
    const int*   wlen    = (const int*)  d_in[3];
    const float* convL_w = (const float*)d_in[5];
    const float* convL_b = (const float*)d_in[6];
    const float* convA_w = (const float*)d_in[7];
    const float* convA_b = (const float*)d_in[8];
    const float* convE_w = (const float*)d_in[9];
    const float* convE_b = (const float*)d_in[10];
    const float* hwL_Wp  = (const float*)d_in[11];
    const float* hwL_bp  = (const float*)d_in[12];
    const float* hwL_Wg  = (const float*)d_in[13];
    const float* hwL_bg  = (const float*)d_in[14];
    const float* hwA_Wp  = (const float*)d_in[15];
    const float* hwA_bp  = (const float*)d_in[16];
    const float* hwA_Wg  = (const float*)d_in[17];
    const float* hwA_bg  = (const float*)d_in[18];
    const float* hwE_Wp  = (const float*)d_in[19];
    const float* hwE_bp  = (const float*)d_in[20];
    const float* hwE_Wg  = (const float*)d_in[21];
    const float* hwE_bg  = (const float*)d_in[22];
    const float* Wih     = (const float*)d_in[23];
    const float* Whh     = (const float*)d_in[24];
    const float* bih     = (const float*)d_in[25];
    const float* bhh     = (const float*)d_in[26];
    float* out = (float*)d_out;

    // 1-3: conv weight permutes
    permute_w_kernel<<<(CA_ * EA_ * KA_ + 255) / 256, 256>>>(convA_w, OFF_WAT, CA_, EA_, KA_);
    permute_w_kernel<<<(CL_ * EL_ * KL_ + 255) / 256, 256>>>(convL_w, OFF_WLT, CL_, EL_, KL_);
    permute_w_kernel<<<(CE_ * HH_ * KE_ + 255) / 256, 256>>>(convE_w, OFF_WET, CE_, HH_, KE_);

    // 4: acoustic GEMM (fp16 HMMA) — grid (n, m) so A-sharing CTAs are adjacent
    conv_gemm_f16_kernel<<<dim3(CA_ / TBN, MA_ / TBM), 256>>>(
        x_aco, OFF_WAT, OFF_CA, CA_, KKA_, WOA_, EA_, WA_ * EA_);

    // 5: linguistic GEMM (fp16 HMMA)
    conv_gemm_f16_kernel<<<dim3(CL_ / TBN, ML_ / TBM), 256>>>(
        x_lin, OFF_WLT, OFF_CL, CL_, KKL_, WOL_, EL_, WL_ * EL_);

    // 6-7: LSTM weight transposes
    transpose2d_kernel<<<(512 * EE_ + 255) / 256, 256>>>(Wih, OFF_WIHT, 512, EE_);
    transpose2d_kernel<<<(512 * HH_ + 255) / 256, 256>>>(Whh, OFF_WHHT, 512, HH_);

    // 8: LSTM (-> hbuf)
    lstm_kernel<<<BT_ / SEQS, 512>>>(x_emo, wlen, bih, bhh);

    // 9: emotient GEMM (fp32, input = hbuf)
    conv_gemm_kernel<128, 64, 16, 8, 4><<<dim3(ME_ / 128, CE_ / 64), 256>>>(
        OFF_HBUF, OFF_WET, OFF_CE, ME_, CE_, KKE_, WOE_, HH_, WE_ * HH_);

    // 10-15: highway weight transposes
    transpose2d_kernel<<<(CL_ * CL_ + 255) / 256, 256>>>(hwL_Wp, OFF_HWLPT, CL_, CL_);
    transpose2d_kernel<<<(CL_ * CL_ + 255) / 256, 256>>>(hwL_Wg, OFF_HWLGT, CL_, CL_);
    transpose2d_kernel<<<(CA_ * CA_ + 255) / 256, 256>>>(hwA_Wp, OFF_HWAPT, CA_, CA_);
    transpose2d_kernel<<<(CA_ * CA_ + 255) / 256, 256>>>(hwA_Wg, OFF_HWAGT, CA_, CA_);
    transpose2d_kernel<<<(CE_ * CE_ + 255) / 256, 256>>>(hwE_Wp, OFF_HWEPT, CE_, CE_);
    transpose2d_kernel<<<(CE_ * CE_ + 255) / 256, 256>>>(hwE_Wg, OFF_HWEGT, CE_, CE_);

    // 16-18: fused maxpool + highway -> output
    pool_highway_kernel<<<BT_, CL_, CL_ * sizeof(float)>>>(
        OFF_CL, CL_, WOL_, convL_b, OFF_HWLPT, hwL_bp, OFF_HWLGT, hwL_bg, out, 0);
    pool_highway_kernel<<<BT_, CA_, CA_ * sizeof(float)>>>(
        OFF_CA, CA_, WOA_, convA_b, OFF_HWAPT, hwA_bp, OFF_HWAGT, hwA_bg, out, CL_);
    pool_highway_kernel<<<BT_, CE_, CE_ * sizeof(float)>>>(
        OFF_CE, CE_, WOE_, convE_b, OFF_HWEPT, hwE_bp, OFF_HWEGT, hwE_bg, out, CL_ + CA_);
}

// round 14
// speedup vs baseline: 3.4438x; 1.0099x over previous
#include <cuda_runtime.h>
#include <cuda_fp16.h>
#include <math.h>
#include <stdint.h>

// ---------------------------------------------------------------------------
// Problem dimensions
// ---------------------------------------------------------------------------
#define BT_   1536
#define WL_   33
#define WA_   50
#define WE_   30
#define EL_   300
#define EA_   988
#define EE_   20
#define HH_   128
#define CL_   128
#define CA_   256
#define CE_   64
#define KL_   5
#define KA_   10
#define KE_   3
#define WOL_  (WL_ - KL_ + 1)      // 29
#define WOA_  (WA_ - KA_ + 1)      // 41
#define WOE_  (WE_ - KE_ + 1)      // 28
#define ML_   (BT_ * WOL_)         // 44544
#define MA_   (BT_ * WOA_)         // 62976
#define ME_   (BT_ * WOE_)         // 43008
#define KKL_  (KL_ * EL_)          // 1500
#define KKA_  (KA_ * EA_)          // 9880
#define KKE_  (KE_ * HH_)          // 384
#define OUTW_ 448

// ---------------------------------------------------------------------------
// Device scratch — EXACT proven 134 MB layout (delta=0 rounds 2/8/9/10)
// ---------------------------------------------------------------------------
#define OFF_CA     ((size_t)0)
#define OFF_CL     ((size_t)16121856)
#define OFF_CE     ((size_t)21823488)
#define OFF_HBUF   ((size_t)24576000)
#define OFF_WAT    ((size_t)30474240)
#define OFF_WLT    ((size_t)33003520)
#define OFF_WET    ((size_t)33195520)
#define OFF_WIHT   ((size_t)33220096)
#define OFF_WHHT   ((size_t)33230336)
#define OFF_HWLPT  ((size_t)33295872)
#define OFF_HWLGT  ((size_t)33312256)
#define OFF_HWAPT  ((size_t)33328640)
#define OFF_HWAGT  ((size_t)33394176)
#define OFF_HWEPT  ((size_t)33459712)
#define OFF_HWEGT  ((size_t)33463808)
#define SCRATCH_TOTAL ((size_t)33467904)

__device__ __align__(16) float g_scratch[SCRATCH_TOTAL];

// ---------------------------------------------------------------------------
// Weight permute: (Cout, Cin, K) -> (Cout, K, Cin)     [verbatim round 10]
// ---------------------------------------------------------------------------
__global__ void permute_w_kernel(const float* __restrict__ src, size_t dstOff,
                                 int Cout, int Cin, int K)
{
    int idx = blockIdx.x * 256 + threadIdx.x;
    int tot = Cout * Cin * K;
    if (idx >= tot) return;
    float* dst = g_scratch + dstOff;
    int ci = idx % Cin;
    int r  = idx / Cin;
    int k  = r % K;
    int co = r / K;
    dst[idx] = src[(size_t)co * Cin * K + (size_t)ci * K + k];
}

// 2D transpose: src (R x C) -> dst (C x R)             [verbatim round 10]
__global__ void transpose2d_kernel(const float* __restrict__ src, size_t dstOff,
                                   int R, int C)
{
    int idx = blockIdx.x * 256 + threadIdx.x;
    int tot = R * C;
    if (idx >= tot) return;
    float* dst = g_scratch + dstOff;
    int r = idx % R;
    int c = idx / R;
    dst[idx] = src[(size_t)r * C + c];
}

// ---------------------------------------------------------------------------
// FP16 HMMA conv-as-GEMM — BYTE-IDENTICAL to round 10 (2698us, delta=0)
// ---------------------------------------------------------------------------
__device__ __forceinline__ uint32_t f2h2(float lo, float hi) {
    __half2 h = __floats2half2_rn(lo, hi);
    return *(uint32_t*)&h;
}

__device__ __forceinline__ void mma_f16(float c[4], uint32_t a0, uint32_t a1,
                                        uint32_t a2, uint32_t a3,
                                        uint32_t b0, uint32_t b1) {
    asm volatile(
        "mma.sync.aligned.m16n8k16.row.col.f32.f16.f16.f32 "
        "{%0,%1,%2,%3}, {%4,%5,%6,%7}, {%8,%9}, {%0,%1,%2,%3};"
        : "+f"(c[0]), "+f"(c[1]), "+f"(c[2]), "+f"(c[3])
        : "r"(a0), "r"(a1), "r"(a2), "r"(a3), "r"(b0), "r"(b1));
}

#define TBM 128
#define TBN 128
#define TBK 16
#define ASTR 264

__global__ __launch_bounds__(256, 2)
void conv_gemm_f16_kernel(const float* __restrict__ X,
                          size_t wOff, size_t cOff,
                          int N, int KK,
                          int Wout, int rowStride, int btStride)
{
    __shared__ __align__(16) uint32_t As[2][4][ASTR];
    __shared__ __align__(16) uint32_t Bs[2][4][ASTR];

    const float* Wt   = g_scratch + wOff;
    float*       Cmat = g_scratch + cOff;

    const int tid  = threadIdx.x;
    const int bm   = blockIdx.y * TBM;
    const int bn   = blockIdx.x * TBN;
    const int wid  = tid >> 5;
    const int lane = tid & 31;
    const int wm   = wid & 1;
    const int wn   = wid >> 1;
    const int g    = lane >> 2;
    const int c    = lane & 3;

    const int lr   = tid >> 2;
    const int lk   = (tid & 3) * 4;
    const int hb   = (tid & 3) >> 1;
    const int row0 = ((tid & 3) * 2) & 3;

    const float* aRow[2];
    const float* bRow[2];
    int cA[2], cB[2];
#pragma unroll
    for (int v = 0; v < 2; v++) {
        int mr = lr + v * 64;
        int m  = bm + mr;
        int bt = m / Wout;
        int t  = m - bt * Wout;
        aRow[v] = X + (size_t)bt * btStride + (size_t)t * rowStride;
        int q = mr >> 4, r = mr & 15;
        cA[v] = q * 32 + (r & 7) * 4 + hb * 2 + (r >> 3);
        cB[v] = mr * 2 + hb;
        bRow[v] = Wt + (size_t)(bn + mr) * KK;
    }

    float acc[4][4][4];
#pragma unroll
    for (int mi = 0; mi < 4; mi++)
#pragma unroll
        for (int ni = 0; ni < 4; ni++)
#pragma unroll
            for (int q = 0; q < 4; q++) acc[mi][ni][q] = 0.f;

    float4 ra[2], rb[2];
    const int ktiles = (KK + TBK - 1) / TBK;

    // ---- prologue: tile 0 -> stage 0; tile 1 -> registers
    {
        bool ok = (lk < KK);
#pragma unroll
        for (int v = 0; v < 2; v++) {
            ra[v] = ok ? *(const float4*)(aRow[v] + lk)
                       : make_float4(0.f, 0.f, 0.f, 0.f);
            rb[v] = ok ? *(const float4*)(bRow[v] + lk)
                       : make_float4(0.f, 0.f, 0.f, 0.f);
        }
#pragma unroll
        for (int v = 0; v < 2; v++) {
            As[0][row0    ][cA[v]] = f2h2(ra[v].x, ra[v].y);
            As[0][row0 + 1][cA[v]] = f2h2(ra[v].z, ra[v].w);
            Bs[0][row0    ][cB[v]] = f2h2(rb[v].x, rb[v].y);
            Bs[0][row0 + 1][cB[v]] = f2h2(rb[v].z, rb[v].w);
        }
        if (ktiles > 1) {
            int kg = TBK + lk;
            bool ok1 = (kg < KK);
#pragma unroll
            for (int v = 0; v < 2; v++) {
                ra[v] = ok1 ? *(const float4*)(aRow[v] + kg)
                            : make_float4(0.f, 0.f, 0.f, 0.f);
                rb[v] = ok1 ? *(const float4*)(bRow[v] + kg)
                            : make_float4(0.f, 0.f, 0.f, 0.f);
            }
        }
    }
    __syncthreads();

    for (int kt = 0; kt < ktiles; kt++) {
        // 1) STS tile kt+1 (registers loaded a full iteration ago)
        if (kt + 1 < ktiles) {
            const int st = (kt + 1) & 1;
#pragma unroll
            for (int v = 0; v < 2; v++) {
                As[st][row0    ][cA[v]] = f2h2(ra[v].x, ra[v].y);
                As[st][row0 + 1][cA[v]] = f2h2(ra[v].z, ra[v].w);
                Bs[st][row0    ][cB[v]] = f2h2(rb[v].x, rb[v].y);
                Bs[st][row0 + 1][cB[v]] = f2h2(rb[v].z, rb[v].w);
            }
        }
        // 2) LDG tile kt+2
        if (kt + 2 < ktiles) {
            int kg = (kt + 2) * TBK + lk;
            bool ok = (kg < KK);
#pragma unroll
            for (int v = 0; v < 2; v++) {
                ra[v] = ok ? *(const float4*)(aRow[v] + kg)
                           : make_float4(0.f, 0.f, 0.f, 0.f);
                rb[v] = ok ? *(const float4*)(bRow[v] + kg)
                           : make_float4(0.f, 0.f, 0.f, 0.f);
            }
        }
        // 3) compute from stage kt&1
        {
            const int st = kt & 1;
            uint2 bfr[4];
#pragma unroll
            for (int ni = 0; ni < 4; ni++)
                bfr[ni] = *(const uint2*)&Bs[st][c][(wn * 32 + ni * 8 + g) * 2];
#pragma unroll
            for (int mi = 0; mi < 4; mi++) {
                uint4 av = *(const uint4*)&As[st][c][(wm * 4 + mi) * 32 + g * 4];
#pragma unroll
                for (int ni = 0; ni < 4; ni++)
                    mma_f16(acc[mi][ni], av.x, av.y, av.z, av.w,
                            bfr[ni].x, bfr[ni].y);
            }
        }
        // 4) barrier
        if (kt + 1 < ktiles) __syncthreads();
    }

    // epilogue
#pragma unroll
    for (int mi = 0; mi < 4; mi++) {
#pragma unroll
        for (int ni = 0; ni < 4; ni++) {
            int row = bm + wm * 64 + mi * 16 + g;
            int col = bn + wn * 32 + ni * 8 + c * 2;
            *(float2*)(Cmat + (size_t)row * N + col) =
                make_float2(acc[mi][ni][0], acc[mi][ni][1]);
            *(float2*)(Cmat + (size_t)(row + 8) * N + col) =
                make_float2(acc[mi][ni][2], acc[mi][ni][3]);
        }
    }
}

// ---------------------------------------------------------------------------
// FP32 conv-as-GEMM (small Emotient GEMM)              [verbatim round 10]
// ---------------------------------------------------------------------------
template<int BM, int BN, int BK, int TM, int TN>
__global__ __launch_bounds__(256)
void conv_gemm_kernel(size_t xOff, size_t wOff, size_t cOff,
                      int M, int N, int KK,
                      int Wout, int rowStride, int btStride)
{
    static_assert((BM / TM) * (BN / TN) == 256, "256 threads");
    constexpr int A_VECS = BM * BK / (256 * 4);
    constexpr int B_VECS = BN * BK / (256 * 4);

    const float* X    = g_scratch + xOff;
    const float* Wt   = g_scratch + wOff;
    float*       Cmat = g_scratch + cOff;

    __shared__ __align__(16) float As[BK][BM + 4];
    __shared__ __align__(16) float Bs[BK][BN + 4];

    const int tid = threadIdx.x;
    const int bm  = blockIdx.x * BM;
    const int bn  = blockIdx.y * BN;
    const int lr = tid >> 2;
    const int lk = (tid & 3) * 4;

    const float* aRow[A_VECS];
#pragma unroll
    for (int v = 0; v < A_VECS; v++) {
        int m  = bm + lr + v * 64;
        int bt = m / Wout;
        int t  = m - bt * Wout;
        aRow[v] = X + (size_t)bt * btStride + (size_t)t * rowStride;
    }
    const float* bRow[B_VECS];
#pragma unroll
    for (int v = 0; v < B_VECS; v++) {
        int n = bn + lr + v * 64;
        bRow[v] = Wt + (size_t)n * KK;
    }

    float acc[TM][TN];
#pragma unroll
    for (int i = 0; i < TM; i++)
#pragma unroll
        for (int j = 0; j < TN; j++) acc[i][j] = 0.f;

    const int ty = tid / (BN / TN);
    const int tx = tid % (BN / TN);

    for (int k0 = 0; k0 < KK; k0 += BK) {
        int kg = k0 + lk;
        bool ok = (kg < KK);
#pragma unroll
        for (int v = 0; v < A_VECS; v++) {
            float4 a = ok ? *(const float4*)(aRow[v] + kg)
                          : make_float4(0.f, 0.f, 0.f, 0.f);
            int mr = lr + v * 64;
            As[lk + 0][mr] = a.x; As[lk + 1][mr] = a.y;
            As[lk + 2][mr] = a.z; As[lk + 3][mr] = a.w;
        }
#pragma unroll
        for (int v = 0; v < B_VECS; v++) {
            float4 b = ok ? *(const float4*)(bRow[v] + kg)
                          : make_float4(0.f, 0.f, 0.f, 0.f);
            int nr = lr + v * 64;
            Bs[lk + 0][nr] = b.x; Bs[lk + 1][nr] = b.y;
            Bs[lk + 2][nr] = b.z; Bs[lk + 3][nr] = b.w;
        }
        __syncthreads();

#pragma unroll
        for (int kk = 0; kk < BK; kk++) {
            float a[TM], b[TN];
#pragma unroll
            for (int i = 0; i < TM; i += 4) {
                float4 v = *(const float4*)&As[kk][ty * TM + i];
                a[i] = v.x; a[i + 1] = v.y; a[i + 2] = v.z; a[i + 3] = v.w;
            }
#pragma unroll
            for (int j = 0; j < TN; j += 4) {
                float4 v = *(const float4*)&Bs[kk][tx * TN + j];
                b[j] = v.x; b[j + 1] = v.y; b[j + 2] = v.z; b[j + 3] = v.w;
            }
#pragma unroll
            for (int i = 0; i < TM; i++)
#pragma unroll
                for (int j = 0; j < TN; j++)
                    acc[i][j] = fmaf(a[i], b[j], acc[i][j]);
        }
        __syncthreads();
    }

#pragma unroll
    for (int i = 0; i < TM; i++) {
        size_t m = (size_t)bm + ty * TM + i;
        float* cp = Cmat + m * (size_t)N + bn + tx * TN;
#pragma unroll
        for (int j = 0; j < TN; j += 4) {
            float4 v = make_float4(acc[i][j], acc[i][j + 1],
                                   acc[i][j + 2], acc[i][j + 3]);
            *(float4*)(cp + j) = v;
        }
    }
}

// ---------------------------------------------------------------------------
// Masked LSTM: 16 sequences per block (halved L2 weight traffic), 512 threads
// Dynamic smem: sh[16][128] sc[16][128] sx[16][20] sz[512][17] slen[16]
// ---------------------------------------------------------------------------
#define SEQS 16
__device__ __forceinline__ float sigf(float x) { return 1.f / (1.f + expf(-x)); }

#define LSTM_SMEM_FLOATS (SEQS*HH_ + SEQS*HH_ + SEQS*EE_ + 512*(SEQS+1) + SEQS)
#define LSTM_SMEM_BYTES  (LSTM_SMEM_FLOATS * 4)

__global__ __launch_bounds__(512)
void lstm_kernel(const float* __restrict__ xe,
                 const int*   __restrict__ wlen,
                 const float* __restrict__ bih,
                 const float* __restrict__ bhh)
{
    const float* WihT = g_scratch + OFF_WIHT;
    const float* WhhT = g_scratch + OFF_WHHT;
    float*       hbuf = g_scratch + OFF_HBUF;

    extern __shared__ float sm[];
    float* sh   = sm;                              // [SEQS][HH_]
    float* sc   = sh + SEQS * HH_;                 // [SEQS][HH_]
    float* sx   = sc + SEQS * HH_;                 // [SEQS][EE_]
    float* sz   = sx + SEQS * EE_;                 // [512][SEQS+1]
    int*   slen = (int*)(sz + 512 * (SEQS + 1));   // [SEQS]

    const int tid = threadIdx.x;
    const int bt0 = blockIdx.x * SEQS;

    for (int i = tid; i < SEQS * HH_; i += 512) {
        sh[i] = 0.f;
        sc[i] = 0.f;
    }
    if (tid < SEQS) slen[tid] = wlen[bt0 + tid];
    __syncthreads();

    const int r = tid;
    const float bias = bih[r] + bhh[r];

    for (int t = 0; t < WE_; t++) {
        for (int i = tid; i < SEQS * EE_; i += 512) {
            int s = i / EE_, e = i - s * EE_;
            sx[s * EE_ + e] = xe[(size_t)(bt0 + s) * (WE_ * EE_) + t * EE_ + e];
        }
        __syncthreads();

        float acc[SEQS];
#pragma unroll
        for (int s = 0; s < SEQS; s++) acc[s] = bias;
#pragma unroll
        for (int e = 0; e < EE_; e++) {
            float w = WihT[e * 512 + r];
#pragma unroll
            for (int s = 0; s < SEQS; s++) acc[s] = fmaf(w, sx[s * EE_ + e], acc[s]);
        }
#pragma unroll 4
        for (int j = 0; j < HH_; j++) {
            float w = WhhT[j * 512 + r];
#pragma unroll
            for (int s = 0; s < SEQS; s++) acc[s] = fmaf(w, sh[s * HH_ + j], acc[s]);
        }
#pragma unroll
        for (int s = 0; s < SEQS; s++) sz[r * (SEQS + 1) + s] = acc[s];
        __syncthreads();

        // gate combine: 16*128 = 2048 (s,j) pairs / 512 threads
#pragma unroll
        for (int p = tid; p < SEQS * HH_; p += 512) {
            int s = p & (SEQS - 1);
            int j = p >> 4;
            float zi = sz[j * (SEQS + 1) + s];
            float zf = sz[(HH_ + j) * (SEQS + 1) + s];
            float zg = sz[(2 * HH_ + j) * (SEQS + 1) + s];
            float zo = sz[(3 * HH_ + j) * (SEQS + 1) + s];
            float cc = sc[s * HH_ + j];
            float cn = sigf(zf) * cc + sigf(zi) * tanhf(zg);
            float hn = sigf(zo) * tanhf(cn);
            bool valid = (t < slen[s]);
            sc[s * HH_ + j] = valid ? cn : cc;
            sh[s * HH_ + j] = valid ? hn : sh[s * HH_ + j];
            hbuf[(size_t)(bt0 + s) * (WE_ * HH_) + t * HH_ + j] = valid ? hn : 0.f;
        }
        __syncthreads();
    }
}

// ---------------------------------------------------------------------------
// Fused maxpool(+conv bias) + highway, 8 bt-rows per block (weights reused)
// dynamic smem: sy[8][N]
// ---------------------------------------------------------------------------
#define BTB 8
__global__ void pool_highway_kernel(size_t cOff, int N, int Wout,
                                    const float* __restrict__ convB,
                                    size_t wpOff, const float* __restrict__ bp,
                                    size_t wgOff, const float* __restrict__ bg,
                                    float* __restrict__ out, int outOff)
{
    extern __shared__ float sy[];                  // [BTB][N]
    const float* Cmat = g_scratch + cOff;
    const float* WpT  = g_scratch + wpOff;
    const float* WgT  = g_scratch + wgOff;

    const int bt0 = blockIdx.x * BTB;
    const int co  = threadIdx.x;
    const float cb = convB[co];

#pragma unroll
    for (int b = 0; b < BTB; b++) {
        const float* cp = Cmat + (size_t)(bt0 + b) * Wout * N + co;
        float y = cp[0];
        for (int t = 1; t < Wout; t++) y = fmaxf(y, cp[(size_t)t * N]);
        sy[b * N + co] = y + cb;
    }
    __syncthreads();

    float ap[BTB], ag[BTB];
    const float bpc = bp[co], bgc = bg[co];
#pragma unroll
    for (int b = 0; b < BTB; b++) { ap[b] = bpc; ag[b] = bgc; }

    for (int j = 0; j < N; j++) {
        float wp = WpT[j * N + co];
        float wg = WgT[j * N + co];
#pragma unroll
        for (int b = 0; b < BTB; b++) {
            float yj = sy[b * N + j];
            ap[b] = fmaf(wp, yj, ap[b]);
            ag[b] = fmaf(wg, yj, ag[b]);
        }
    }
#pragma unroll
    for (int b = 0; b < BTB; b++) {
        float p  = fmaxf(ap[b], 0.f);
        float gg = 1.f / (1.f + expf(-ag[b]));
        float y  = sy[b * N + co];
        out[(size_t)(bt0 + b) * OUTW_ + outOff + co] = gg * p + (1.f - gg) * y;
    }
}

// ---------------------------------------------------------------------------
// Launch
// ---------------------------------------------------------------------------
extern "C" void kernel_launch(void* const* d_in, const int* in_sizes, int n_in,
                              void* d_out, int out_size)
{
    (void)in_sizes; (void)n_in; (void)out_size;
    const float* x_lin   = (const float*)d_in[0];
    const float* x_aco   = (const float*)d_in[1];
    const float* x_emo   = (const float*)d_in[2];
    const int*   wlen    = (const int*)  d_in[3];
    const float* convL_w = (const float*)d_in[5];
    const float* convL_b = (const float*)d_in[6];
    const float* convA_w = (const float*)d_in[7];
    const float* convA_b = (const float*)d_in[8];
    const float* convE_w = (const float*)d_in[9];
    const float* convE_b = (const float*)d_in[10];
    const float* hwL_Wp  = (const float*)d_in[11];
    const float* hwL_bp  = (const float*)d_in[12];
    const float* hwL_Wg  = (const float*)d_in[13];
    const float* hwL_bg  = (const float*)d_in[14];
    const float* hwA_Wp  = (const float*)d_in[15];
    const float* hwA_bp  = (const float*)d_in[16];
    const float* hwA_Wg  = (const float*)d_in[17];
    const float* hwA_bg  = (const float*)d_in[18];
    const float* hwE_Wp  = (const float*)d_in[19];
    const float* hwE_bp  = (const float*)d_in[20];
    const float* hwE_Wg  = (const float*)d_in[21];
    const float* hwE_bg  = (const float*)d_in[22];
    const float* Wih     = (const float*)d_in[23];
    const float* Whh     = (const float*)d_in[24];
    const float* bih     = (const float*)d_in[25];
    const float* bhh     = (const float*)d_in[26];
    float* out = (float*)d_out;

    cudaFuncSetAttribute(lstm_kernel,
                         cudaFuncAttributeMaxDynamicSharedMemorySize,
                         LSTM_SMEM_BYTES);

    // 1-3: conv weight permutes
    permute_w_kernel<<<(CA_ * EA_ * KA_ + 255) / 256, 256>>>(convA_w, OFF_WAT, CA_, EA_, KA_);
    permute_w_kernel<<<(CL_ * EL_ * KL_ + 255) / 256, 256>>>(convL_w, OFF_WLT, CL_, EL_, KL_);
    permute_w_kernel<<<(CE_ * HH_ * KE_ + 255) / 256, 256>>>(convE_w, OFF_WET, CE_, HH_, KE_);

    // 4: acoustic GEMM (fp16 HMMA) — the ncu-profiled launch
    conv_gemm_f16_kernel<<<dim3(CA_ / TBN, MA_ / TBM), 256>>>(
        x_aco, OFF_WAT, OFF_CA, CA_, KKA_, WOA_, EA_, WA_ * EA_);

    // 5: linguistic GEMM (fp16 HMMA)
    conv_gemm_f16_kernel<<<dim3(CL_ / TBN, ML_ / TBM), 256>>>(
        x_lin, OFF_WLT, OFF_CL, CL_, KKL_, WOL_, EL_, WL_ * EL_);

    // 6-7: LSTM weight transposes
    transpose2d_kernel<<<(512 * EE_ + 255) / 256, 256>>>(Wih, OFF_WIHT, 512, EE_);
    transpose2d_kernel<<<(512 * HH_ + 255) / 256, 256>>>(Whh, OFF_WHHT, 512, HH_);

    // 8: LSTM (-> hbuf), 16 seqs/block
    lstm_kernel<<<BT_ / SEQS, 512, LSTM_SMEM_BYTES>>>(x_emo, wlen, bih, bhh);

    // 9: emotient GEMM (fp32, input = hbuf)
    conv_gemm_kernel<128, 64, 16, 8, 4><<<dim3(ME_ / 128, CE_ / 64), 256>>>(
        OFF_HBUF, OFF_WET, OFF_CE, ME_, CE_, KKE_, WOE_, HH_, WE_ * HH_);

    // 10-15: highway weight transposes
    transpose2d_kernel<<<(CL_ * CL_ + 255) / 256, 256>>>(hwL_Wp, OFF_HWLPT, CL_, CL_);
    transpose2d_kernel<<<(CL_ * CL_ + 255) / 256, 256>>>(hwL_Wg, OFF_HWLGT, CL_, CL_);
    transpose2d_kernel<<<(CA_ * CA_ + 255) / 256, 256>>>(hwA_Wp, OFF_HWAPT, CA_, CA_);
    transpose2d_kernel<<<(CA_ * CA_ + 255) / 256, 256>>>(hwA_Wg, OFF_HWAGT, CA_, CA_);
    transpose2d_kernel<<<(CE_ * CE_ + 255) / 256, 256>>>(hwE_Wp, OFF_HWEPT, CE_, CE_);
    transpose2d_kernel<<<(CE_ * CE_ + 255) / 256, 256>>>(hwE_Wg, OFF_HWEGT, CE_, CE_);

    // 16-18: fused maxpool + highway -> output (8 bt per block)
    pool_highway_kernel<<<BT_ / BTB, CL_, BTB * CL_ * sizeof(float)>>>(
        OFF_CL, CL_, WOL_, convL_b, OFF_HWLPT, hwL_bp, OFF_HWLGT, hwL_bg, out, 0);
    pool_highway_kernel<<<BT_ / BTB, CA_, BTB * CA_ * sizeof(float)>>>(
        OFF_CA, CA_, WOA_, convA_b, OFF_HWAPT, hwA_bp, OFF_HWAGT, hwA_bg, out, CL_);
    pool_highway_kernel<<<BT_ / BTB, CE_, BTB * CE_ * sizeof(float)>>>(
        OFF_CE, CE_, WOE_, convE_b, OFF_HWEPT, hwE_bp, OFF_HWEGT, hwE_bg, out, CL_ + CA_);
}

// round 15
// speedup vs baseline: 3.5217x; 1.0226x over previous
#include <cuda_runtime.h>
#include <cuda_fp16.h>
#include <math.h>
#include <stdint.h>

// ---------------------------------------------------------------------------
// Problem dimensions
// ---------------------------------------------------------------------------
#define BT_   1536
#define WL_   33
#define WA_   50
#define WE_   30
#define EL_   300
#define EA_   988
#define EE_   20
#define HH_   128
#define CL_   128
#define CA_   256
#define CE_   64
#define KL_   5
#define KA_   10
#define KE_   3
#define WOL_  (WL_ - KL_ + 1)      // 29
#define WOA_  (WA_ - KA_ + 1)      // 41
#define WOE_  (WE_ - KE_ + 1)      // 28
#define ML_   (BT_ * WOL_)         // 44544
#define MA_   (BT_ * WOA_)         // 62976
#define ME_   (BT_ * WOE_)         // 43008
#define KKL_  (KL_ * EL_)          // 1500
#define KKA_  (KA_ * EA_)          // 9880
#define KKE_  (KE_ * HH_)          // 384
#define OUTW_ 448

// ---------------------------------------------------------------------------
// Device scratch — EXACT proven 134 MB layout
// ---------------------------------------------------------------------------
#define OFF_CA     ((size_t)0)
#define OFF_CL     ((size_t)16121856)
#define OFF_CE     ((size_t)21823488)
#define OFF_HBUF   ((size_t)24576000)
#define OFF_WAT    ((size_t)30474240)
#define OFF_WLT    ((size_t)33003520)
#define OFF_WET    ((size_t)33195520)
#define OFF_WIHT   ((size_t)33220096)
#define OFF_WHHT   ((size_t)33230336)
#define OFF_HWLPT  ((size_t)33295872)
#define OFF_HWLGT  ((size_t)33312256)
#define OFF_HWAPT  ((size_t)33328640)
#define OFF_HWAGT  ((size_t)33394176)
#define OFF_HWEPT  ((size_t)33459712)
#define OFF_HWEGT  ((size_t)33463808)
#define SCRATCH_TOTAL ((size_t)33467904)

__device__ __align__(16) float g_scratch[SCRATCH_TOTAL];

// ---------------------------------------------------------------------------
// Weight permute: (Cout, Cin, K) -> (Cout, K, Cin)
// ---------------------------------------------------------------------------
__global__ void permute_w_kernel(const float* __restrict__ src, size_t dstOff,
                                 int Cout, int Cin, int K)
{
    int idx = blockIdx.x * 256 + threadIdx.x;
    int tot = Cout * Cin * K;
    if (idx >= tot) return;
    float* dst = g_scratch + dstOff;
    int ci = idx % Cin;
    int r  = idx / Cin;
    int k  = r % K;
    int co = r / K;
    dst[idx] = src[(size_t)co * Cin * K + (size_t)ci * K + k];
}

// 2D transpose: src (R x C) -> dst (C x R)
__global__ void transpose2d_kernel(const float* __restrict__ src, size_t dstOff,
                                   int R, int C)
{
    int idx = blockIdx.x * 256 + threadIdx.x;
    int tot = R * C;
    if (idx >= tot) return;
    float* dst = g_scratch + dstOff;
    int r = idx % R;
    int c = idx / R;
    dst[idx] = src[(size_t)r * C + c];
}

// ---------------------------------------------------------------------------
// Shared HMMA helpers
// ---------------------------------------------------------------------------
__device__ __forceinline__ uint32_t f2h2(float lo, float hi) {
    __half2 h = __floats2half2_rn(lo, hi);
    return *(uint32_t*)&h;
}

__device__ __forceinline__ void mma_f16(float c[4], uint32_t a0, uint32_t a1,
                                        uint32_t a2, uint32_t a3,
                                        uint32_t b0, uint32_t b1) {
    asm volatile(
        "mma.sync.aligned.m16n8k16.row.col.f32.f16.f16.f32 "
        "{%0,%1,%2,%3}, {%4,%5,%6,%7}, {%8,%9}, {%0,%1,%2,%3};"
        : "+f"(c[0]), "+f"(c[1]), "+f"(c[2]), "+f"(c[3])
        : "r"(a0), "r"(a1), "r"(a2), "r"(a3), "r"(b0), "r"(b1));
}

#define TBM 128
#define TBK 16
#define ASTR 264
#define BSTR 520     // 256 cols * 2 + 8 pad ; 520 mod 32 == 8 (conflict-free)

// ---------------------------------------------------------------------------
// WIDE fp16 HMMA conv-as-GEMM: CTA 128x256, 512 threads, 16 warps (2x8).
// A loaded ONCE per row-tile (full N in one CTA). Per-thread structure
// identical to the proven 256-thread kernel; staging registers are FEWER
// (ra[1], rb[2]).
// ---------------------------------------------------------------------------
__global__ __launch_bounds__(512)
void conv_gemm_f16_wide(const float* __restrict__ X,
                        size_t wOff, size_t cOff,
                        int KK, int Wout, int rowStride, int btStride)
{
    __shared__ __align__(16) uint32_t As[2][4][ASTR];
    __shared__ __align__(16) uint32_t Bs[2][4][BSTR];

    const float* Wt   = g_scratch + wOff;
    float*       Cmat = g_scratch + cOff;

    const int tid  = threadIdx.x;
    const int bm   = blockIdx.y * TBM;
    const int wid  = tid >> 5;
    const int lane = tid & 31;
    const int wm   = wid & 1;            // 0..1  (64 rows)
    const int wn   = wid >> 1;           // 0..7  (32 cols)
    const int g    = lane >> 2;
    const int c    = lane & 3;

    const int lr   = tid >> 2;           // 0..127
    const int lk   = (tid & 3) * 4;
    const int hb   = (tid & 3) >> 1;
    const int row0 = ((tid & 3) * 2) & 3;

    // A: one window pointer (row lr)
    const float* aRow;
    {
        int m  = bm + lr;
        int bt = m / Wout;
        int t  = m - bt * Wout;
        aRow = X + (size_t)bt * btStride + (size_t)t * rowStride;
    }
    const int cA0 = ((lr >> 4) * 32) + ((lr & 7) * 4) + hb * 2 + ((lr & 15) >> 3);

    // B: rows lr and lr+128
    const float* bRow[2];
    int cB[2];
#pragma unroll
    for (int v = 0; v < 2; v++) {
        bRow[v] = Wt + (size_t)(lr + v * 128) * KK;
        cB[v]   = (lr + v * 128) * 2 + hb;
    }

    float acc[4][4][4];
#pragma unroll
    for (int mi = 0; mi < 4; mi++)
#pragma unroll
        for (int ni = 0; ni < 4; ni++)
#pragma unroll
            for (int q = 0; q < 4; q++) acc[mi][ni][q] = 0.f;

    float4 ra, rb[2];
    const int ktiles = (KK + TBK - 1) / TBK;

    // ---- prologue: tile 0 -> stage 0; tile 1 -> registers
    {
        bool ok = (lk < KK);
        ra = ok ? *(const float4*)(aRow + lk) : make_float4(0.f, 0.f, 0.f, 0.f);
#pragma unroll
        for (int v = 0; v < 2; v++)
            rb[v] = ok ? *(const float4*)(bRow[v] + lk)
                       : make_float4(0.f, 0.f, 0.f, 0.f);

        As[0][row0    ][cA0] = f2h2(ra.x, ra.y);
        As[0][row0 + 1][cA0] = f2h2(ra.z, ra.w);
#pragma unroll
        for (int v = 0; v < 2; v++) {
            Bs[0][row0    ][cB[v]] = f2h2(rb[v].x, rb[v].y);
            Bs[0][row0 + 1][cB[v]] = f2h2(rb[v].z, rb[v].w);
        }
        if (ktiles > 1) {
            int kg = TBK + lk;
            bool ok1 = (kg < KK);
            ra = ok1 ? *(const float4*)(aRow + kg) : make_float4(0.f, 0.f, 0.f, 0.f);
#pragma unroll
            for (int v = 0; v < 2; v++)
                rb[v] = ok1 ? *(const float4*)(bRow[v] + kg)
                            : make_float4(0.f, 0.f, 0.f, 0.f);
        }
    }
    __syncthreads();

    for (int kt = 0; kt < ktiles; kt++) {
        // 1) STS tile kt+1 (registers loaded a full iteration ago)
        if (kt + 1 < ktiles) {
            const int st = (kt + 1) & 1;
            As[st][row0    ][cA0] = f2h2(ra.x, ra.y);
            As[st][row0 + 1][cA0] = f2h2(ra.z, ra.w);
#pragma unroll
            for (int v = 0; v < 2; v++) {
                Bs[st][row0    ][cB[v]] = f2h2(rb[v].x, rb[v].y);
                Bs[st][row0 + 1][cB[v]] = f2h2(rb[v].z, rb[v].w);
            }
        }
        // 2) LDG tile kt+2
        if (kt + 2 < ktiles) {
            int kg = (kt + 2) * TBK + lk;
            bool ok = (kg < KK);
            ra = ok ? *(const float4*)(aRow + kg) : make_float4(0.f, 0.f, 0.f, 0.f);
#pragma unroll
            for (int v = 0; v < 2; v++)
                rb[v] = ok ? *(const float4*)(bRow[v] + kg)
                           : make_float4(0.f, 0.f, 0.f, 0.f);
        }
        // 3) compute from stage kt&1
        {
            const int st = kt & 1;
            uint2 bfr[4];
#pragma unroll
            for (int ni = 0; ni < 4; ni++)
                bfr[ni] = *(const uint2*)&Bs[st][c][(wn * 32 + ni * 8 + g) * 2];
#pragma unroll
            for (int mi = 0; mi < 4; mi++) {
                uint4 av = *(const uint4*)&As[st][c][(wm * 4 + mi) * 32 + g * 4];
#pragma unroll
                for (int ni = 0; ni < 4; ni++)
                    mma_f16(acc[mi][ni], av.x, av.y, av.z, av.w,
                            bfr[ni].x, bfr[ni].y);
            }
        }
        // 4) barrier
        if (kt + 1 < ktiles) __syncthreads();
    }

    // epilogue (N = 256)
#pragma unroll
    for (int mi = 0; mi < 4; mi++) {
#pragma unroll
        for (int ni = 0; ni < 4; ni++) {
            int row = bm + wm * 64 + mi * 16 + g;
            int col = wn * 32 + ni * 8 + c * 2;
            *(float2*)(Cmat + (size_t)row * CA_ + col) =
                make_float2(acc[mi][ni][0], acc[mi][ni][1]);
            *(float2*)(Cmat + (size_t)(row + 8) * CA_ + col) =
                make_float2(acc[mi][ni][2], acc[mi][ni][3]);
        }
    }
}

// ---------------------------------------------------------------------------
// 256-thread fp16 HMMA conv-as-GEMM — BYTE-IDENTICAL to round 10 (for gemmL)
// ---------------------------------------------------------------------------
#define TBN 128

__global__ __launch_bounds__(256, 2)
void conv_gemm_f16_kernel(const float* __restrict__ X,
                          size_t wOff, size_t cOff,
                          int N, int KK,
                          int Wout, int rowStride, int btStride)
{
    __shared__ __align__(16) uint32_t As[2][4][ASTR];
    __shared__ __align__(16) uint32_t Bs[2][4][ASTR];

    const float* Wt   = g_scratch + wOff;
    float*       Cmat = g_scratch + cOff;

    const int tid  = threadIdx.x;
    const int bm   = blockIdx.y * TBM;
    const int bn   = blockIdx.x * TBN;
    const int wid  = tid >> 5;
    const int lane = tid & 31;
    const int wm   = wid & 1;
    const int wn   = wid >> 1;
    const int g    = lane >> 2;
    const int c    = lane & 3;

    const int lr   = tid >> 2;
    const int lk   = (tid & 3) * 4;
    const int hb   = (tid & 3) >> 1;
    const int row0 = ((tid & 3) * 2) & 3;

    const float* aRow[2];
    const float* bRow[2];
    int cA[2], cB[2];
#pragma unroll
    for (int v = 0; v < 2; v++) {
        int mr = lr + v * 64;
        int m  = bm + mr;
        int bt = m / Wout;
        int t  = m - bt * Wout;
        aRow[v] = X + (size_t)bt * btStride + (size_t)t * rowStride;
        int q = mr >> 4, r = mr & 15;
        cA[v] = q * 32 + (r & 7) * 4 + hb * 2 + (r >> 3);
        cB[v] = mr * 2 + hb;
        bRow[v] = Wt + (size_t)(bn + mr) * KK;
    }

    float acc[4][4][4];
#pragma unroll
    for (int mi = 0; mi < 4; mi++)
#pragma unroll
        for (int ni = 0; ni < 4; ni++)
#pragma unroll
            for (int q = 0; q < 4; q++) acc[mi][ni][q] = 0.f;

    float4 ra[2], rb[2];
    const int ktiles = (KK + TBK - 1) / TBK;

    {
        bool ok = (lk < KK);
#pragma unroll
        for (int v = 0; v < 2; v++) {
            ra[v] = ok ? *(const float4*)(aRow[v] + lk)
                       : make_float4(0.f, 0.f, 0.f, 0.f);
            rb[v] = ok ? *(const float4*)(bRow[v] + lk)
                       : make_float4(0.f, 0.f, 0.f, 0.f);
        }
#pragma unroll
        for (int v = 0; v < 2; v++) {
            As[0][row0    ][cA[v]] = f2h2(ra[v].x, ra[v].y);
            As[0][row0 + 1][cA[v]] = f2h2(ra[v].z, ra[v].w);
            Bs[0][row0    ][cB[v]] = f2h2(rb[v].x, rb[v].y);
            Bs[0][row0 + 1][cB[v]] = f2h2(rb[v].z, rb[v].w);
        }
        if (ktiles > 1) {
            int kg = TBK + lk;
            bool ok1 = (kg < KK);
#pragma unroll
            for (int v = 0; v < 2; v++) {
                ra[v] = ok1 ? *(const float4*)(aRow[v] + kg)
                            : make_float4(0.f, 0.f, 0.f, 0.f);
                rb[v] = ok1 ? *(const float4*)(bRow[v] + kg)
                            : make_float4(0.f, 0.f, 0.f, 0.f);
            }
        }
    }
    __syncthreads();

    for (int kt = 0; kt < ktiles; kt++) {
        if (kt + 1 < ktiles) {
            const int st = (kt + 1) & 1;
#pragma unroll
            for (int v = 0; v < 2; v++) {
                As[st][row0    ][cA[v]] = f2h2(ra[v].x, ra[v].y);
                As[st][row0 + 1][cA[v]] = f2h2(ra[v].z, ra[v].w);
                Bs[st][row0    ][cB[v]] = f2h2(rb[v].x, rb[v].y);
                Bs[st][row0 + 1][cB[v]] = f2h2(rb[v].z, rb[v].w);
            }
        }
        if (kt + 2 < ktiles) {
            int kg = (kt + 2) * TBK + lk;
            bool ok = (kg < KK);
#pragma unroll
            for (int v = 0; v < 2; v++) {
                ra[v] = ok ? *(const float4*)(aRow[v] + kg)
                           : make_float4(0.f, 0.f, 0.f, 0.f);
                rb[v] = ok ? *(const float4*)(bRow[v] + kg)
                           : make_float4(0.f, 0.f, 0.f, 0.f);
            }
        }
        {
            const int st = kt & 1;
            uint2 bfr[4];
#pragma unroll
            for (int ni = 0; ni < 4; ni++)
                bfr[ni] = *(const uint2*)&Bs[st][c][(wn * 32 + ni * 8 + g) * 2];
#pragma unroll
            for (int mi = 0; mi < 4; mi++) {
                uint4 av = *(const uint4*)&As[st][c][(wm * 4 + mi) * 32 + g * 4];
#pragma unroll
                for (int ni = 0; ni < 4; ni++)
                    mma_f16(acc[mi][ni], av.x, av.y, av.z, av.w,
                            bfr[ni].x, bfr[ni].y);
            }
        }
        if (kt + 1 < ktiles) __syncthreads();
    }

#pragma unroll
    for (int mi = 0; mi < 4; mi++) {
#pragma unroll
        for (int ni = 0; ni < 4; ni++) {
            int row = bm + wm * 64 + mi * 16 + g;
            int col = bn + wn * 32 + ni * 8 + c * 2;
            *(float2*)(Cmat + (size_t)row * N + col) =
                make_float2(acc[mi][ni][0], acc[mi][ni][1]);
            *(float2*)(Cmat + (size_t)(row + 8) * N + col) =
                make_float2(acc[mi][ni][2], acc[mi][ni][3]);
        }
    }
}

// ---------------------------------------------------------------------------
// FP32 conv-as-GEMM (small Emotient GEMM)
// ---------------------------------------------------------------------------
template<int BM, int BN, int BK, int TM, int TN>
__global__ __launch_bounds__(256)
void conv_gemm_kernel(size_t xOff, size_t wOff, size_t cOff,
                      int M, int N, int KK,
                      int Wout, int rowStride, int btStride)
{
    static_assert((BM / TM) * (BN / TN) == 256, "256 threads");
    constexpr int A_VECS = BM * BK / (256 * 4);
    constexpr int B_VECS = BN * BK / (256 * 4);

    const float* X    = g_scratch + xOff;
    const float* Wt   = g_scratch + wOff;
    float*       Cmat = g_scratch + cOff;

    __shared__ __align__(16) float As[BK][BM + 4];
    __shared__ __align__(16) float Bs[BK][BN + 4];

    const int tid = threadIdx.x;
    const int bm  = blockIdx.x * BM;
    const int bn  = blockIdx.y * BN;
    const int lr = tid >> 2;
    const int lk = (tid & 3) * 4;

    const float* aRow[A_VECS];
#pragma unroll
    for (int v = 0; v < A_VECS; v++) {
        int m  = bm + lr + v * 64;
        int bt = m / Wout;
        int t  = m - bt * Wout;
        aRow[v] = X + (size_t)bt * btStride + (size_t)t * rowStride;
    }
    const float* bRow[B_VECS];
#pragma unroll
    for (int v = 0; v < B_VECS; v++) {
        int n = bn + lr + v * 64;
        bRow[v] = Wt + (size_t)n * KK;
    }

    float acc[TM][TN];
#pragma unroll
    for (int i = 0; i < TM; i++)
#pragma unroll
        for (int j = 0; j < TN; j++) acc[i][j] = 0.f;

    const int ty = tid / (BN / TN);
    const int tx = tid % (BN / TN);

    for (int k0 = 0; k0 < KK; k0 += BK) {
        int kg = k0 + lk;
        bool ok = (kg < KK);
#pragma unroll
        for (int v = 0; v < A_VECS; v++) {
            float4 a = ok ? *(const float4*)(aRow[v] + kg)
                          : make_float4(0.f, 0.f, 0.f, 0.f);
            int mr = lr + v * 64;
            As[lk + 0][mr] = a.x; As[lk + 1][mr] = a.y;
            As[lk + 2][mr] = a.z; As[lk + 3][mr] = a.w;
        }
#pragma unroll
        for (int v = 0; v < B_VECS; v++) {
            float4 b = ok ? *(const float4*)(bRow[v] + kg)
                          : make_float4(0.f, 0.f, 0.f, 0.f);
            int nr = lr + v * 64;
            Bs[lk + 0][nr] = b.x; Bs[lk + 1][nr] = b.y;
            Bs[lk + 2][nr] = b.z; Bs[lk + 3][nr] = b.w;
        }
        __syncthreads();

#pragma unroll
        for (int kk = 0; kk < BK; kk++) {
            float a[TM], b[TN];
#pragma unroll
            for (int i = 0; i < TM; i += 4) {
                float4 v = *(const float4*)&As[kk][ty * TM + i];
                a[i] = v.x; a[i + 1] = v.y; a[i + 2] = v.z; a[i + 3] = v.w;
            }
#pragma unroll
            for (int j = 0; j < TN; j += 4) {
                float4 v = *(const float4*)&Bs[kk][tx * TN + j];
                b[j] = v.x; b[j + 1] = v.y; b[j + 2] = v.z; b[j + 3] = v.w;
            }
#pragma unroll
            for (int i = 0; i < TM; i++)
#pragma unroll
                for (int j = 0; j < TN; j++)
                    acc[i][j] = fmaf(a[i], b[j], acc[i][j]);
        }
        __syncthreads();
    }

#pragma unroll
    for (int i = 0; i < TM; i++) {
        size_t m = (size_t)bm + ty * TM + i;
        float* cp = Cmat + m * (size_t)N + bn + tx * TN;
#pragma unroll
        for (int j = 0; j < TN; j += 4) {
            float4 v = make_float4(acc[i][j], acc[i][j + 1],
                                   acc[i][j + 2], acc[i][j + 3]);
            *(float4*)(cp + j) = v;
        }
    }
}

// ---------------------------------------------------------------------------
// Masked LSTM: 16 sequences per block (round-14, passed)
// ---------------------------------------------------------------------------
#define SEQS 16
__device__ __forceinline__ float sigf(float x) { return 1.f / (1.f + expf(-x)); }

#define LSTM_SMEM_FLOATS (SEQS*HH_ + SEQS*HH_ + SEQS*EE_ + 512*(SEQS+1) + SEQS)
#define LSTM_SMEM_BYTES  (LSTM_SMEM_FLOATS * 4)

__global__ __launch_bounds__(512)
void lstm_kernel(const float* __restrict__ xe,
                 const int*   __restrict__ wlen,
                 const float* __restrict__ bih,
                 const float* __restrict__ bhh)
{
    const float* WihT = g_scratch + OFF_WIHT;
    const float* WhhT = g_scratch + OFF_WHHT;
    float*       hbuf = g_scratch + OFF_HBUF;

    extern __shared__ float sm[];
    float* sh   = sm;
    float* sc   = sh + SEQS * HH_;
    float* sx   = sc + SEQS * HH_;
    float* sz   = sx + SEQS * EE_;
    int*   slen = (int*)(sz + 512 * (SEQS + 1));

    const int tid = threadIdx.x;
    const int bt0 = blockIdx.x * SEQS;

    for (int i = tid; i < SEQS * HH_; i += 512) {
        sh[i] = 0.f;
        sc[i] = 0.f;
    }
    if (tid < SEQS) slen[tid] = wlen[bt0 + tid];
    __syncthreads();

    const int r = tid;
    const float bias = bih[r] + bhh[r];

    for (int t = 0; t < WE_; t++) {
        for (int i = tid; i < SEQS * EE_; i += 512) {
            int s = i / EE_, e = i - s * EE_;
            sx[s * EE_ + e] = xe[(size_t)(bt0 + s) * (WE_ * EE_) + t * EE_ + e];
        }
        __syncthreads();

        float acc[SEQS];
#pragma unroll
        for (int s = 0; s < SEQS; s++) acc[s] = bias;
#pragma unroll
        for (int e = 0; e < EE_; e++) {
            float w = WihT[e * 512 + r];
#pragma unroll
            for (int s = 0; s < SEQS; s++) acc[s] = fmaf(w, sx[s * EE_ + e], acc[s]);
        }
#pragma unroll 4
        for (int j = 0; j < HH_; j++) {
            float w = WhhT[j * 512 + r];
#pragma unroll
            for (int s = 0; s < SEQS; s++) acc[s] = fmaf(w, sh[s * HH_ + j], acc[s]);
        }
#pragma unroll
        for (int s = 0; s < SEQS; s++) sz[r * (SEQS + 1) + s] = acc[s];
        __syncthreads();

#pragma unroll
        for (int p = tid; p < SEQS * HH_; p += 512) {
            int s = p & (SEQS - 1);
            int j = p >> 4;
            float zi = sz[j * (SEQS + 1) + s];
            float zf = sz[(HH_ + j) * (SEQS + 1) + s];
            float zg = sz[(2 * HH_ + j) * (SEQS + 1) + s];
            float zo = sz[(3 * HH_ + j) * (SEQS + 1) + s];
            float cc = sc[s * HH_ + j];
            float cn = sigf(zf) * cc + sigf(zi) * tanhf(zg);
            float hn = sigf(zo) * tanhf(cn);
            bool valid = (t < slen[s]);
            sc[s * HH_ + j] = valid ? cn : cc;
            sh[s * HH_ + j] = valid ? hn : sh[s * HH_ + j];
            hbuf[(size_t)(bt0 + s) * (WE_ * HH_) + t * HH_ + j] = valid ? hn : 0.f;
        }
        __syncthreads();
    }
}

// ---------------------------------------------------------------------------
// Fused maxpool + highway, 8 bt-rows per block (round-14, passed)
// ---------------------------------------------------------------------------
#define BTB 8
__global__ void pool_highway_kernel(size_t cOff, int N, int Wout,
                                    const float* __restrict__ convB,
                                    size_t wpOff, const float* __restrict__ bp,
                                    size_t wgOff, const float* __restrict__ bg,
                                    float* __restrict__ out, int outOff)
{
    extern __shared__ float sy[];
    const float* Cmat = g_scratch + cOff;
    const float* WpT  = g_scratch + wpOff;
    const float* WgT  = g_scratch + wgOff;

    const int bt0 = blockIdx.x * BTB;
    const int co  = threadIdx.x;
    const float cb = convB[co];

#pragma unroll
    for (int b = 0; b < BTB; b++) {
        const float* cp = Cmat + (size_t)(bt0 + b) * Wout * N + co;
        float y = cp[0];
        for (int t = 1; t < Wout; t++) y = fmaxf(y, cp[(size_t)t * N]);
        sy[b * N + co] = y + cb;
    }
    __syncthreads();

    float ap[BTB], ag[BTB];
    const float bpc = bp[co], bgc = bg[co];
#pragma unroll
    for (int b = 0; b < BTB; b++) { ap[b] = bpc; ag[b] = bgc; }

    for (int j = 0; j < N; j++) {
        float wp = WpT[j * N + co];
        float wg = WgT[j * N + co];
#pragma unroll
        for (int b = 0; b < BTB; b++) {
            float yj = sy[b * N + j];
            ap[b] = fmaf(wp, yj, ap[b]);
            ag[b] = fmaf(wg, yj, ag[b]);
        }
    }
#pragma unroll
    for (int b = 0; b < BTB; b++) {
        float p  = fmaxf(ap[b], 0.f);
        float gg = 1.f / (1.f + expf(-ag[b]));
        float y  = sy[b * N + co];
        out[(size_t)(bt0 + b) * OUTW_ + outOff + co] = gg * p + (1.f - gg) * y;
    }
}

// ---------------------------------------------------------------------------
// Launch
// ---------------------------------------------------------------------------
extern "C" void kernel_launch(void* const* d_in, const int* in_sizes, int n_in,
                              void* d_out, int out_size)
{
    (void)in_sizes; (void)n_in; (void)out_size;
    const float* x_lin   = (const float*)d_in[0];
    const float* x_aco   = (const float*)d_in[1];
    const float* x_emo   = (const float*)d_in[2];
    const int*   wlen    = (const int*)  d_in[3];
    const float* convL_w = (const float*)d_in[5];
    const float* convL_b = (const float*)d_in[6];
    const float* convA_w = (const float*)d_in[7];
    const float* convA_b = (const float*)d_in[8];
    const float* convE_w = (const float*)d_in[9];
    const float* convE_b = (const float*)d_in[10];
    const float* hwL_Wp  = (const float*)d_in[11];
    const float* hwL_bp  = (const float*)d_in[12];
    const float* hwL_Wg  = (const float*)d_in[13];
    const float* hwL_bg  = (const float*)d_in[14];
    const float* hwA_Wp  = (const float*)d_in[15];
    const float* hwA_bp  = (const float*)d_in[16];
    const float* hwA_Wg  = (const float*)d_in[17];
    const float* hwA_bg  = (const float*)d_in[18];
    const float* hwE_Wp  = (const float*)d_in[19];
    const float* hwE_bp  = (const float*)d_in[20];
    const float* hwE_Wg  = (const float*)d_in[21];
    const float* hwE_bg  = (const float*)d_in[22];
    const float* Wih     = (const float*)d_in[23];
    const float* Whh     = (const float*)d_in[24];
    const float* bih     = (const float*)d_in[25];
    const float* bhh     = (const float*)d_in[26];
    float* out = (float*)d_out;

    cudaFuncSetAttribute(lstm_kernel,
                         cudaFuncAttributeMaxDynamicSharedMemorySize,
                         LSTM_SMEM_BYTES);

    // 1-3: conv weight permutes
    permute_w_kernel<<<(CA_ * EA_ * KA_ + 255) / 256, 256>>>(convA_w, OFF_WAT, CA_, EA_, KA_);
    permute_w_kernel<<<(CL_ * EL_ * KL_ + 255) / 256, 256>>>(convL_w, OFF_WLT, CL_, EL_, KL_);
    permute_w_kernel<<<(CE_ * HH_ * KE_ + 255) / 256, 256>>>(convE_w, OFF_WET, CE_, HH_, KE_);

    // 4: acoustic GEMM — WIDE full-N CTA (profiled launch)
    conv_gemm_f16_wide<<<dim3(1, MA_ / TBM), 512>>>(
        x_aco, OFF_WAT, OFF_CA, KKA_, WOA_, EA_, WA_ * EA_);

    // 5: linguistic GEMM (proven 256-thread kernel; already full-N)
    conv_gemm_f16_kernel<<<dim3(CL_ / TBN, ML_ / TBM), 256>>>(
        x_lin, OFF_WLT, OFF_CL, CL_, KKL_, WOL_, EL_, WL_ * EL_);

    // 6-7: LSTM weight transposes
    transpose2d_kernel<<<(512 * EE_ + 255) / 256, 256>>>(Wih, OFF_WIHT, 512, EE_);
    transpose2d_kernel<<<(512 * HH_ + 255) / 256, 256>>>(Whh, OFF_WHHT, 512, HH_);

    // 8: LSTM (-> hbuf), 16 seqs/block
    lstm_kernel<<<BT_ / SEQS, 512, LSTM_SMEM_BYTES>>>(x_emo, wlen, bih, bhh);

    // 9: emotient GEMM (fp32, input = hbuf)
    conv_gemm_kernel<128, 64, 16, 8, 4><<<dim3(ME_ / 128, CE_ / 64), 256>>>(
        OFF_HBUF, OFF_WET, OFF_CE, ME_, CE_, KKE_, WOE_, HH_, WE_ * HH_);

    // 10-15: highway weight transposes
    transpose2d_kernel<<<(CL_ * CL_ + 255) / 256, 256>>>(hwL_Wp, OFF_HWLPT, CL_, CL_);
    transpose2d_kernel<<<(CL_ * CL_ + 255) / 256, 256>>>(hwL_Wg, OFF_HWLGT, CL_, CL_);
    transpose2d_kernel<<<(CA_ * CA_ + 255) / 256, 256>>>(hwA_Wp, OFF_HWAPT, CA_, CA_);
    transpose2d_kernel<<<(CA_ * CA_ + 255) / 256, 256>>>(hwA_Wg, OFF_HWAGT, CA_, CA_);
    transpose2d_kernel<<<(CE_ * CE_ + 255) / 256, 256>>>(hwE_Wp, OFF_HWEPT, CE_, CE_);
    transpose2d_kernel<<<(CE_ * CE_ + 255) / 256, 256>>>(hwE_Wg, OFF_HWEGT, CE_, CE_);

    // 16-18: fused maxpool + highway -> output
    pool_highway_kernel<<<BT_ / BTB, CL_, BTB * CL_ * sizeof(float)>>>(
        OFF_CL, CL_, WOL_, convL_b, OFF_HWLPT, hwL_bp, OFF_HWLGT, hwL_bg, out, 0);
    pool_highway_kernel<<<BT_ / BTB, CA_, BTB * CA_ * sizeof(float)>>>(
        OFF_CA, CA_, WOA_, convA_b, OFF_HWAPT, hwA_bp, OFF_HWAGT, hwA_bg, out, CL_);
    pool_highway_kernel<<<BT_ / BTB, CE_, BTB * CE_ * sizeof(float)>>>(
        OFF_CE, CE_, WOE_, convE_b, OFF_HWEPT, hwE_bp, OFF_HWEGT, hwE_bg, out, CL_ + CA_);
}

// round 16
// speedup vs baseline: 3.6074x; 1.0243x over previous
#include <cuda_runtime.h>
#include <cuda_fp16.h>
#include <math.h>
#include <stdint.h>

// ---------------------------------------------------------------------------
// Problem dimensions
// ---------------------------------------------------------------------------
#define BT_   1536
#define WL_   33
#define WA_   50
#define WE_   30
#define EL_   300
#define EA_   988
#define EE_   20
#define HH_   128
#define CL_   128
#define CA_   256
#define CE_   64
#define KL_   5
#define KA_   10
#define KE_   3
#define WOL_  (WL_ - KL_ + 1)      // 29
#define WOA_  (WA_ - KA_ + 1)      // 41
#define WOE_  (WE_ - KE_ + 1)      // 28
#define ML_   (BT_ * WOL_)         // 44544
#define MA_   (BT_ * WOA_)         // 62976
#define ME_   (BT_ * WOE_)         // 43008
#define KKL_  (KL_ * EL_)          // 1500
#define KKA_  (KA_ * EA_)          // 9880
#define KKE_  (KE_ * HH_)          // 384
#define OUTW_ 448

// ---------------------------------------------------------------------------
// Device scratch — EXACT proven 134 MB layout
// ---------------------------------------------------------------------------
#define OFF_CA     ((size_t)0)
#define OFF_CL     ((size_t)16121856)
#define OFF_CE     ((size_t)21823488)
#define OFF_HBUF   ((size_t)24576000)
#define OFF_WAT    ((size_t)30474240)
#define OFF_WLT    ((size_t)33003520)
#define OFF_WET    ((size_t)33195520)
#define OFF_WIHT   ((size_t)33220096)
#define OFF_WHHT   ((size_t)33230336)
#define OFF_HWLPT  ((size_t)33295872)
#define OFF_HWLGT  ((size_t)33312256)
#define OFF_HWAPT  ((size_t)33328640)
#define OFF_HWAGT  ((size_t)33394176)
#define OFF_HWEPT  ((size_t)33459712)
#define OFF_HWEGT  ((size_t)33463808)
#define SCRATCH_TOTAL ((size_t)33467904)

__device__ __align__(16) float g_scratch[SCRATCH_TOTAL];

// ---------------------------------------------------------------------------
// Weight permute: (Cout, Cin, K) -> (Cout, K, Cin)
// ---------------------------------------------------------------------------
__global__ void permute_w_kernel(const float* __restrict__ src, size_t dstOff,
                                 int Cout, int Cin, int K)
{
    int idx = blockIdx.x * 256 + threadIdx.x;
    int tot = Cout * Cin * K;
    if (idx >= tot) return;
    float* dst = g_scratch + dstOff;
    int ci = idx % Cin;
    int r  = idx / Cin;
    int k  = r % K;
    int co = r / K;
    dst[idx] = src[(size_t)co * Cin * K + (size_t)ci * K + k];
}

// 2D transpose: src (R x C) -> dst (C x R)
__global__ void transpose2d_kernel(const float* __restrict__ src, size_t dstOff,
                                   int R, int C)
{
    int idx = blockIdx.x * 256 + threadIdx.x;
    int tot = R * C;
    if (idx >= tot) return;
    float* dst = g_scratch + dstOff;
    int r = idx % R;
    int c = idx / R;
    dst[idx] = src[(size_t)r * C + c];
}

// ---------------------------------------------------------------------------
// Shared HMMA helpers
// ---------------------------------------------------------------------------
__device__ __forceinline__ uint32_t f2h2(float lo, float hi) {
    __half2 h = __floats2half2_rn(lo, hi);
    return *(uint32_t*)&h;
}

__device__ __forceinline__ void mma_f16(float c[4], uint32_t a0, uint32_t a1,
                                        uint32_t a2, uint32_t a3,
                                        uint32_t b0, uint32_t b1) {
    asm volatile(
        "mma.sync.aligned.m16n8k16.row.col.f32.f16.f16.f32 "
        "{%0,%1,%2,%3}, {%4,%5,%6,%7}, {%8,%9}, {%0,%1,%2,%3};"
        : "+f"(c[0]), "+f"(c[1]), "+f"(c[2]), "+f"(c[3])
        : "r"(a0), "r"(a1), "r"(a2), "r"(a3), "r"(b0), "r"(b1));
}

#define TBM 128
#define TBK 16
#define ASTR 264
#define BSTR 520

// ---------------------------------------------------------------------------
// WIDE fp16 HMMA conv-as-GEMM, double-pumped: CTA 128x256, 512 threads,
// TBK32 stages (two k16 sub-tiles per smem stage -> half the barriers),
// same 12-register staging set reused for both chunks.
// Dynamic smem: As[2][8][ASTR] + Bs[2][8][BSTR] = 50176 B.
// ---------------------------------------------------------------------------
#define WIDE_SMEM_BYTES ((2*8*ASTR + 2*8*BSTR) * 4)

__global__ __launch_bounds__(512)
void conv_gemm_f16_wide(const float* __restrict__ X,
                        size_t wOff, size_t cOff,
                        int KK, int Wout, int rowStride, int btStride)
{
    extern __shared__ __align__(16) uint32_t dsm[];
    uint32_t* AsB = dsm;                 // (st*8 + row)*ASTR + col
    uint32_t* BsB = dsm + 2 * 8 * ASTR;  // (st*8 + row)*BSTR + col

    const float* Wt   = g_scratch + wOff;
    float*       Cmat = g_scratch + cOff;

    const int tid  = threadIdx.x;
    const int bm   = blockIdx.y * TBM;
    const int wid  = tid >> 5;
    const int lane = tid & 31;
    const int wm   = wid & 1;            // 0..1  (64 rows)
    const int wn   = wid >> 1;           // 0..7  (32 cols)
    const int g    = lane >> 2;
    const int c    = lane & 3;

    const int lr   = tid >> 2;           // 0..127
    const int lk   = (tid & 3) * 4;      // 0,4,8,12
    const int hb   = (tid & 3) >> 1;
    const int row0 = ((tid & 3) * 2) & 3;

    // A: one window pointer (row lr)
    const float* aRow;
    {
        int m  = bm + lr;
        int bt = m / Wout;
        int t  = m - bt * Wout;
        aRow = X + (size_t)bt * btStride + (size_t)t * rowStride;
    }
    const int cA0 = ((lr >> 4) * 32) + ((lr & 7) * 4) + hb * 2 + ((lr & 15) >> 3);

    // B: rows lr and lr+128
    const float* bRow[2];
    int cB[2];
#pragma unroll
    for (int v = 0; v < 2; v++) {
        bRow[v] = Wt + (size_t)(lr + v * 128) * KK;
        cB[v]   = (lr + v * 128) * 2 + hb;
    }

    float acc[4][4][4];
#pragma unroll
    for (int mi = 0; mi < 4; mi++)
#pragma unroll
        for (int ni = 0; ni < 4; ni++)
#pragma unroll
            for (int q = 0; q < 4; q++) acc[mi][ni][q] = 0.f;

    float4 ra, rb[2];
    const int ktiles = (KK + 31) / 32;   // 32-k tiles

    // ---- macros for load/store of one 16-k chunk (staging regs ra/rb) ----
#define LOADCHUNK(kbase)                                                     \
    do {                                                                     \
        int kg = (kbase) + lk;                                               \
        bool ok = (kg < KK);                                                 \
        ra = ok ? *(const float4*)(aRow + kg)                                \
                : make_float4(0.f, 0.f, 0.f, 0.f);                           \
        rb[0] = ok ? *(const float4*)(bRow[0] + kg)                          \
                   : make_float4(0.f, 0.f, 0.f, 0.f);                        \
        rb[1] = ok ? *(const float4*)(bRow[1] + kg)                          \
                   : make_float4(0.f, 0.f, 0.f, 0.f);                        \
    } while (0)

#define STSCHUNK(st, q)                                                      \
    do {                                                                     \
        uint32_t* Ad = AsB + ((st) * 8 + (q) * 4 + row0) * ASTR + cA0;       \
        Ad[0]    = f2h2(ra.x, ra.y);                                         \
        Ad[ASTR] = f2h2(ra.z, ra.w);                                         \
        uint32_t* Bd = BsB + ((st) * 8 + (q) * 4 + row0) * BSTR;             \
        Bd[cB[0]]        = f2h2(rb[0].x, rb[0].y);                           \
        Bd[BSTR + cB[0]] = f2h2(rb[0].z, rb[0].w);                           \
        Bd[cB[1]]        = f2h2(rb[1].x, rb[1].y);                           \
        Bd[BSTR + cB[1]] = f2h2(rb[1].z, rb[1].w);                           \
    } while (0)

#define COMPUTE16(st, q)                                                     \
    do {                                                                     \
        const uint32_t* Ar = AsB + ((st) * 8 + (q) * 4 + c) * ASTR;          \
        const uint32_t* Br = BsB + ((st) * 8 + (q) * 4 + c) * BSTR;          \
        uint2 bfr[4];                                                        \
        _Pragma("unroll")                                                    \
        for (int ni = 0; ni < 4; ni++)                                       \
            bfr[ni] = *(const uint2*)&Br[(wn * 32 + ni * 8 + g) * 2];        \
        _Pragma("unroll")                                                    \
        for (int mi = 0; mi < 4; mi++) {                                     \
            uint4 av = *(const uint4*)&Ar[(wm * 4 + mi) * 32 + g * 4];       \
            _Pragma("unroll")                                                \
            for (int ni = 0; ni < 4; ni++)                                   \
                mma_f16(acc[mi][ni], av.x, av.y, av.z, av.w,                 \
                        bfr[ni].x, bfr[ni].y);                               \
        }                                                                    \
    } while (0)

    // ---- prologue: tile 0 both chunks -> stage 0; chunk0 of tile 1 -> regs
    LOADCHUNK(0);
    STSCHUNK(0, 0);
    LOADCHUNK(16);
    STSCHUNK(0, 1);
    if (ktiles > 1) LOADCHUNK(32);
    __syncthreads();

    for (int kt = 0; kt < ktiles; kt++) {
        const int stc = kt & 1;
        const int stn = (kt + 1) & 1;
        const bool more = (kt + 1 < ktiles);

        // 1) STS chunk0 of tile kt+1 (regs loaded a full iteration ago)
        if (more) STSCHUNK(stn, 0);
        // 2) LDG chunk1 of tile kt+1
        if (more) LOADCHUNK((kt + 1) * 32 + 16);
        // 3) compute k16 #0 of tile kt
        COMPUTE16(stc, 0);
        // 4) STS chunk1 of tile kt+1
        if (more) STSCHUNK(stn, 1);
        // 5) LDG chunk0 of tile kt+2
        if (kt + 2 < ktiles) LOADCHUNK((kt + 2) * 32);
        // 6) compute k16 #1 of tile kt
        COMPUTE16(stc, 1);
        // 7) barrier (publishes both chunks of kt+1, retires reads of kt)
        if (more) __syncthreads();
    }

#undef LOADCHUNK
#undef STSCHUNK
#undef COMPUTE16

    // epilogue (N = 256)
#pragma unroll
    for (int mi = 0; mi < 4; mi++) {
#pragma unroll
        for (int ni = 0; ni < 4; ni++) {
            int row = bm + wm * 64 + mi * 16 + g;
            int col = wn * 32 + ni * 8 + c * 2;
            *(float2*)(Cmat + (size_t)row * CA_ + col) =
                make_float2(acc[mi][ni][0], acc[mi][ni][1]);
            *(float2*)(Cmat + (size_t)(row + 8) * CA_ + col) =
                make_float2(acc[mi][ni][2], acc[mi][ni][3]);
        }
    }
}

// ---------------------------------------------------------------------------
// 256-thread fp16 HMMA conv-as-GEMM — BYTE-IDENTICAL to round 10 (for gemmL)
// ---------------------------------------------------------------------------
#define TBN 128

__global__ __launch_bounds__(256, 2)
void conv_gemm_f16_kernel(const float* __restrict__ X,
                          size_t wOff, size_t cOff,
                          int N, int KK,
                          int Wout, int rowStride, int btStride)
{
    __shared__ __align__(16) uint32_t As[2][4][ASTR];
    __shared__ __align__(16) uint32_t Bs[2][4][ASTR];

    const float* Wt   = g_scratch + wOff;
    float*       Cmat = g_scratch + cOff;

    const int tid  = threadIdx.x;
    const int bm   = blockIdx.y * TBM;
    const int bn   = blockIdx.x * TBN;
    const int wid  = tid >> 5;
    const int lane = tid & 31;
    const int wm   = wid & 1;
    const int wn   = wid >> 1;
    const int g    = lane >> 2;
    const int c    = lane & 3;

    const int lr   = tid >> 2;
    const int lk   = (tid & 3) * 4;
    const int hb   = (tid & 3) >> 1;
    const int row0 = ((tid & 3) * 2) & 3;

    const float* aRow[2];
    const float* bRow[2];
    int cA[2], cB[2];
#pragma unroll
    for (int v = 0; v < 2; v++) {
        int mr = lr + v * 64;
        int m  = bm + mr;
        int bt = m / Wout;
        int t  = m - bt * Wout;
        aRow[v] = X + (size_t)bt * btStride + (size_t)t * rowStride;
        int q = mr >> 4, r = mr & 15;
        cA[v] = q * 32 + (r & 7) * 4 + hb * 2 + (r >> 3);
        cB[v] = mr * 2 + hb;
        bRow[v] = Wt + (size_t)(bn + mr) * KK;
    }

    float acc[4][4][4];
#pragma unroll
    for (int mi = 0; mi < 4; mi++)
#pragma unroll
        for (int ni = 0; ni < 4; ni++)
#pragma unroll
            for (int q = 0; q < 4; q++) acc[mi][ni][q] = 0.f;

    float4 ra[2], rb[2];
    const int ktiles = (KK + TBK - 1) / TBK;

    {
        bool ok = (lk < KK);
#pragma unroll
        for (int v = 0; v < 2; v++) {
            ra[v] = ok ? *(const float4*)(aRow[v] + lk)
                       : make_float4(0.f, 0.f, 0.f, 0.f);
            rb[v] = ok ? *(const float4*)(bRow[v] + lk)
                       : make_float4(0.f, 0.f, 0.f, 0.f);
        }
#pragma unroll
        for (int v = 0; v < 2; v++) {
            As[0][row0    ][cA[v]] = f2h2(ra[v].x, ra[v].y);
            As[0][row0 + 1][cA[v]] = f2h2(ra[v].z, ra[v].w);
            Bs[0][row0    ][cB[v]] = f2h2(rb[v].x, rb[v].y);
            Bs[0][row0 + 1][cB[v]] = f2h2(rb[v].z, rb[v].w);
        }
        if (ktiles > 1) {
            int kg = TBK + lk;
            bool ok1 = (kg < KK);
#pragma unroll
            for (int v = 0; v < 2; v++) {
                ra[v] = ok1 ? *(const float4*)(aRow[v] + kg)
                            : make_float4(0.f, 0.f, 0.f, 0.f);
                rb[v] = ok1 ? *(const float4*)(bRow[v] + kg)
                            : make_float4(0.f, 0.f, 0.f, 0.f);
            }
        }
    }
    __syncthreads();

    for (int kt = 0; kt < ktiles; kt++) {
        if (kt + 1 < ktiles) {
            const int st = (kt + 1) & 1;
#pragma unroll
            for (int v = 0; v < 2; v++) {
                As[st][row0    ][cA[v]] = f2h2(ra[v].x, ra[v].y);
                As[st][row0 + 1][cA[v]] = f2h2(ra[v].z, ra[v].w);
                Bs[st][row0    ][cB[v]] = f2h2(rb[v].x, rb[v].y);
                Bs[st][row0 + 1][cB[v]] = f2h2(rb[v].z, rb[v].w);
            }
        }
        if (kt + 2 < ktiles) {
            int kg = (kt + 2) * TBK + lk;
            bool ok = (kg < KK);
#pragma unroll
            for (int v = 0; v < 2; v++) {
                ra[v] = ok ? *(const float4*)(aRow[v] + kg)
                           : make_float4(0.f, 0.f, 0.f, 0.f);
                rb[v] = ok ? *(const float4*)(bRow[v] + kg)
                           : make_float4(0.f, 0.f, 0.f, 0.f);
            }
        }
        {
            const int st = kt & 1;
            uint2 bfr[4];
#pragma unroll
            for (int ni = 0; ni < 4; ni++)
                bfr[ni] = *(const uint2*)&Bs[st][c][(wn * 32 + ni * 8 + g) * 2];
#pragma unroll
            for (int mi = 0; mi < 4; mi++) {
                uint4 av = *(const uint4*)&As[st][c][(wm * 4 + mi) * 32 + g * 4];
#pragma unroll
                for (int ni = 0; ni < 4; ni++)
                    mma_f16(acc[mi][ni], av.x, av.y, av.z, av.w,
                            bfr[ni].x, bfr[ni].y);
            }
        }
        if (kt + 1 < ktiles) __syncthreads();
    }

#pragma unroll
    for (int mi = 0; mi < 4; mi++) {
#pragma unroll
        for (int ni = 0; ni < 4; ni++) {
            int row = bm + wm * 64 + mi * 16 + g;
            int col = bn + wn * 32 + ni * 8 + c * 2;
            *(float2*)(Cmat + (size_t)row * N + col) =
                make_float2(acc[mi][ni][0], acc[mi][ni][1]);
            *(float2*)(Cmat + (size_t)(row + 8) * N + col) =
                make_float2(acc[mi][ni][2], acc[mi][ni][3]);
        }
    }
}

// ---------------------------------------------------------------------------
// FP32 conv-as-GEMM (small Emotient GEMM)
// ---------------------------------------------------------------------------
template<int BM, int BN, int BK, int TM, int TN>
__global__ __launch_bounds__(256)
void conv_gemm_kernel(size_t xOff, size_t wOff, size_t cOff,
                      int M, int N, int KK,
                      int Wout, int rowStride, int btStride)
{
    static_assert((BM / TM) * (BN / TN) == 256, "256 threads");
    constexpr int A_VECS = BM * BK / (256 * 4);
    constexpr int B_VECS = BN * BK / (256 * 4);

    const float* X    = g_scratch + xOff;
    const float* Wt   = g_scratch + wOff;
    float*       Cmat = g_scratch + cOff;

    __shared__ __align__(16) float As[BK][BM + 4];
    __shared__ __align__(16) float Bs[BK][BN + 4];

    const int tid = threadIdx.x;
    const int bm  = blockIdx.x * BM;
    const int bn  = blockIdx.y * BN;
    const int lr = tid >> 2;
    const int lk = (tid & 3) * 4;

    const float* aRow[A_VECS];
#pragma unroll
    for (int v = 0; v < A_VECS; v++) {
        int m  = bm + lr + v * 64;
        int bt = m / Wout;
        int t  = m - bt * Wout;
        aRow[v] = X + (size_t)bt * btStride + (size_t)t * rowStride;
    }
    const float* bRow[B_VECS];
#pragma unroll
    for (int v = 0; v < B_VECS; v++) {
        int n = bn + lr + v * 64;
        bRow[v] = Wt + (size_t)n * KK;
    }

    float acc[TM][TN];
#pragma unroll
    for (int i = 0; i < TM; i++)
#pragma unroll
        for (int j = 0; j < TN; j++) acc[i][j] = 0.f;

    const int ty = tid / (BN / TN);
    const int tx = tid % (BN / TN);

    for (int k0 = 0; k0 < KK; k0 += BK) {
        int kg = k0 + lk;
        bool ok = (kg < KK);
#pragma unroll
        for (int v = 0; v < A_VECS; v++) {
            float4 a = ok ? *(const float4*)(aRow[v] + kg)
                          : make_float4(0.f, 0.f, 0.f, 0.f);
            int mr = lr + v * 64;
            As[lk + 0][mr] = a.x; As[lk + 1][mr] = a.y;
            As[lk + 2][mr] = a.z; As[lk + 3][mr] = a.w;
        }
#pragma unroll
        for (int v = 0; v < B_VECS; v++) {
            float4 b = ok ? *(const float4*)(bRow[v] + kg)
                          : make_float4(0.f, 0.f, 0.f, 0.f);
            int nr = lr + v * 64;
            Bs[lk + 0][nr] = b.x; Bs[lk + 1][nr] = b.y;
            Bs[lk + 2][nr] = b.z; Bs[lk + 3][nr] = b.w;
        }
        __syncthreads();

#pragma unroll
        for (int kk = 0; kk < BK; kk++) {
            float a[TM], b[TN];
#pragma unroll
            for (int i = 0; i < TM; i += 4) {
                float4 v = *(const float4*)&As[kk][ty * TM + i];
                a[i] = v.x; a[i + 1] = v.y; a[i + 2] = v.z; a[i + 3] = v.w;
            }
#pragma unroll
            for (int j = 0; j < TN; j += 4) {
                float4 v = *(const float4*)&Bs[kk][tx * TN + j];
                b[j] = v.x; b[j + 1] = v.y; b[j + 2] = v.z; b[j + 3] = v.w;
            }
#pragma unroll
            for (int i = 0; i < TM; i++)
#pragma unroll
                for (int j = 0; j < TN; j++)
                    acc[i][j] = fmaf(a[i], b[j], acc[i][j]);
        }
        __syncthreads();
    }

#pragma unroll
    for (int i = 0; i < TM; i++) {
        size_t m = (size_t)bm + ty * TM + i;
        float* cp = Cmat + m * (size_t)N + bn + tx * TN;
#pragma unroll
        for (int j = 0; j < TN; j += 4) {
            float4 v = make_float4(acc[i][j], acc[i][j + 1],
                                   acc[i][j + 2], acc[i][j + 3]);
            *(float4*)(cp + j) = v;
        }
    }
}

// ---------------------------------------------------------------------------
// Masked LSTM: 16 sequences per block (round-14, passed)
// ---------------------------------------------------------------------------
#define SEQS 16
__device__ __forceinline__ float sigf(float x) { return 1.f / (1.f + expf(-x)); }

#define LSTM_SMEM_FLOATS (SEQS*HH_ + SEQS*HH_ + SEQS*EE_ + 512*(SEQS+1) + SEQS)
#define LSTM_SMEM_BYTES  (LSTM_SMEM_FLOATS * 4)

__global__ __launch_bounds__(512)
void lstm_kernel(const float* __restrict__ xe,
                 const int*   __restrict__ wlen,
                 const float* __restrict__ bih,
                 const float* __restrict__ bhh)
{
    const float* WihT = g_scratch + OFF_WIHT;
    const float* WhhT = g_scratch + OFF_WHHT;
    float*       hbuf = g_scratch + OFF_HBUF;

    extern __shared__ float sm[];
    float* sh   = sm;
    float* sc   = sh + SEQS * HH_;
    float* sx   = sc + SEQS * HH_;
    float* sz   = sx + SEQS * EE_;
    int*   slen = (int*)(sz + 512 * (SEQS + 1));

    const int tid = threadIdx.x;
    const int bt0 = blockIdx.x * SEQS;

    for (int i = tid; i < SEQS * HH_; i += 512) {
        sh[i] = 0.f;
        sc[i] = 0.f;
    }
    if (tid < SEQS) slen[tid] = wlen[bt0 + tid];
    __syncthreads();

    const int r = tid;
    const float bias = bih[r] + bhh[r];

    for (int t = 0; t < WE_; t++) {
        for (int i = tid; i < SEQS * EE_; i += 512) {
            int s = i / EE_, e = i - s * EE_;
            sx[s * EE_ + e] = xe[(size_t)(bt0 + s) * (WE_ * EE_) + t * EE_ + e];
        }
        __syncthreads();

        float acc[SEQS];
#pragma unroll
        for (int s = 0; s < SEQS; s++) acc[s] = bias;
#pragma unroll
        for (int e = 0; e < EE_; e++) {
            float w = WihT[e * 512 + r];
#pragma unroll
            for (int s = 0; s < SEQS; s++) acc[s] = fmaf(w, sx[s * EE_ + e], acc[s]);
        }
#pragma unroll 4
        for (int j = 0; j < HH_; j++) {
            float w = WhhT[j * 512 + r];
#pragma unroll
            for (int s = 0; s < SEQS; s++) acc[s] = fmaf(w, sh[s * HH_ + j], acc[s]);
        }
#pragma unroll
        for (int s = 0; s < SEQS; s++) sz[r * (SEQS + 1) + s] = acc[s];
        __syncthreads();

#pragma unroll
        for (int p = tid; p < SEQS * HH_; p += 512) {
            int s = p & (SEQS - 1);
            int j = p >> 4;
            float zi = sz[j * (SEQS + 1) + s];
            float zf = sz[(HH_ + j) * (SEQS + 1) + s];
            float zg = sz[(2 * HH_ + j) * (SEQS + 1) + s];
            float zo = sz[(3 * HH_ + j) * (SEQS + 1) + s];
            float cc = sc[s * HH_ + j];
            float cn = sigf(zf) * cc + sigf(zi) * tanhf(zg);
            float hn = sigf(zo) * tanhf(cn);
            bool valid = (t < slen[s]);
            sc[s * HH_ + j] = valid ? cn : cc;
            sh[s * HH_ + j] = valid ? hn : sh[s * HH_ + j];
            hbuf[(size_t)(bt0 + s) * (WE_ * HH_) + t * HH_ + j] = valid ? hn : 0.f;
        }
        __syncthreads();
    }
}

// ---------------------------------------------------------------------------
// Fused maxpool + highway, 8 bt-rows per block (round-14, passed)
// ---------------------------------------------------------------------------
#define BTB 8
__global__ void pool_highway_kernel(size_t cOff, int N, int Wout,
                                    const float* __restrict__ convB,
                                    size_t wpOff, const float* __restrict__ bp,
                                    size_t wgOff, const float* __restrict__ bg,
                                    float* __restrict__ out, int outOff)
{
    extern __shared__ float sy[];
    const float* Cmat = g_scratch + cOff;
    const float* WpT  = g_scratch + wpOff;
    const float* WgT  = g_scratch + wgOff;

    const int bt0 = blockIdx.x * BTB;
    const int co  = threadIdx.x;
    const float cb = convB[co];

#pragma unroll
    for (int b = 0; b < BTB; b++) {
        const float* cp = Cmat + (size_t)(bt0 + b) * Wout * N + co;
        float y = cp[0];
        for (int t = 1; t < Wout; t++) y = fmaxf(y, cp[(size_t)t * N]);
        sy[b * N + co] = y + cb;
    }
    __syncthreads();

    float ap[BTB], ag[BTB];
    const float bpc = bp[co], bgc = bg[co];
#pragma unroll
    for (int b = 0; b < BTB; b++) { ap[b] = bpc; ag[b] = bgc; }

    for (int j = 0; j < N; j++) {
        float wp = WpT[j * N + co];
        float wg = WgT[j * N + co];
#pragma unroll
        for (int b = 0; b < BTB; b++) {
            float yj = sy[b * N + j];
            ap[b] = fmaf(wp, yj, ap[b]);
            ag[b] = fmaf(wg, yj, ag[b]);
        }
    }
#pragma unroll
    for (int b = 0; b < BTB; b++) {
        float p  = fmaxf(ap[b], 0.f);
        float gg = 1.f / (1.f + expf(-ag[b]));
        float y  = sy[b * N + co];
        out[(size_t)(bt0 + b) * OUTW_ + outOff + co] = gg * p + (1.f - gg) * y;
    }
}

// ---------------------------------------------------------------------------
// Launch
// ---------------------------------------------------------------------------
extern "C" void kernel_launch(void* const* d_in, const int* in_sizes, int n_in,
                              void* d_out, int out_size)
{
    (void)in_sizes; (void)n_in; (void)out_size;
    const float* x_lin   = (const float*)d_in[0];
    const float* x_aco   = (const float*)d_in[1];
    const float* x_emo   = (const float*)d_in[2];
    const int*   wlen    = (const int*)  d_in[3];
    const float* convL_w = (const float*)d_in[5];
    const float* convL_b = (const float*)d_in[6];
    const float* convA_w = (const float*)d_in[7];
    const float* convA_b = (const float*)d_in[8];
    const float* convE_w = (const float*)d_in[9];
    const float* convE_b = (const float*)d_in[10];
    const float* hwL_Wp  = (const float*)d_in[11];
    const float* hwL_bp  = (const float*)d_in[12];
    const float* hwL_Wg  = (const float*)d_in[13];
    const float* hwL_bg  = (const float*)d_in[14];
    const float* hwA_Wp  = (const float*)d_in[15];
    const float* hwA_bp  = (const float*)d_in[16];
    const float* hwA_Wg  = (const float*)d_in[17];
    const float* hwA_bg  = (const float*)d_in[18];
    const float* hwE_Wp  = (const float*)d_in[19];
    const float* hwE_bp  = (const float*)d_in[20];
    const float* hwE_Wg  = (const float*)d_in[21];
    const float* hwE_bg  = (const float*)d_in[22];
    const float* Wih     = (const float*)d_in[23];
    const float* Whh     = (const float*)d_in[24];
    const float* bih     = (const float*)d_in[25];
    const float* bhh     = (const float*)d_in[26];
    float* out = (float*)d_out;

    cudaFuncSetAttribute(lstm_kernel,
                         cudaFuncAttributeMaxDynamicSharedMemorySize,
                         LSTM_SMEM_BYTES);
    cudaFuncSetAttribute(conv_gemm_f16_wide,
                         cudaFuncAttributeMaxDynamicSharedMemorySize,
                         WIDE_SMEM_BYTES);

    // 1-3: conv weight permutes
    permute_w_kernel<<<(CA_ * EA_ * KA_ + 255) / 256, 256>>>(convA_w, OFF_WAT, CA_, EA_, KA_);
    permute_w_kernel<<<(CL_ * EL_ * KL_ + 255) / 256, 256>>>(convL_w, OFF_WLT, CL_, EL_, KL_);
    permute_w_kernel<<<(CE_ * HH_ * KE_ + 255) / 256, 256>>>(convE_w, OFF_WET, CE_, HH_, KE_);

    // 4: acoustic GEMM — WIDE double-pumped (profiled launch)
    conv_gemm_f16_wide<<<dim3(1, MA_ / TBM), 512, WIDE_SMEM_BYTES>>>(
        x_aco, OFF_WAT, OFF_CA, KKA_, WOA_, EA_, WA_ * EA_);

    // 5: linguistic GEMM (proven 256-thread kernel)
    conv_gemm_f16_kernel<<<dim3(CL_ / TBN, ML_ / TBM), 256>>>(
        x_lin, OFF_WLT, OFF_CL, CL_, KKL_, WOL_, EL_, WL_ * EL_);

    // 6-7: LSTM weight transposes
    transpose2d_kernel<<<(512 * EE_ + 255) / 256, 256>>>(Wih, OFF_WIHT, 512, EE_);
    transpose2d_kernel<<<(512 * HH_ + 255) / 256, 256>>>(Whh, OFF_WHHT, 512, HH_);

    // 8: LSTM (-> hbuf), 16 seqs/block
    lstm_kernel<<<BT_ / SEQS, 512, LSTM_SMEM_BYTES>>>(x_emo, wlen, bih, bhh);

    // 9: emotient GEMM (fp32, input = hbuf)
    conv_gemm_kernel<128, 64, 16, 8, 4><<<dim3(ME_ / 128, CE_ / 64), 256>>>(
        OFF_HBUF, OFF_WET, OFF_CE, ME_, CE_, KKE_, WOE_, HH_, WE_ * HH_);

    // 10-15: highway weight transposes
    transpose2d_kernel<<<(CL_ * CL_ + 255) / 256, 256>>>(hwL_Wp, OFF_HWLPT, CL_, CL_);
    transpose2d_kernel<<<(CL_ * CL_ + 255) / 256, 256>>>(hwL_Wg, OFF_HWLGT, CL_, CL_);
    transpose2d_kernel<<<(CA_ * CA_ + 255) / 256, 256>>>(hwA_Wp, OFF_HWAPT, CA_, CA_);
    transpose2d_kernel<<<(CA_ * CA_ + 255) / 256, 256>>>(hwA_Wg, OFF_HWAGT, CA_, CA_);
    transpose2d_kernel<<<(CE_ * CE_ + 255) / 256, 256>>>(hwE_Wp, OFF_HWEPT, CE_, CE_);
    transpose2d_kernel<<<(CE_ * CE_ + 255) / 256, 256>>>(hwE_Wg, OFF_HWEGT, CE_, CE_);

    // 16-18: fused maxpool + highway -> output
    pool_highway_kernel<<<BT_ / BTB, CL_, BTB * CL_ * sizeof(float)>>>(
        OFF_CL, CL_, WOL_, convL_b, OFF_HWLPT, hwL_bp, OFF_HWLGT, hwL_bg, out, 0);
    pool_highway_kernel<<<BT_ / BTB, CA_, BTB * CA_ * sizeof(float)>>>(
        OFF_CA, CA_, WOA_, convA_b, OFF_HWAPT, hwA_bp, OFF_HWAGT, hwA_bg, out, CL_);
    pool_highway_kernel<<<BT_ / BTB, CE_, BTB * CE_ * sizeof(float)>>>(
        OFF_CE, CE_, WOE_, convE_b, OFF_HWEPT, hwE_bp, OFF_HWEGT, hwE_bg, out, CL_ + CA_);
}

// round 17
// speedup vs baseline: 3.6507x; 1.0120x over previous
#include <cuda_runtime.h>
#include <cuda_fp16.h>
#include <math.h>
#include <stdint.h>

// ---------------------------------------------------------------------------
// Problem dimensions
// ---------------------------------------------------------------------------
#define BT_   1536
#define WL_   33
#define WA_   50
#define WE_   30
#define EL_   300
#define EA_   988
#define EE_   20
#define HH_   128
#define CL_   128
#define CA_   256
#define CE_   64
#define KL_   5
#define KA_   10
#define KE_   3
#define WOL_  (WL_ - KL_ + 1)      // 29
#define WOA_  (WA_ - KA_ + 1)      // 41
#define WOE_  (WE_ - KE_ + 1)      // 28
#define ML_   (BT_ * WOL_)         // 44544
#define MA_   (BT_ * WOA_)         // 62976
#define ME_   (BT_ * WOE_)         // 43008
#define KKL_  (KL_ * EL_)          // 1500
#define KKA_  (KA_ * EA_)          // 9880
#define KKE_  (KE_ * HH_)          // 384
#define OUTW_ 448

// ---------------------------------------------------------------------------
// Device scratch — EXACT proven 134 MB layout
// ---------------------------------------------------------------------------
#define OFF_CA     ((size_t)0)
#define OFF_CL     ((size_t)16121856)
#define OFF_CE     ((size_t)21823488)
#define OFF_HBUF   ((size_t)24576000)
#define OFF_WAT    ((size_t)30474240)
#define OFF_WLT    ((size_t)33003520)
#define OFF_WET    ((size_t)33195520)
#define OFF_WIHT   ((size_t)33220096)
#define OFF_WHHT   ((size_t)33230336)
#define OFF_HWLPT  ((size_t)33295872)
#define OFF_HWLGT  ((size_t)33312256)
#define OFF_HWAPT  ((size_t)33328640)
#define OFF_HWAGT  ((size_t)33394176)
#define OFF_HWEPT  ((size_t)33459712)
#define OFF_HWEGT  ((size_t)33463808)
#define SCRATCH_TOTAL ((size_t)33467904)

__device__ __align__(16) float g_scratch[SCRATCH_TOTAL];

// ---------------------------------------------------------------------------
// Weight permute: (Cout, Cin, K) -> (Cout, K, Cin)
// ---------------------------------------------------------------------------
__global__ void permute_w_kernel(const float* __restrict__ src, size_t dstOff,
                                 int Cout, int Cin, int K)
{
    int idx = blockIdx.x * 256 + threadIdx.x;
    int tot = Cout * Cin * K;
    if (idx >= tot) return;
    float* dst = g_scratch + dstOff;
    int ci = idx % Cin;
    int r  = idx / Cin;
    int k  = r % K;
    int co = r / K;
    dst[idx] = src[(size_t)co * Cin * K + (size_t)ci * K + k];
}

// 2D transpose: src (R x C) -> dst (C x R)
__global__ void transpose2d_kernel(const float* __restrict__ src, size_t dstOff,
                                   int R, int C)
{
    int idx = blockIdx.x * 256 + threadIdx.x;
    int tot = R * C;
    if (idx >= tot) return;
    float* dst = g_scratch + dstOff;
    int r = idx % R;
    int c = idx / R;
    dst[idx] = src[(size_t)r * C + c];
}

// ---------------------------------------------------------------------------
// Shared HMMA helpers
// ---------------------------------------------------------------------------
__device__ __forceinline__ uint32_t f2h2(float lo, float hi) {
    __half2 h = __floats2half2_rn(lo, hi);
    return *(uint32_t*)&h;
}

__device__ __forceinline__ void mma_f16(float c[4], uint32_t a0, uint32_t a1,
                                        uint32_t a2, uint32_t a3,
                                        uint32_t b0, uint32_t b1) {
    asm volatile(
        "mma.sync.aligned.m16n8k16.row.col.f32.f16.f16.f32 "
        "{%0,%1,%2,%3}, {%4,%5,%6,%7}, {%8,%9}, {%0,%1,%2,%3};"
        : "+f"(c[0]), "+f"(c[1]), "+f"(c[2]), "+f"(c[3])
        : "r"(a0), "r"(a1), "r"(a2), "r"(a3), "r"(b0), "r"(b1));
}

#define TBM 128
#define TBK 16
#define ASTR 264
#define BSTR 520

// ---------------------------------------------------------------------------
// WIDE fp16 HMMA conv-as-GEMM, double-pumped  [BYTE-IDENTICAL to round 16]
// ---------------------------------------------------------------------------
#define WIDE_SMEM_BYTES ((2*8*ASTR + 2*8*BSTR) * 4)

__global__ __launch_bounds__(512)
void conv_gemm_f16_wide(const float* __restrict__ X,
                        size_t wOff, size_t cOff,
                        int KK, int Wout, int rowStride, int btStride)
{
    extern __shared__ __align__(16) uint32_t dsm[];
    uint32_t* AsB = dsm;
    uint32_t* BsB = dsm + 2 * 8 * ASTR;

    const float* Wt   = g_scratch + wOff;
    float*       Cmat = g_scratch + cOff;

    const int tid  = threadIdx.x;
    const int bm   = blockIdx.y * TBM;
    const int wid  = tid >> 5;
    const int lane = tid & 31;
    const int wm   = wid & 1;
    const int wn   = wid >> 1;
    const int g    = lane >> 2;
    const int c    = lane & 3;

    const int lr   = tid >> 2;
    const int lk   = (tid & 3) * 4;
    const int hb   = (tid & 3) >> 1;
    const int row0 = ((tid & 3) * 2) & 3;

    const float* aRow;
    {
        int m  = bm + lr;
        int bt = m / Wout;
        int t  = m - bt * Wout;
        aRow = X + (size_t)bt * btStride + (size_t)t * rowStride;
    }
    const int cA0 = ((lr >> 4) * 32) + ((lr & 7) * 4) + hb * 2 + ((lr & 15) >> 3);

    const float* bRow[2];
    int cB[2];
#pragma unroll
    for (int v = 0; v < 2; v++) {
        bRow[v] = Wt + (size_t)(lr + v * 128) * KK;
        cB[v]   = (lr + v * 128) * 2 + hb;
    }

    float acc[4][4][4];
#pragma unroll
    for (int mi = 0; mi < 4; mi++)
#pragma unroll
        for (int ni = 0; ni < 4; ni++)
#pragma unroll
            for (int q = 0; q < 4; q++) acc[mi][ni][q] = 0.f;

    float4 ra, rb[2];
    const int ktiles = (KK + 31) / 32;

#define LOADCHUNK(kbase)                                                     \
    do {                                                                     \
        int kg = (kbase) + lk;                                               \
        bool ok = (kg < KK);                                                 \
        ra = ok ? *(const float4*)(aRow + kg)                                \
                : make_float4(0.f, 0.f, 0.f, 0.f);                           \
        rb[0] = ok ? *(const float4*)(bRow[0] + kg)                          \
                   : make_float4(0.f, 0.f, 0.f, 0.f);                        \
        rb[1] = ok ? *(const float4*)(bRow[1] + kg)                          \
                   : make_float4(0.f, 0.f, 0.f, 0.f);                        \
    } while (0)

#define STSCHUNK(st, q)                                                      \
    do {                                                                     \
        uint32_t* Ad = AsB + ((st) * 8 + (q) * 4 + row0) * ASTR + cA0;       \
        Ad[0]    = f2h2(ra.x, ra.y);                                         \
        Ad[ASTR] = f2h2(ra.z, ra.w);                                         \
        uint32_t* Bd = BsB + ((st) * 8 + (q) * 4 + row0) * BSTR;             \
        Bd[cB[0]]        = f2h2(rb[0].x, rb[0].y);                           \
        Bd[BSTR + cB[0]] = f2h2(rb[0].z, rb[0].w);                           \
        Bd[cB[1]]        = f2h2(rb[1].x, rb[1].y);                           \
        Bd[BSTR + cB[1]] = f2h2(rb[1].z, rb[1].w);                           \
    } while (0)

#define COMPUTE16(st, q)                                                     \
    do {                                                                     \
        const uint32_t* Ar = AsB + ((st) * 8 + (q) * 4 + c) * ASTR;          \
        const uint32_t* Br = BsB + ((st) * 8 + (q) * 4 + c) * BSTR;          \
        uint2 bfr[4];                                                        \
        _Pragma("unroll")                                                    \
        for (int ni = 0; ni < 4; ni++)                                       \
            bfr[ni] = *(const uint2*)&Br[(wn * 32 + ni * 8 + g) * 2];        \
        _Pragma("unroll")                                                    \
        for (int mi = 0; mi < 4; mi++) {                                     \
            uint4 av = *(const uint4*)&Ar[(wm * 4 + mi) * 32 + g * 4];       \
            _Pragma("unroll")                                                \
            for (int ni = 0; ni < 4; ni++)                                   \
                mma_f16(acc[mi][ni], av.x, av.y, av.z, av.w,                 \
                        bfr[ni].x, bfr[ni].y);                               \
        }                                                                    \
    } while (0)

    LOADCHUNK(0);
    STSCHUNK(0, 0);
    LOADCHUNK(16);
    STSCHUNK(0, 1);
    if (ktiles > 1) LOADCHUNK(32);
    __syncthreads();

    for (int kt = 0; kt < ktiles; kt++) {
        const int stc = kt & 1;
        const int stn = (kt + 1) & 1;
        const bool more = (kt + 1 < ktiles);

        if (more) STSCHUNK(stn, 0);
        if (more) LOADCHUNK((kt + 1) * 32 + 16);
        COMPUTE16(stc, 0);
        if (more) STSCHUNK(stn, 1);
        if (kt + 2 < ktiles) LOADCHUNK((kt + 2) * 32);
        COMPUTE16(stc, 1);
        if (more) __syncthreads();
    }

#undef LOADCHUNK
#undef STSCHUNK
#undef COMPUTE16

#pragma unroll
    for (int mi = 0; mi < 4; mi++) {
#pragma unroll
        for (int ni = 0; ni < 4; ni++) {
            int row = bm + wm * 64 + mi * 16 + g;
            int col = wn * 32 + ni * 8 + c * 2;
            *(float2*)(Cmat + (size_t)row * CA_ + col) =
                make_float2(acc[mi][ni][0], acc[mi][ni][1]);
            *(float2*)(Cmat + (size_t)(row + 8) * CA_ + col) =
                make_float2(acc[mi][ni][2], acc[mi][ni][3]);
        }
    }
}

// ---------------------------------------------------------------------------
// 256-thread fp16 HMMA conv-as-GEMM — proven (for gemmL)
// ---------------------------------------------------------------------------
#define TBN 128

__global__ __launch_bounds__(256, 2)
void conv_gemm_f16_kernel(const float* __restrict__ X,
                          size_t wOff, size_t cOff,
                          int N, int KK,
                          int Wout, int rowStride, int btStride)
{
    __shared__ __align__(16) uint32_t As[2][4][ASTR];
    __shared__ __align__(16) uint32_t Bs[2][4][ASTR];

    const float* Wt   = g_scratch + wOff;
    float*       Cmat = g_scratch + cOff;

    const int tid  = threadIdx.x;
    const int bm   = blockIdx.y * TBM;
    const int bn   = blockIdx.x * TBN;
    const int wid  = tid >> 5;
    const int lane = tid & 31;
    const int wm   = wid & 1;
    const int wn   = wid >> 1;
    const int g    = lane >> 2;
    const int c    = lane & 3;

    const int lr   = tid >> 2;
    const int lk   = (tid & 3) * 4;
    const int hb   = (tid & 3) >> 1;
    const int row0 = ((tid & 3) * 2) & 3;

    const float* aRow[2];
    const float* bRow[2];
    int cA[2], cB[2];
#pragma unroll
    for (int v = 0; v < 2; v++) {
        int mr = lr + v * 64;
        int m  = bm + mr;
        int bt = m / Wout;
        int t  = m - bt * Wout;
        aRow[v] = X + (size_t)bt * btStride + (size_t)t * rowStride;
        int q = mr >> 4, r = mr & 15;
        cA[v] = q * 32 + (r & 7) * 4 + hb * 2 + (r >> 3);
        cB[v] = mr * 2 + hb;
        bRow[v] = Wt + (size_t)(bn + mr) * KK;
    }

    float acc[4][4][4];
#pragma unroll
    for (int mi = 0; mi < 4; mi++)
#pragma unroll
        for (int ni = 0; ni < 4; ni++)
#pragma unroll
            for (int q = 0; q < 4; q++) acc[mi][ni][q] = 0.f;

    float4 ra[2], rb[2];
    const int ktiles = (KK + TBK - 1) / TBK;

    {
        bool ok = (lk < KK);
#pragma unroll
        for (int v = 0; v < 2; v++) {
            ra[v] = ok ? *(const float4*)(aRow[v] + lk)
                       : make_float4(0.f, 0.f, 0.f, 0.f);
            rb[v] = ok ? *(const float4*)(bRow[v] + lk)
                       : make_float4(0.f, 0.f, 0.f, 0.f);
        }
#pragma unroll
        for (int v = 0; v < 2; v++) {
            As[0][row0    ][cA[v]] = f2h2(ra[v].x, ra[v].y);
            As[0][row0 + 1][cA[v]] = f2h2(ra[v].z, ra[v].w);
            Bs[0][row0    ][cB[v]] = f2h2(rb[v].x, rb[v].y);
            Bs[0][row0 + 1][cB[v]] = f2h2(rb[v].z, rb[v].w);
        }
        if (ktiles > 1) {
            int kg = TBK + lk;
            bool ok1 = (kg < KK);
#pragma unroll
            for (int v = 0; v < 2; v++) {
                ra[v] = ok1 ? *(const float4*)(aRow[v] + kg)
                            : make_float4(0.f, 0.f, 0.f, 0.f);
                rb[v] = ok1 ? *(const float4*)(bRow[v] + kg)
                            : make_float4(0.f, 0.f, 0.f, 0.f);
            }
        }
    }
    __syncthreads();

    for (int kt = 0; kt < ktiles; kt++) {
        if (kt + 1 < ktiles) {
            const int st = (kt + 1) & 1;
#pragma unroll
            for (int v = 0; v < 2; v++) {
                As[st][row0    ][cA[v]] = f2h2(ra[v].x, ra[v].y);
                As[st][row0 + 1][cA[v]] = f2h2(ra[v].z, ra[v].w);
                Bs[st][row0    ][cB[v]] = f2h2(rb[v].x, rb[v].y);
                Bs[st][row0 + 1][cB[v]] = f2h2(rb[v].z, rb[v].w);
            }
        }
        if (kt + 2 < ktiles) {
            int kg = (kt + 2) * TBK + lk;
            bool ok = (kg < KK);
#pragma unroll
            for (int v = 0; v < 2; v++) {
                ra[v] = ok ? *(const float4*)(aRow[v] + kg)
                           : make_float4(0.f, 0.f, 0.f, 0.f);
                rb[v] = ok ? *(const float4*)(bRow[v] + kg)
                           : make_float4(0.f, 0.f, 0.f, 0.f);
            }
        }
        {
            const int st = kt & 1;
            uint2 bfr[4];
#pragma unroll
            for (int ni = 0; ni < 4; ni++)
                bfr[ni] = *(const uint2*)&Bs[st][c][(wn * 32 + ni * 8 + g) * 2];
#pragma unroll
            for (int mi = 0; mi < 4; mi++) {
                uint4 av = *(const uint4*)&As[st][c][(wm * 4 + mi) * 32 + g * 4];
#pragma unroll
                for (int ni = 0; ni < 4; ni++)
                    mma_f16(acc[mi][ni], av.x, av.y, av.z, av.w,
                            bfr[ni].x, bfr[ni].y);
            }
        }
        if (kt + 1 < ktiles) __syncthreads();
    }

#pragma unroll
    for (int mi = 0; mi < 4; mi++) {
#pragma unroll
        for (int ni = 0; ni < 4; ni++) {
            int row = bm + wm * 64 + mi * 16 + g;
            int col = bn + wn * 32 + ni * 8 + c * 2;
            *(float2*)(Cmat + (size_t)row * N + col) =
                make_float2(acc[mi][ni][0], acc[mi][ni][1]);
            *(float2*)(Cmat + (size_t)(row + 8) * N + col) =
                make_float2(acc[mi][ni][2], acc[mi][ni][3]);
        }
    }
}

// ---------------------------------------------------------------------------
// FP32 conv-as-GEMM (small Emotient GEMM)
// ---------------------------------------------------------------------------
template<int BM, int BN, int BK, int TM, int TN>
__global__ __launch_bounds__(256)
void conv_gemm_kernel(size_t xOff, size_t wOff, size_t cOff,
                      int M, int N, int KK,
                      int Wout, int rowStride, int btStride)
{
    static_assert((BM / TM) * (BN / TN) == 256, "256 threads");
    constexpr int A_VECS = BM * BK / (256 * 4);
    constexpr int B_VECS = BN * BK / (256 * 4);

    const float* X    = g_scratch + xOff;
    const float* Wt   = g_scratch + wOff;
    float*       Cmat = g_scratch + cOff;

    __shared__ __align__(16) float As[BK][BM + 4];
    __shared__ __align__(16) float Bs[BK][BN + 4];

    const int tid = threadIdx.x;
    const int bm  = blockIdx.x * BM;
    const int bn  = blockIdx.y * BN;
    const int lr = tid >> 2;
    const int lk = (tid & 3) * 4;

    const float* aRow[A_VECS];
#pragma unroll
    for (int v = 0; v < A_VECS; v++) {
        int m  = bm + lr + v * 64;
        int bt = m / Wout;
        int t  = m - bt * Wout;
        aRow[v] = X + (size_t)bt * btStride + (size_t)t * rowStride;
    }
    const float* bRow[B_VECS];
#pragma unroll
    for (int v = 0; v < B_VECS; v++) {
        int n = bn + lr + v * 64;
        bRow[v] = Wt + (size_t)n * KK;
    }

    float acc[TM][TN];
#pragma unroll
    for (int i = 0; i < TM; i++)
#pragma unroll
        for (int j = 0; j < TN; j++) acc[i][j] = 0.f;

    const int ty = tid / (BN / TN);
    const int tx = tid % (BN / TN);

    for (int k0 = 0; k0 < KK; k0 += BK) {
        int kg = k0 + lk;
        bool ok = (kg < KK);
#pragma unroll
        for (int v = 0; v < A_VECS; v++) {
            float4 a = ok ? *(const float4*)(aRow[v] + kg)
                          : make_float4(0.f, 0.f, 0.f, 0.f);
            int mr = lr + v * 64;
            As[lk + 0][mr] = a.x; As[lk + 1][mr] = a.y;
            As[lk + 2][mr] = a.z; As[lk + 3][mr] = a.w;
        }
#pragma unroll
        for (int v = 0; v < B_VECS; v++) {
            float4 b = ok ? *(const float4*)(bRow[v] + kg)
                          : make_float4(0.f, 0.f, 0.f, 0.f);
            int nr = lr + v * 64;
            Bs[lk + 0][nr] = b.x; Bs[lk + 1][nr] = b.y;
            Bs[lk + 2][nr] = b.z; Bs[lk + 3][nr] = b.w;
        }
        __syncthreads();

#pragma unroll
        for (int kk = 0; kk < BK; kk++) {
            float a[TM], b[TN];
#pragma unroll
            for (int i = 0; i < TM; i += 4) {
                float4 v = *(const float4*)&As[kk][ty * TM + i];
                a[i] = v.x; a[i + 1] = v.y; a[i + 2] = v.z; a[i + 3] = v.w;
            }
#pragma unroll
            for (int j = 0; j < TN; j += 4) {
                float4 v = *(const float4*)&Bs[kk][tx * TN + j];
                b[j] = v.x; b[j + 1] = v.y; b[j + 2] = v.z; b[j + 3] = v.w;
            }
#pragma unroll
            for (int i = 0; i < TM; i++)
#pragma unroll
                for (int j = 0; j < TN; j++)
                    acc[i][j] = fmaf(a[i], b[j], acc[i][j]);
        }
        __syncthreads();
    }

#pragma unroll
    for (int i = 0; i < TM; i++) {
        size_t m = (size_t)bm + ty * TM + i;
        float* cp = Cmat + m * (size_t)N + bn + tx * TN;
#pragma unroll
        for (int j = 0; j < TN; j += 4) {
            float4 v = make_float4(acc[i][j], acc[i][j + 1],
                                   acc[i][j + 2], acc[i][j + 3]);
            *(float4*)(cp + j) = v;
        }
    }
}

// ---------------------------------------------------------------------------
// Masked LSTM: 16 seqs/block; Whh loop unroll 8 (MLP 4->8, hides L2 latency)
// ---------------------------------------------------------------------------
#define SEQS 16
__device__ __forceinline__ float sigf(float x) { return 1.f / (1.f + expf(-x)); }

#define LSTM_SMEM_FLOATS (SEQS*HH_ + SEQS*HH_ + SEQS*EE_ + 512*(SEQS+1) + SEQS)
#define LSTM_SMEM_BYTES  (LSTM_SMEM_FLOATS * 4)

__global__ __launch_bounds__(512)
void lstm_kernel(const float* __restrict__ xe,
                 const int*   __restrict__ wlen,
                 const float* __restrict__ bih,
                 const float* __restrict__ bhh)
{
    const float* WihT = g_scratch + OFF_WIHT;
    const float* WhhT = g_scratch + OFF_WHHT;
    float*       hbuf = g_scratch + OFF_HBUF;

    extern __shared__ float sm[];
    float* sh   = sm;
    float* sc   = sh + SEQS * HH_;
    float* sx   = sc + SEQS * HH_;
    float* sz   = sx + SEQS * EE_;
    int*   slen = (int*)(sz + 512 * (SEQS + 1));

    const int tid = threadIdx.x;
    const int bt0 = blockIdx.x * SEQS;

    for (int i = tid; i < SEQS * HH_; i += 512) {
        sh[i] = 0.f;
        sc[i] = 0.f;
    }
    if (tid < SEQS) slen[tid] = wlen[bt0 + tid];
    __syncthreads();

    const int r = tid;
    const float bias = bih[r] + bhh[r];

    for (int t = 0; t < WE_; t++) {
        for (int i = tid; i < SEQS * EE_; i += 512) {
            int s = i / EE_, e = i - s * EE_;
            sx[s * EE_ + e] = xe[(size_t)(bt0 + s) * (WE_ * EE_) + t * EE_ + e];
        }
        __syncthreads();

        float acc[SEQS];
#pragma unroll
        for (int s = 0; s < SEQS; s++) acc[s] = bias;
#pragma unroll
        for (int e = 0; e < EE_; e++) {
            float w = WihT[e * 512 + r];
#pragma unroll
            for (int s = 0; s < SEQS; s++) acc[s] = fmaf(w, sx[s * EE_ + e], acc[s]);
        }
#pragma unroll 8
        for (int j = 0; j < HH_; j++) {
            float w = WhhT[j * 512 + r];
#pragma unroll
            for (int s = 0; s < SEQS; s++) acc[s] = fmaf(w, sh[s * HH_ + j], acc[s]);
        }
#pragma unroll
        for (int s = 0; s < SEQS; s++) sz[r * (SEQS + 1) + s] = acc[s];
        __syncthreads();

#pragma unroll
        for (int p = tid; p < SEQS * HH_; p += 512) {
            int s = p & (SEQS - 1);
            int j = p >> 4;
            float zi = sz[j * (SEQS + 1) + s];
            float zf = sz[(HH_ + j) * (SEQS + 1) + s];
            float zg = sz[(2 * HH_ + j) * (SEQS + 1) + s];
            float zo = sz[(3 * HH_ + j) * (SEQS + 1) + s];
            float cc = sc[s * HH_ + j];
            float cn = sigf(zf) * cc + sigf(zi) * tanhf(zg);
            float hn = sigf(zo) * tanhf(cn);
            bool valid = (t < slen[s]);
            sc[s * HH_ + j] = valid ? cn : cc;
            sh[s * HH_ + j] = valid ? hn : sh[s * HH_ + j];
            hbuf[(size_t)(bt0 + s) * (WE_ * HH_) + t * HH_ + j] = valid ? hn : 0.f;
        }
        __syncthreads();
    }
}

// ---------------------------------------------------------------------------
// Fused maxpool + highway, 8 bt-rows per block; unrolled loops for MLP
// ---------------------------------------------------------------------------
#define BTB 8
__global__ void pool_highway_kernel(size_t cOff, int N, int Wout,
                                    const float* __restrict__ convB,
                                    size_t wpOff, const float* __restrict__ bp,
                                    size_t wgOff, const float* __restrict__ bg,
                                    float* __restrict__ out, int outOff)
{
    extern __shared__ float sy[];
    const float* Cmat = g_scratch + cOff;
    const float* WpT  = g_scratch + wpOff;
    const float* WgT  = g_scratch + wgOff;

    const int bt0 = blockIdx.x * BTB;
    const int co  = threadIdx.x;
    const float cb = convB[co];

#pragma unroll
    for (int b = 0; b < BTB; b++) {
        const float* cp = Cmat + (size_t)(bt0 + b) * Wout * N + co;
        float y = cp[0];
#pragma unroll 4
        for (int t = 1; t < Wout; t++) y = fmaxf(y, cp[(size_t)t * N]);
        sy[b * N + co] = y + cb;
    }
    __syncthreads();

    float ap[BTB], ag[BTB];
    const float bpc = bp[co], bgc = bg[co];
#pragma unroll
    for (int b = 0; b < BTB; b++) { ap[b] = bpc; ag[b] = bgc; }

#pragma unroll 4
    for (int j = 0; j < N; j++) {
        float wp = WpT[j * N + co];
        float wg = WgT[j * N + co];
#pragma unroll
        for (int b = 0; b < BTB; b++) {
            float yj = sy[b * N + j];
            ap[b] = fmaf(wp, yj, ap[b]);
            ag[b] = fmaf(wg, yj, ag[b]);
        }
    }
#pragma unroll
    for (int b = 0; b < BTB; b++) {
        float p  = fmaxf(ap[b], 0.f);
        float gg = 1.f / (1.f + expf(-ag[b]));
        float y  = sy[b * N + co];
        out[(size_t)(bt0 + b) * OUTW_ + outOff + co] = gg * p + (1.f - gg) * y;
    }
}

// ---------------------------------------------------------------------------
// Launch
// ---------------------------------------------------------------------------
extern "C" void kernel_launch(void* const* d_in, const int* in_sizes, int n_in,
                              void* d_out, int out_size)
{
    (void)in_sizes; (void)n_in; (void)out_size;
    const float* x_lin   = (const float*)d_in[0];
    const float* x_aco   = (const float*)d_in[1];
    const float* x_emo   = (const float*)d_in[2];
    const int*   wlen    = (const int*)  d_in[3];
    const float* convL_w = (const float*)d_in[5];
    const float* convL_b = (const float*)d_in[6];
    const float* convA_w = (const float*)d_in[7];
    const float* convA_b = (const float*)d_in[8];
    const float* convE_w = (const float*)d_in[9];
    const float* convE_b = (const float*)d_in[10];
    const float* hwL_Wp  = (const float*)d_in[11];
    const float* hwL_bp  = (const float*)d_in[12];
    const float* hwL_Wg  = (const float*)d_in[13];
    const float* hwL_bg  = (const float*)d_in[14];
    const float* hwA_Wp  = (const float*)d_in[15];
    const float* hwA_bp  = (const float*)d_in[16];
    const float* hwA_Wg  = (const float*)d_in[17];
    const float* hwA_bg  = (const float*)d_in[18];
    const float* hwE_Wp  = (const float*)d_in[19];
    const float* hwE_bp  = (const float*)d_in[20];
    const float* hwE_Wg  = (const float*)d_in[21];
    const float* hwE_bg  = (const float*)d_in[22];
    const float* Wih     = (const float*)d_in[23];
    const float* Whh     = (const float*)d_in[24];
    const float* bih     = (const float*)d_in[25];
    const float* bhh     = (const float*)d_in[26];
    float* out = (float*)d_out;

    cudaFuncSetAttribute(lstm_kernel,
                         cudaFuncAttributeMaxDynamicSharedMemorySize,
                         LSTM_SMEM_BYTES);
    cudaFuncSetAttribute(conv_gemm_f16_wide,
                         cudaFuncAttributeMaxDynamicSharedMemorySize,
                         WIDE_SMEM_BYTES);

    // 1-3: conv weight permutes
    permute_w_kernel<<<(CA_ * EA_ * KA_ + 255) / 256, 256>>>(convA_w, OFF_WAT, CA_, EA_, KA_);
    permute_w_kernel<<<(CL_ * EL_ * KL_ + 255) / 256, 256>>>(convL_w, OFF_WLT, CL_, EL_, KL_);
    permute_w_kernel<<<(CE_ * HH_ * KE_ + 255) / 256, 256>>>(convE_w, OFF_WET, CE_, HH_, KE_);

    // 4: acoustic GEMM — WIDE double-pumped (profiled launch)
    conv_gemm_f16_wide<<<dim3(1, MA_ / TBM), 512, WIDE_SMEM_BYTES>>>(
        x_aco, OFF_WAT, OFF_CA, KKA_, WOA_, EA_, WA_ * EA_);

    // 5: linguistic GEMM
    conv_gemm_f16_kernel<<<dim3(CL_ / TBN, ML_ / TBM), 256>>>(
        x_lin, OFF_WLT, OFF_CL, CL_, KKL_, WOL_, EL_, WL_ * EL_);

    // 6-7: LSTM weight transposes
    transpose2d_kernel<<<(512 * EE_ + 255) / 256, 256>>>(Wih, OFF_WIHT, 512, EE_);
    transpose2d_kernel<<<(512 * HH_ + 255) / 256, 256>>>(Whh, OFF_WHHT, 512, HH_);

    // 8: LSTM (-> hbuf), 16 seqs/block
    lstm_kernel<<<BT_ / SEQS, 512, LSTM_SMEM_BYTES>>>(x_emo, wlen, bih, bhh);

    // 9: emotient GEMM (fp32, input = hbuf)
    conv_gemm_kernel<128, 64, 16, 8, 4><<<dim3(ME_ / 128, CE_ / 64), 256>>>(
        OFF_HBUF, OFF_WET, OFF_CE, ME_, CE_, KKE_, WOE_, HH_, WE_ * HH_);

    // 10-15: highway weight transposes
    transpose2d_kernel<<<(CL_ * CL_ + 255) / 256, 256>>>(hwL_Wp, OFF_HWLPT, CL_, CL_);
    transpose2d_kernel<<<(CL_ * CL_ + 255) / 256, 256>>>(hwL_Wg, OFF_HWLGT, CL_, CL_);
    transpose2d_kernel<<<(CA_ * CA_ + 255) / 256, 256>>>(hwA_Wp, OFF_HWAPT, CA_, CA_);
    transpose2d_kernel<<<(CA_ * CA_ + 255) / 256, 256>>>(hwA_Wg, OFF_HWAGT, CA_, CA_);
    transpose2d_kernel<<<(CE_ * CE_ + 255) / 256, 256>>>(hwE_Wp, OFF_HWEPT, CE_, CE_);
    transpose2d_kernel<<<(CE_ * CE_ + 255) / 256, 256>>>(hwE_Wg, OFF_HWEGT, CE_, CE_);

    // 16-18: fused maxpool + highway -> output
    pool_highway_kernel<<<BT_ / BTB, CL_, BTB * CL_ * sizeof(float)>>>(
        OFF_CL, CL_, WOL_, convL_b, OFF_HWLPT, hwL_bp, OFF_HWLGT, hwL_bg, out, 0);
    pool_highway_kernel<<<BT_ / BTB, CA_, BTB * CA_ * sizeof(float)>>>(
        OFF_CA, CA_, WOA_, convA_b, OFF_HWAPT, hwA_bp, OFF_HWAGT, hwA_bg, out, CL_);
    pool_highway_kernel<<<BT_ / BTB, CE_, BTB * CE_ * sizeof(float)>>>(
        OFF_CE, CE_, WOE_, convE_b, OFF_HWEPT, hwE_bp, OFF_HWEGT, hwE_bg, out, CL_ + CA_);
}